// round 2
// baseline (speedup 1.0000x reference)
#include <cuda_runtime.h>
#include <math.h>

#define NN     10000
#define EE     320000
#define NE     (EE + NN)     // with self loops
#define NFEAT  512
#define NHID1  256
#define NHID2  64
#define H1     128           // 2*NHID2
#define NEG_SLOPE 0.2f
#define BN_EPS 1e-5f
#define MAXDEG 512

// output layout (flattened tuple: emb, re_x, readj, mu, logvar)
#define EMB_OFF   ((size_t)0)
#define REX_OFF   ((size_t)NN * NHID2)                       // 640000
#define READJ_OFF (REX_OFF + (size_t)NN * NFEAT)             // 5760000
#define MU_OFF    (READJ_OFF + (size_t)NN * NN)              // 105760000
#define LV_OFF    (MU_OFF + (size_t)NN * NHID2)              // 106400000

// ---------------- scratch (device globals; no allocation allowed) ----------
__device__ float g_xl1[NN * H1];
__device__ float g_xr1[NN * H1];
__device__ float g_h  [NN * H1];
__device__ float g_xl2[NN * NHID2];
__device__ float g_xr2[NN * NHID2];
__device__ float g_xl3[NN * NHID2];
__device__ float g_xr3[NN * NHID2];
__device__ float g_d  [NN * NHID1];
__device__ int   g_deg[NN];
__device__ int   g_rowptr[NN + 1];
__device__ int   g_cursor[NN];
__device__ int   g_srclist[NE];
__device__ float g_mean[NHID1];
__device__ float g_rstd[NHID1];

// ---------------- CSR build ----------------
__global__ void k_zero_counts() {
    int i = blockIdx.x * blockDim.x + threadIdx.x;
    if (i < NN) { g_deg[i] = 0; g_cursor[i] = 0; }
}

__global__ void k_count_deg(const int* __restrict__ edge_index) {
    int i = blockIdx.x * blockDim.x + threadIdx.x;
    if (i >= NE) return;
    int tgt = (i < EE) ? edge_index[EE + i] : (i - EE);
    atomicAdd(&g_deg[tgt], 1);
}

__global__ void k_scan_deg() {
    __shared__ int s[1024];
    __shared__ int sc;
    int tid = threadIdx.x;
    if (tid == 0) { sc = 0; g_rowptr[0] = 0; }
    __syncthreads();
    for (int base = 0; base < NN; base += 1024) {
        int i = base + tid;
        s[tid] = (i < NN) ? g_deg[i] : 0;
        __syncthreads();
        for (int off = 1; off < 1024; off <<= 1) {
            int t = (tid >= off) ? s[tid - off] : 0;
            __syncthreads();
            s[tid] += t;
            __syncthreads();
        }
        int c = sc;
        if (i < NN) g_rowptr[i + 1] = c + s[tid];
        __syncthreads();
        if (tid == 0) sc = c + s[1023];
        __syncthreads();
    }
}

__global__ void k_fill_list(const int* __restrict__ edge_index) {
    int i = blockIdx.x * blockDim.x + threadIdx.x;
    if (i >= NE) return;
    int src, tgt;
    if (i < EE) { src = edge_index[i]; tgt = edge_index[EE + i]; }
    else        { src = i - EE;        tgt = i - EE; }
    int pos = atomicAdd(&g_cursor[tgt], 1);
    g_srclist[g_rowptr[tgt] + pos] = src;
}

// ---------------- small tiled SGEMM (64x64 tile, 4x4/thread) --------------
// used for the narrow Nc=64 layers
__global__ void sgemm_bias(const float* __restrict__ A, const float* __restrict__ B,
                           const float* __restrict__ bias, float* __restrict__ C,
                           int M, int K, int Nc) {
    __shared__ float As[16][65];
    __shared__ float Bs[16][65];
    int tx = threadIdx.x, ty = threadIdx.y;
    int tid = ty * 16 + tx;
    int row0 = blockIdx.y * 64, col0 = blockIdx.x * 64;
    float acc[4][4] = {};
    for (int k0 = 0; k0 < K; k0 += 16) {
#pragma unroll
        for (int i = 0; i < 4; i++) {
            int e = tid + i * 256;
            int k = e & 15, m = e >> 4;
            As[k][m] = (row0 + m < M) ? A[(size_t)(row0 + m) * K + k0 + k] : 0.f;
        }
#pragma unroll
        for (int i = 0; i < 4; i++) {
            int e = tid + i * 256;
            int n = e & 63, k = e >> 6;
            Bs[k][n] = B[(size_t)(k0 + k) * Nc + col0 + n];
        }
        __syncthreads();
#pragma unroll
        for (int kk = 0; kk < 16; kk++) {
            float a[4], b[4];
#pragma unroll
            for (int i = 0; i < 4; i++) a[i] = As[kk][ty * 4 + i];
#pragma unroll
            for (int j = 0; j < 4; j++) b[j] = Bs[kk][tx * 4 + j];
#pragma unroll
            for (int i = 0; i < 4; i++)
#pragma unroll
                for (int j = 0; j < 4; j++) acc[i][j] += a[i] * b[j];
        }
        __syncthreads();
    }
#pragma unroll
    for (int i = 0; i < 4; i++) {
        int r = row0 + ty * 4 + i;
        if (r < M) {
#pragma unroll
            for (int j = 0; j < 4; j++) {
                int c = col0 + tx * 4 + j;
                C[(size_t)r * Nc + c] = acc[i][j] + bias[c];
            }
        }
    }
}

// ---------------- big tiled SGEMM: 128x128 tile, BK=16, 8x8/thread --------
// requires: Nc % 128 == 0, K % 16 == 0. M guarded.
__global__ __launch_bounds__(256)
void sgemm128_bias(const float* __restrict__ A, const float* __restrict__ B,
                   const float* __restrict__ bias, float* __restrict__ C,
                   int M, int K, int Nc) {
    __shared__ float As[16][140];   // k-major, padded (140*4B = 35x16B, float4-aligned)
    __shared__ float Bs[16][132];
    int tid = threadIdx.x;
    int tx = tid & 15, ty = tid >> 4;
    int row0 = blockIdx.y * 128, col0 = blockIdx.x * 128;
    float acc[8][8] = {};
    for (int k0 = 0; k0 < K; k0 += 16) {
        // load A tile: 128 rows x 16 k  (512 float4, 2 per thread), transpose to As[k][m]
#pragma unroll
        for (int i = 0; i < 2; i++) {
            int idx = tid + i * 256;          // 0..511
            int m = idx >> 2;                 // row in tile 0..127
            int kq = idx & 3;                 // k = kq*4
            int r = row0 + m;
            float4 v = make_float4(0.f, 0.f, 0.f, 0.f);
            if (r < M) v = *(const float4*)(A + (size_t)r * K + k0 + kq * 4);
            As[kq * 4 + 0][m] = v.x;
            As[kq * 4 + 1][m] = v.y;
            As[kq * 4 + 2][m] = v.z;
            As[kq * 4 + 3][m] = v.w;
        }
        // load B tile: 16 k-rows x 128 cols (512 float4, 2 per thread), row-contiguous
#pragma unroll
        for (int i = 0; i < 2; i++) {
            int idx = tid + i * 256;
            int k = idx >> 5;                 // 0..15
            int nq = idx & 31;                // n = nq*4
            float4 v = *(const float4*)(B + (size_t)(k0 + k) * Nc + col0 + nq * 4);
            *(float4*)&Bs[k][nq * 4] = v;
        }
        __syncthreads();
#pragma unroll
        for (int kk = 0; kk < 16; kk++) {
            float a[8], b[8];
            *(float4*)(a)     = *(const float4*)&As[kk][ty * 8];
            *(float4*)(a + 4) = *(const float4*)&As[kk][ty * 8 + 4];
            *(float4*)(b)     = *(const float4*)&Bs[kk][tx * 8];
            *(float4*)(b + 4) = *(const float4*)&Bs[kk][tx * 8 + 4];
#pragma unroll
            for (int i = 0; i < 8; i++)
#pragma unroll
                for (int j = 0; j < 8; j++) acc[i][j] += a[i] * b[j];
        }
        __syncthreads();
    }
#pragma unroll
    for (int i = 0; i < 8; i++) {
        int r = row0 + ty * 8 + i;
        if (r < M) {
#pragma unroll
            for (int j = 0; j < 8; j++) {
                int c = col0 + tx * 8 + j;
                C[(size_t)r * Nc + c] = acc[i][j] + bias[c];
            }
        }
    }
}

// ---------------- GATv2 aggregation (one block per target node) -----------
template <int C>
__global__ void gat_agg(const float* __restrict__ xl, const float* __restrict__ xr,
                        const float* __restrict__ att, const float* __restrict__ bias,
                        float* __restrict__ out) {
    constexpr int W = C / 32;
    int t = blockIdx.x;
    int tid = threadIdx.x, lane = tid & 31, warp = tid >> 5;
    __shared__ float s_xr[C], s_att[C];
    __shared__ float s_e[MAXDEG];
    __shared__ int   s_src[MAXDEG];
    __shared__ float s_red[W];
    s_xr[tid]  = xr[(size_t)t * C + tid];
    s_att[tid] = att[tid];
    int beg = g_rowptr[t];
    int deg = g_rowptr[t + 1] - beg;
    __syncthreads();

    // pass A: per-warp edge scores e_j = a . leaky(xl[src] + xr[tgt])
    for (int j = warp; j < deg; j += W) {
        int src = g_srclist[beg + j];
        const float* xs = xl + (size_t)src * C;
        float p = 0.f;
#pragma unroll
        for (int k = 0; k < C / 32; k++) {
            int c = lane + 32 * k;
            float s = xs[c] + s_xr[c];
            s = fmaxf(s, NEG_SLOPE * s);
            p += s_att[c] * s;
        }
#pragma unroll
        for (int o = 16; o; o >>= 1) p += __shfl_xor_sync(0xffffffffu, p, o);
        if (lane == 0) { s_e[j] = p; s_src[j] = src; }
    }
    __syncthreads();

    // max over edges
    float m = -1e30f;
    for (int j = tid; j < deg; j += C) m = fmaxf(m, s_e[j]);
#pragma unroll
    for (int o = 16; o; o >>= 1) m = fmaxf(m, __shfl_xor_sync(0xffffffffu, m, o));
    if (lane == 0) s_red[warp] = m;
    __syncthreads();
    m = s_red[0];
#pragma unroll
    for (int w = 1; w < W; w++) m = fmaxf(m, s_red[w]);
    __syncthreads();

    // exp + sum
    float ssum = 0.f;
    for (int j = tid; j < deg; j += C) {
        float wj = __expf(s_e[j] - m);
        s_e[j] = wj;
        ssum += wj;
    }
#pragma unroll
    for (int o = 16; o; o >>= 1) ssum += __shfl_xor_sync(0xffffffffu, ssum, o);
    if (lane == 0) s_red[warp] = ssum;
    __syncthreads();
    ssum = 0.f;
#pragma unroll
    for (int w = 0; w < W; w++) ssum += s_red[w];
    float inv = 1.f / ssum;

    // pass B: weighted aggregation of xl[src]
    float acc = 0.f;
    for (int j = 0; j < deg; j++) {
        acc += s_e[j] * xl[(size_t)s_src[j] * C + tid];
    }
    out[(size_t)t * C + tid] = acc * inv + bias[tid];
}

// ---------------- batch norm ----------------
__global__ void bn_stats(const float* __restrict__ h, int C) {
    int c = blockIdx.x;
    int tid = threadIdx.x;
    float s = 0.f, s2 = 0.f;
    for (int r = tid; r < NN; r += 256) {
        float v = h[(size_t)r * C + c];
        s += v; s2 += v * v;
    }
    __shared__ float sh[8], sh2[8];
#pragma unroll
    for (int o = 16; o; o >>= 1) {
        s  += __shfl_xor_sync(0xffffffffu, s,  o);
        s2 += __shfl_xor_sync(0xffffffffu, s2, o);
    }
    if ((tid & 31) == 0) { sh[tid >> 5] = s; sh2[tid >> 5] = s2; }
    __syncthreads();
    if (tid == 0) {
        float ts = 0.f, ts2 = 0.f;
        for (int w = 0; w < 8; w++) { ts += sh[w]; ts2 += sh2[w]; }
        float mean = ts / NN;
        float var = ts2 / NN - mean * mean;
        g_mean[c] = mean;
        g_rstd[c] = rsqrtf(var + BN_EPS);
    }
}

__global__ void bn_apply_relu(float* __restrict__ buf, const float* __restrict__ g,
                              const float* __restrict__ b, int C, int total) {
    int i = blockIdx.x * blockDim.x + threadIdx.x;
    if (i >= total) return;
    int c = i % C;
    float v = (buf[i] - g_mean[c]) * g_rstd[c] * g[c] + b[c];
    buf[i] = fmaxf(v, 0.f);
}

// ---------------- reparameterize ----------------
__global__ void k_reparam(const float* __restrict__ eps, float* __restrict__ out) {
    int i = blockIdx.x * blockDim.x + threadIdx.x;
    if (i >= NN * NHID2) return;
    float mu = out[MU_OFF + i];
    float lv = out[LV_OFF + i];
    out[EMB_OFF + i] = eps[i] * __expf(lv) + mu;
}

// ---------------- readj = sigmoid(emb @ emb^T), symmetric ------------------
// 128x128 tiles, 8x8 per thread, upper-triangular blocks only; mirror write.
__global__ __launch_bounds__(256)
void gram_sigmoid_sym(const float* __restrict__ E, float* __restrict__ out) {
    int by = blockIdx.y, bx = blockIdx.x;
    if (bx < by) return;                      // upper triangle only
    __shared__ float Ea[32][140];
    __shared__ float Eb[32][140];
    int tid = threadIdx.x;
    int tx = tid & 15, ty = tid >> 4;
    int row0 = by * 128, col0 = bx * 128;
    float acc[8][8] = {};
#pragma unroll
    for (int k0 = 0; k0 < 64; k0 += 32) {
        // load 128 rows x 32 k for each side (1024 float4 each, 4 per thread)
#pragma unroll
        for (int i = 0; i < 4; i++) {
            int idx = tid + i * 256;          // 0..1023
            int m = idx >> 3;                 // 0..127
            int kq = idx & 7;                 // k = kq*4
            int r = row0 + m;
            float4 v = make_float4(0.f, 0.f, 0.f, 0.f);
            if (r < NN) v = *(const float4*)(E + (size_t)r * 64 + k0 + kq * 4);
            Ea[kq * 4 + 0][m] = v.x;
            Ea[kq * 4 + 1][m] = v.y;
            Ea[kq * 4 + 2][m] = v.z;
            Ea[kq * 4 + 3][m] = v.w;
            int c = col0 + m;
            float4 w = make_float4(0.f, 0.f, 0.f, 0.f);
            if (c < NN) w = *(const float4*)(E + (size_t)c * 64 + k0 + kq * 4);
            Eb[kq * 4 + 0][m] = w.x;
            Eb[kq * 4 + 1][m] = w.y;
            Eb[kq * 4 + 2][m] = w.z;
            Eb[kq * 4 + 3][m] = w.w;
        }
        __syncthreads();
#pragma unroll
        for (int kk = 0; kk < 32; kk++) {
            float a[8], b[8];
            *(float4*)(a)     = *(const float4*)&Ea[kk][ty * 8];
            *(float4*)(a + 4) = *(const float4*)&Ea[kk][ty * 8 + 4];
            *(float4*)(b)     = *(const float4*)&Eb[kk][tx * 8];
            *(float4*)(b + 4) = *(const float4*)&Eb[kk][tx * 8 + 4];
#pragma unroll
            for (int i = 0; i < 8; i++)
#pragma unroll
                for (int j = 0; j < 8; j++) acc[i][j] += a[i] * b[j];
        }
        __syncthreads();
    }
    // sigmoid + direct write (coalesced)
#pragma unroll
    for (int i = 0; i < 8; i++) {
        int r = row0 + ty * 8 + i;
        if (r < NN) {
#pragma unroll
            for (int j = 0; j < 8; j++) {
                int c = col0 + tx * 8 + j;
                if (c < NN) {
                    float s = 1.f / (1.f + __expf(-acc[i][j]));
                    acc[i][j] = s;
                    out[(size_t)r * NN + c] = s;
                }
            }
        }
    }
    if (bx == by) return;                     // diagonal: mirror identical
    // mirror write: out[c][r]; per thread 8 runs of 8 contiguous floats
#pragma unroll
    for (int j = 0; j < 8; j++) {
        int c = col0 + tx * 8 + j;
        if (c < NN) {
#pragma unroll
            for (int i = 0; i < 8; i++) {
                int r = row0 + ty * 8 + i;
                if (r < NN) out[(size_t)c * NN + r] = acc[i][j];
            }
        }
    }
}

// ---------------- launch ----------------
extern "C" void kernel_launch(void* const* d_in, const int* in_sizes, int n_in,
                              void* d_out, int out_size) {
    const float* x   = (const float*)d_in[0];
    const int*   ei  = (const int*)  d_in[1];
    const float* eps = (const float*)d_in[2];
    const float* w1l = (const float*)d_in[3];
    const float* b1l = (const float*)d_in[4];
    const float* w1r = (const float*)d_in[5];
    const float* b1r = (const float*)d_in[6];
    const float* a1  = (const float*)d_in[7];
    const float* bias1 = (const float*)d_in[8];
    const float* bn1_g = (const float*)d_in[9];
    const float* bn1_b = (const float*)d_in[10];
    const float* w2l = (const float*)d_in[11];
    const float* b2l = (const float*)d_in[12];
    const float* w2r = (const float*)d_in[13];
    const float* b2r = (const float*)d_in[14];
    const float* a2  = (const float*)d_in[15];
    const float* bias2 = (const float*)d_in[16];
    const float* w3l = (const float*)d_in[17];
    const float* b3l = (const float*)d_in[18];
    const float* w3r = (const float*)d_in[19];
    const float* b3r = (const float*)d_in[20];
    const float* a3  = (const float*)d_in[21];
    const float* bias3 = (const float*)d_in[22];
    const float* dw1 = (const float*)d_in[23];
    const float* db1 = (const float*)d_in[24];
    const float* dbn_g = (const float*)d_in[25];
    const float* dbn_b = (const float*)d_in[26];
    const float* dw2 = (const float*)d_in[27];
    const float* db2 = (const float*)d_in[28];
    float* out = (float*)d_out;

    // resolve scratch symbol addresses
    float *p_xl1, *p_xr1, *p_h, *p_xl2, *p_xr2, *p_xl3, *p_xr3, *p_d;
    cudaGetSymbolAddress((void**)&p_xl1, g_xl1);
    cudaGetSymbolAddress((void**)&p_xr1, g_xr1);
    cudaGetSymbolAddress((void**)&p_h,   g_h);
    cudaGetSymbolAddress((void**)&p_xl2, g_xl2);
    cudaGetSymbolAddress((void**)&p_xr2, g_xr2);
    cudaGetSymbolAddress((void**)&p_xl3, g_xl3);
    cudaGetSymbolAddress((void**)&p_xr3, g_xr3);
    cudaGetSymbolAddress((void**)&p_d,   g_d);

    dim3 blk16(16, 16);

    // ---- CSR build (edges + self loops, grouped by target) ----
    k_zero_counts<<<(NN + 255) / 256, 256>>>();
    k_count_deg<<<(NE + 255) / 256, 256>>>(ei);
    k_scan_deg<<<1, 1024>>>();
    k_fill_list<<<(NE + 255) / 256, 256>>>(ei);

    // ---- layer 1 linear transforms (big sgemm: K=512, Nc=128) ----
    sgemm128_bias<<<dim3(H1 / 128, (NN + 127) / 128), 256>>>(x, w1l, b1l, p_xl1, NN, NFEAT, H1);
    sgemm128_bias<<<dim3(H1 / 128, (NN + 127) / 128), 256>>>(x, w1r, b1r, p_xr1, NN, NFEAT, H1);

    // ---- GAT layer 1 -> BN -> ReLU ----
    gat_agg<H1><<<NN, H1>>>(p_xl1, p_xr1, a1, bias1, p_h);
    bn_stats<<<H1, 256>>>(p_h, H1);
    bn_apply_relu<<<(NN * H1 + 255) / 256, 256>>>(p_h, bn1_g, bn1_b, H1, NN * H1);

    // ---- layers 2 & 3 linear transforms (narrow: Nc=64) ----
    sgemm_bias<<<dim3(NHID2 / 64, (NN + 63) / 64), blk16>>>(p_h, w2l, b2l, p_xl2, NN, H1, NHID2);
    sgemm_bias<<<dim3(NHID2 / 64, (NN + 63) / 64), blk16>>>(p_h, w2r, b2r, p_xr2, NN, H1, NHID2);
    sgemm_bias<<<dim3(NHID2 / 64, (NN + 63) / 64), blk16>>>(p_h, w3l, b3l, p_xl3, NN, H1, NHID2);
    sgemm_bias<<<dim3(NHID2 / 64, (NN + 63) / 64), blk16>>>(p_h, w3r, b3r, p_xr3, NN, H1, NHID2);

    // ---- GAT layers 2 (mu) and 3 (logvar) straight into output ----
    gat_agg<NHID2><<<NN, NHID2>>>(p_xl2, p_xr2, a2, bias2, out + MU_OFF);
    gat_agg<NHID2><<<NN, NHID2>>>(p_xl3, p_xr3, a3, bias3, out + LV_OFF);

    // ---- reparameterize: emb = eps*exp(logvar)+mu ----
    k_reparam<<<(NN * NHID2 + 255) / 256, 256>>>(eps, out);

    // ---- readj = sigmoid(emb @ emb^T), symmetric tiles ----
    {
        int nt = (NN + 127) / 128;            // 79
        gram_sigmoid_sym<<<dim3(nt, nt), 256>>>(out + EMB_OFF, out + READJ_OFF);
    }

    // ---- decoder MLP ----
    sgemm_bias<<<dim3(NHID1 / 64, (NN + 63) / 64), blk16>>>(out + EMB_OFF, dw1, db1, p_d, NN, NHID2, NHID1);
    bn_stats<<<NHID1, 256>>>(p_d, NHID1);
    bn_apply_relu<<<(NN * NHID1 + 255) / 256, 256>>>(p_d, dbn_g, dbn_b, NHID1, NN * NHID1);
    sgemm128_bias<<<dim3(NFEAT / 128, (NN + 127) / 128), 256>>>(p_d, dw2, db2, out + REX_OFF, NN, NHID1, NFEAT);
}

// round 3
// speedup vs baseline: 1.1286x; 1.1286x over previous
#include <cuda_runtime.h>
#include <math.h>

#define NN     10000
#define EE     320000
#define NE     (EE + NN)     // with self loops
#define NFEAT  512
#define NHID1  256
#define NHID2  64
#define H1     128           // 2*NHID2
#define NEG_SLOPE 0.2f
#define BN_EPS 1e-5f
#define MAXDEG 512

// output layout (flattened tuple: emb, re_x, readj, mu, logvar)
#define EMB_OFF   ((size_t)0)
#define REX_OFF   ((size_t)NN * NHID2)                       // 640000
#define READJ_OFF (REX_OFF + (size_t)NN * NFEAT)             // 5760000
#define MU_OFF    (READJ_OFF + (size_t)NN * NN)              // 105760000
#define LV_OFF    (MU_OFF + (size_t)NN * NHID2)              // 106400000

typedef unsigned long long u64;

// ---------------- f32x2 packed helpers ----------------
__device__ __forceinline__ u64 pk2(float x, float y) {
    u64 r; asm("mov.b64 %0, {%1, %2};" : "=l"(r) : "f"(x), "f"(y)); return r;
}
__device__ __forceinline__ u64 fma2_(u64 a, u64 b, u64 c) {
    u64 d; asm("fma.rn.f32x2 %0, %1, %2, %3;" : "=l"(d) : "l"(a), "l"(b), "l"(c)); return d;
}
__device__ __forceinline__ float2 upk2(u64 v) {
    float lo, hi; asm("mov.b64 {%0, %1}, %2;" : "=f"(lo), "=f"(hi) : "l"(v));
    float2 r; r.x = lo; r.y = hi; return r;
}
union F4U { float4 f4; u64 u[2]; };

// ---------------- scratch (device globals; no allocation allowed) ----------
__device__ float g_xl1[NN * H1];
__device__ float g_xr1[NN * H1];
__device__ float g_h  [NN * H1];
__device__ float g_xl2[NN * NHID2];
__device__ float g_xr2[NN * NHID2];
__device__ float g_xl3[NN * NHID2];
__device__ float g_xr3[NN * NHID2];
__device__ float g_d  [NN * NHID1];
__device__ int   g_deg[NN];
__device__ int   g_rowptr[NN + 1];
__device__ int   g_cursor[NN];
__device__ int   g_srclist[NE];
__device__ float g_mean[NHID1];
__device__ float g_rstd[NHID1];

// ---------------- CSR build ----------------
__global__ void k_zero_counts() {
    int i = blockIdx.x * blockDim.x + threadIdx.x;
    if (i < NN) { g_deg[i] = 0; g_cursor[i] = 0; }
}

__global__ void k_count_deg(const int* __restrict__ edge_index) {
    int i = blockIdx.x * blockDim.x + threadIdx.x;
    if (i >= NE) return;
    int tgt = (i < EE) ? edge_index[EE + i] : (i - EE);
    atomicAdd(&g_deg[tgt], 1);
}

__global__ void k_scan_deg() {
    __shared__ int s[1024];
    __shared__ int sc;
    int tid = threadIdx.x;
    if (tid == 0) { sc = 0; g_rowptr[0] = 0; }
    __syncthreads();
    for (int base = 0; base < NN; base += 1024) {
        int i = base + tid;
        s[tid] = (i < NN) ? g_deg[i] : 0;
        __syncthreads();
        for (int off = 1; off < 1024; off <<= 1) {
            int t = (tid >= off) ? s[tid - off] : 0;
            __syncthreads();
            s[tid] += t;
            __syncthreads();
        }
        int c = sc;
        if (i < NN) g_rowptr[i + 1] = c + s[tid];
        __syncthreads();
        if (tid == 0) sc = c + s[1023];
        __syncthreads();
    }
}

__global__ void k_fill_list(const int* __restrict__ edge_index) {
    int i = blockIdx.x * blockDim.x + threadIdx.x;
    if (i >= NE) return;
    int src, tgt;
    if (i < EE) { src = edge_index[i]; tgt = edge_index[EE + i]; }
    else        { src = i - EE;        tgt = i - EE; }
    int pos = atomicAdd(&g_cursor[tgt], 1);
    g_srclist[g_rowptr[tgt] + pos] = src;
}

// ---------------- GEMM job plumbing ----------------
struct GJob  { const float* B; const float* bias; float* C; };
struct GJobs { GJob j[4]; };

// ---------------- gemmA: 128x128 tile, BK=16, 256 thr, 8x8/thread, f32x2 --
// requires Nc % 128 == 0, K % 16 == 0. blockIdx.z selects job.
__global__ __launch_bounds__(256)
void gemmA(const float* __restrict__ A, GJobs jobs, int M, int K, int Nc) {
    const GJob jb = jobs.j[blockIdx.z];
    const float* __restrict__ B = jb.B;
    __shared__ __align__(16) float As[16][132];
    __shared__ __align__(16) float Bs[16][132];
    int tid = threadIdx.x;
    int tx = tid & 15, ty = tid >> 4;
    int row0 = blockIdx.y * 128, col0 = blockIdx.x * 128;
    u64 acc[8][4];
#pragma unroll
    for (int i = 0; i < 8; i++)
#pragma unroll
        for (int j = 0; j < 4; j++) acc[i][j] = 0ull;

    for (int k0 = 0; k0 < K; k0 += 16) {
#pragma unroll
        for (int i = 0; i < 2; i++) {
            int idx = tid + i * 256;          // 0..511
            int m = idx >> 2;                 // 0..127
            int kq = idx & 3;
            int r = row0 + m;
            float4 v = make_float4(0.f, 0.f, 0.f, 0.f);
            if (r < M) v = *(const float4*)(A + (size_t)r * K + k0 + kq * 4);
            As[kq * 4 + 0][m] = v.x;
            As[kq * 4 + 1][m] = v.y;
            As[kq * 4 + 2][m] = v.z;
            As[kq * 4 + 3][m] = v.w;
        }
#pragma unroll
        for (int i = 0; i < 2; i++) {
            int idx = tid + i * 256;
            int k = idx >> 5;
            int nq = idx & 31;
            *(float4*)&Bs[k][nq * 4] = *(const float4*)(B + (size_t)(k0 + k) * Nc + col0 + nq * 4);
        }
        __syncthreads();
#pragma unroll
        for (int kk = 0; kk < 16; kk++) {
            float4 a0 = *(const float4*)&As[kk][ty * 8];
            float4 a1 = *(const float4*)&As[kk][ty * 8 + 4];
            F4U b0, b1;
            b0.f4 = *(const float4*)&Bs[kk][tx * 8];
            b1.f4 = *(const float4*)&Bs[kk][tx * 8 + 4];
            u64 ap[8];
            ap[0] = pk2(a0.x, a0.x); ap[1] = pk2(a0.y, a0.y);
            ap[2] = pk2(a0.z, a0.z); ap[3] = pk2(a0.w, a0.w);
            ap[4] = pk2(a1.x, a1.x); ap[5] = pk2(a1.y, a1.y);
            ap[6] = pk2(a1.z, a1.z); ap[7] = pk2(a1.w, a1.w);
            u64 bu[4] = { b0.u[0], b0.u[1], b1.u[0], b1.u[1] };
#pragma unroll
            for (int i = 0; i < 8; i++)
#pragma unroll
                for (int j = 0; j < 4; j++) acc[i][j] = fma2_(ap[i], bu[j], acc[i][j]);
        }
        __syncthreads();
    }
#pragma unroll
    for (int i = 0; i < 8; i++) {
        int r = row0 + ty * 8 + i;
        if (r < M) {
            float* Crow = jb.C + (size_t)r * Nc;
#pragma unroll
            for (int j = 0; j < 4; j++) {
                int c = col0 + tx * 8 + 2 * j;
                float2 p = upk2(acc[i][j]);
                p.x += __ldg(&jb.bias[c]);
                p.y += __ldg(&jb.bias[c + 1]);
                *(float2*)&Crow[c] = p;
            }
        }
    }
}

// ---------------- gemmB: 128x64 tile, BK=16, 256 thr, 8x4/thread, f32x2 ---
// requires Nc % 64 == 0, K % 16 == 0. blockIdx.z selects job.
__global__ __launch_bounds__(256)
void gemmB(const float* __restrict__ A, GJobs jobs, int M, int K, int Nc) {
    const GJob jb = jobs.j[blockIdx.z];
    const float* __restrict__ B = jb.B;
    __shared__ __align__(16) float As[16][132];
    __shared__ __align__(16) float Bs[16][68];
    int tid = threadIdx.x;
    int tx = tid & 15, ty = tid >> 4;
    int row0 = blockIdx.y * 128, col0 = blockIdx.x * 64;
    u64 acc[8][2];
#pragma unroll
    for (int i = 0; i < 8; i++) { acc[i][0] = 0ull; acc[i][1] = 0ull; }

    for (int k0 = 0; k0 < K; k0 += 16) {
#pragma unroll
        for (int i = 0; i < 2; i++) {
            int idx = tid + i * 256;
            int m = idx >> 2;
            int kq = idx & 3;
            int r = row0 + m;
            float4 v = make_float4(0.f, 0.f, 0.f, 0.f);
            if (r < M) v = *(const float4*)(A + (size_t)r * K + k0 + kq * 4);
            As[kq * 4 + 0][m] = v.x;
            As[kq * 4 + 1][m] = v.y;
            As[kq * 4 + 2][m] = v.z;
            As[kq * 4 + 3][m] = v.w;
        }
        {
            int k = tid >> 4;
            int nq = tid & 15;
            *(float4*)&Bs[k][nq * 4] = *(const float4*)(B + (size_t)(k0 + k) * Nc + col0 + nq * 4);
        }
        __syncthreads();
#pragma unroll
        for (int kk = 0; kk < 16; kk++) {
            float4 a0 = *(const float4*)&As[kk][ty * 8];
            float4 a1 = *(const float4*)&As[kk][ty * 8 + 4];
            F4U b0;
            b0.f4 = *(const float4*)&Bs[kk][tx * 4];
            u64 ap[8];
            ap[0] = pk2(a0.x, a0.x); ap[1] = pk2(a0.y, a0.y);
            ap[2] = pk2(a0.z, a0.z); ap[3] = pk2(a0.w, a0.w);
            ap[4] = pk2(a1.x, a1.x); ap[5] = pk2(a1.y, a1.y);
            ap[6] = pk2(a1.z, a1.z); ap[7] = pk2(a1.w, a1.w);
            u64 bu[2] = { b0.u[0], b0.u[1] };
#pragma unroll
            for (int i = 0; i < 8; i++) {
                acc[i][0] = fma2_(ap[i], bu[0], acc[i][0]);
                acc[i][1] = fma2_(ap[i], bu[1], acc[i][1]);
            }
        }
        __syncthreads();
    }
#pragma unroll
    for (int i = 0; i < 8; i++) {
        int r = row0 + ty * 8 + i;
        if (r < M) {
            float* Crow = jb.C + (size_t)r * Nc;
#pragma unroll
            for (int j = 0; j < 2; j++) {
                int c = col0 + tx * 4 + 2 * j;
                float2 p = upk2(acc[i][j]);
                p.x += __ldg(&jb.bias[c]);
                p.y += __ldg(&jb.bias[c + 1]);
                *(float2*)&Crow[c] = p;
            }
        }
    }
}

// ---------------- GATv2 aggregation (one block per target node) -----------
struct AJob  { const float* xl; const float* xr; const float* att; const float* bias; float* out; };
struct AJobs { AJob j[2]; };

template <int C>
__global__ void gat_agg(AJobs jobs) {
    constexpr int W  = C / 32;   // warps per block (block = C threads)
    constexpr int NL = C / 4;    // active lanes per row (float4)
    const AJob jb = jobs.j[blockIdx.y];
    int t = blockIdx.x;
    int tid = threadIdx.x, lane = tid & 31, warp = tid >> 5;
    __shared__ float4 s_xr4[NL], s_att4[NL];
    __shared__ float  s_e[MAXDEG];
    __shared__ int    s_src[MAXDEG];
    __shared__ float  s_red[W];
    __shared__ float4 s_part[W][NL];
    if (tid < NL) {
        s_xr4[tid]  = *(const float4*)(jb.xr + (size_t)t * C + tid * 4);
        s_att4[tid] = *(const float4*)(jb.att + tid * 4);
    }
    int beg = g_rowptr[t];
    int deg = g_rowptr[t + 1] - beg;
    __syncthreads();

    float4 xr4 = make_float4(0.f, 0.f, 0.f, 0.f);
    float4 at4 = xr4;
    if (lane < NL) { xr4 = s_xr4[lane]; at4 = s_att4[lane]; }

    // pass A: per-warp edge scores e_j = a . leaky(xl[src] + xr[tgt])
    for (int j = warp; j < deg; j += W) {
        int src = g_srclist[beg + j];
        float p = 0.f;
        if (lane < NL) {
            float4 v = *(const float4*)(jb.xl + (size_t)src * C + lane * 4);
            float sx = v.x + xr4.x; sx = fmaxf(sx, NEG_SLOPE * sx);
            float sy = v.y + xr4.y; sy = fmaxf(sy, NEG_SLOPE * sy);
            float sz = v.z + xr4.z; sz = fmaxf(sz, NEG_SLOPE * sz);
            float sw = v.w + xr4.w; sw = fmaxf(sw, NEG_SLOPE * sw);
            p = at4.x * sx + at4.y * sy + at4.z * sz + at4.w * sw;
        }
#pragma unroll
        for (int o = 16; o; o >>= 1) p += __shfl_xor_sync(0xffffffffu, p, o);
        if (lane == 0) { s_e[j] = p; s_src[j] = src; }
    }
    __syncthreads();

    // max over edges
    float m = -1e30f;
    for (int j = tid; j < deg; j += C) m = fmaxf(m, s_e[j]);
#pragma unroll
    for (int o = 16; o; o >>= 1) m = fmaxf(m, __shfl_xor_sync(0xffffffffu, m, o));
    if (lane == 0) s_red[warp] = m;
    __syncthreads();
    m = s_red[0];
#pragma unroll
    for (int w = 1; w < W; w++) m = fmaxf(m, s_red[w]);
    __syncthreads();

    // exp + sum
    float ssum = 0.f;
    for (int j = tid; j < deg; j += C) {
        float wj = __expf(s_e[j] - m);
        s_e[j] = wj;
        ssum += wj;
    }
#pragma unroll
    for (int o = 16; o; o >>= 1) ssum += __shfl_xor_sync(0xffffffffu, ssum, o);
    if (lane == 0) s_red[warp] = ssum;
    __syncthreads();
    ssum = 0.f;
#pragma unroll
    for (int w = 0; w < W; w++) ssum += s_red[w];
    float inv = 1.f / ssum;

    // pass B: warp-parallel weighted aggregation of xl[src] (float4 lanes)
    float4 facc = make_float4(0.f, 0.f, 0.f, 0.f);
    if (lane < NL) {
        for (int j = warp; j < deg; j += W) {
            float wj = s_e[j];
            float4 v = *(const float4*)(jb.xl + (size_t)s_src[j] * C + lane * 4);
            facc.x += wj * v.x;
            facc.y += wj * v.y;
            facc.z += wj * v.z;
            facc.w += wj * v.w;
        }
        s_part[warp][lane] = facc;
    }
    __syncthreads();
    if (warp == 0 && lane < NL) {
        float4 tt = s_part[0][lane];
#pragma unroll
        for (int w = 1; w < W; w++) {
            float4 q = s_part[w][lane];
            tt.x += q.x; tt.y += q.y; tt.z += q.z; tt.w += q.w;
        }
        float4 b4 = *(const float4*)(jb.bias + lane * 4);
        float4 o4;
        o4.x = tt.x * inv + b4.x;
        o4.y = tt.y * inv + b4.y;
        o4.z = tt.z * inv + b4.z;
        o4.w = tt.w * inv + b4.w;
        *(float4*)(jb.out + (size_t)t * C + lane * 4) = o4;
    }
}

// ---------------- batch norm ----------------
template <int C>
__global__ void bn_stats(const float* __restrict__ h) {
    int c = blockIdx.x;
    int tid = threadIdx.x;
    float s = 0.f, s2 = 0.f;
    for (int r = tid; r < NN; r += 256) {
        float v = h[(size_t)r * C + c];
        s += v; s2 += v * v;
    }
    __shared__ float sh[8], sh2[8];
#pragma unroll
    for (int o = 16; o; o >>= 1) {
        s  += __shfl_xor_sync(0xffffffffu, s,  o);
        s2 += __shfl_xor_sync(0xffffffffu, s2, o);
    }
    if ((tid & 31) == 0) { sh[tid >> 5] = s; sh2[tid >> 5] = s2; }
    __syncthreads();
    if (tid == 0) {
        float ts = 0.f, ts2 = 0.f;
        for (int w = 0; w < 8; w++) { ts += sh[w]; ts2 += sh2[w]; }
        float mean = ts / NN;
        float var = ts2 / NN - mean * mean;
        g_mean[c] = mean;
        g_rstd[c] = rsqrtf(var + BN_EPS);
    }
}

template <int C>
__global__ void bn_apply_relu(float* __restrict__ buf, const float* __restrict__ g,
                              const float* __restrict__ b) {
    int i = blockIdx.x * blockDim.x + threadIdx.x;
    if (i >= NN * C) return;
    int c = i & (C - 1);
    float v = (buf[i] - g_mean[c]) * g_rstd[c] * g[c] + b[c];
    buf[i] = fmaxf(v, 0.f);
}

// ---------------- reparameterize ----------------
__global__ void k_reparam(const float* __restrict__ eps, float* __restrict__ out) {
    int i = blockIdx.x * blockDim.x + threadIdx.x;
    if (i >= NN * NHID2) return;
    float mu = out[MU_OFF + i];
    float lv = out[LV_OFF + i];
    out[EMB_OFF + i] = eps[i] * __expf(lv) + mu;
}

// ---------------- readj = sigmoid(emb @ emb^T), symmetric, f32x2 ----------
__global__ __launch_bounds__(256)
void gram_sigmoid_sym(const float* __restrict__ E, float* __restrict__ out) {
    int by = blockIdx.y, bx = blockIdx.x;
    if (bx < by) return;                      // upper triangle only
    __shared__ __align__(16) float Ea[32][132];
    __shared__ __align__(16) float Eb[32][132];
    int tid = threadIdx.x;
    int tx = tid & 15, ty = tid >> 4;
    int row0 = by * 128, col0 = bx * 128;
    u64 acc2[8][4];
#pragma unroll
    for (int i = 0; i < 8; i++)
#pragma unroll
        for (int j = 0; j < 4; j++) acc2[i][j] = 0ull;

#pragma unroll
    for (int k0 = 0; k0 < 64; k0 += 32) {
#pragma unroll
        for (int i = 0; i < 4; i++) {
            int idx = tid + i * 256;
            int m = idx >> 3;
            int kq = idx & 7;
            int r = row0 + m;
            float4 v = make_float4(0.f, 0.f, 0.f, 0.f);
            if (r < NN) v = *(const float4*)(E + (size_t)r * 64 + k0 + kq * 4);
            Ea[kq * 4 + 0][m] = v.x;
            Ea[kq * 4 + 1][m] = v.y;
            Ea[kq * 4 + 2][m] = v.z;
            Ea[kq * 4 + 3][m] = v.w;
            int c = col0 + m;
            float4 w = make_float4(0.f, 0.f, 0.f, 0.f);
            if (c < NN) w = *(const float4*)(E + (size_t)c * 64 + k0 + kq * 4);
            Eb[kq * 4 + 0][m] = w.x;
            Eb[kq * 4 + 1][m] = w.y;
            Eb[kq * 4 + 2][m] = w.z;
            Eb[kq * 4 + 3][m] = w.w;
        }
        __syncthreads();
#pragma unroll
        for (int kk = 0; kk < 32; kk++) {
            float4 a0 = *(const float4*)&Ea[kk][ty * 8];
            float4 a1 = *(const float4*)&Ea[kk][ty * 8 + 4];
            F4U b0, b1;
            b0.f4 = *(const float4*)&Eb[kk][tx * 8];
            b1.f4 = *(const float4*)&Eb[kk][tx * 8 + 4];
            u64 ap[8];
            ap[0] = pk2(a0.x, a0.x); ap[1] = pk2(a0.y, a0.y);
            ap[2] = pk2(a0.z, a0.z); ap[3] = pk2(a0.w, a0.w);
            ap[4] = pk2(a1.x, a1.x); ap[5] = pk2(a1.y, a1.y);
            ap[6] = pk2(a1.z, a1.z); ap[7] = pk2(a1.w, a1.w);
            u64 bu[4] = { b0.u[0], b0.u[1], b1.u[0], b1.u[1] };
#pragma unroll
            for (int i = 0; i < 8; i++)
#pragma unroll
                for (int j = 0; j < 4; j++) acc2[i][j] = fma2_(ap[i], bu[j], acc2[i][j]);
        }
        __syncthreads();
    }
    // unpack to scalars
    float acc[8][8];
#pragma unroll
    for (int i = 0; i < 8; i++)
#pragma unroll
        for (int j = 0; j < 4; j++) {
            float2 p = upk2(acc2[i][j]);
            acc[i][2 * j] = p.x;
            acc[i][2 * j + 1] = p.y;
        }
    // sigmoid + direct write (coalesced float2)
#pragma unroll
    for (int i = 0; i < 8; i++) {
        int r = row0 + ty * 8 + i;
        if (r < NN) {
#pragma unroll
            for (int j = 0; j < 8; j++) {
                int c = col0 + tx * 8 + j;
                float s = 1.f / (1.f + __expf(-acc[i][j]));
                acc[i][j] = s;
                if (c < NN) out[(size_t)r * NN + c] = s;
            }
        }
    }
    if (bx == by) return;                     // diagonal: mirror identical
    // mirror write: out[c][r]; per thread 8 runs of 8 contiguous floats
#pragma unroll
    for (int j = 0; j < 8; j++) {
        int c = col0 + tx * 8 + j;
        if (c < NN) {
#pragma unroll
            for (int i = 0; i < 8; i++) {
                int r = row0 + ty * 8 + i;
                if (r < NN) out[(size_t)c * NN + r] = acc[i][j];
            }
        }
    }
}

// ---------------- launch ----------------
extern "C" void kernel_launch(void* const* d_in, const int* in_sizes, int n_in,
                              void* d_out, int out_size) {
    const float* x   = (const float*)d_in[0];
    const int*   ei  = (const int*)  d_in[1];
    const float* eps = (const float*)d_in[2];
    const float* w1l = (const float*)d_in[3];
    const float* b1l = (const float*)d_in[4];
    const float* w1r = (const float*)d_in[5];
    const float* b1r = (const float*)d_in[6];
    const float* a1  = (const float*)d_in[7];
    const float* bias1 = (const float*)d_in[8];
    const float* bn1_g = (const float*)d_in[9];
    const float* bn1_b = (const float*)d_in[10];
    const float* w2l = (const float*)d_in[11];
    const float* b2l = (const float*)d_in[12];
    const float* w2r = (const float*)d_in[13];
    const float* b2r = (const float*)d_in[14];
    const float* a2  = (const float*)d_in[15];
    const float* bias2 = (const float*)d_in[16];
    const float* w3l = (const float*)d_in[17];
    const float* b3l = (const float*)d_in[18];
    const float* w3r = (const float*)d_in[19];
    const float* b3r = (const float*)d_in[20];
    const float* a3  = (const float*)d_in[21];
    const float* bias3 = (const float*)d_in[22];
    const float* dw1 = (const float*)d_in[23];
    const float* db1 = (const float*)d_in[24];
    const float* dbn_g = (const float*)d_in[25];
    const float* dbn_b = (const float*)d_in[26];
    const float* dw2 = (const float*)d_in[27];
    const float* db2 = (const float*)d_in[28];
    float* out = (float*)d_out;

    // resolve scratch symbol addresses
    float *p_xl1, *p_xr1, *p_h, *p_xl2, *p_xr2, *p_xl3, *p_xr3, *p_d;
    cudaGetSymbolAddress((void**)&p_xl1, g_xl1);
    cudaGetSymbolAddress((void**)&p_xr1, g_xr1);
    cudaGetSymbolAddress((void**)&p_h,   g_h);
    cudaGetSymbolAddress((void**)&p_xl2, g_xl2);
    cudaGetSymbolAddress((void**)&p_xr2, g_xr2);
    cudaGetSymbolAddress((void**)&p_xl3, g_xl3);
    cudaGetSymbolAddress((void**)&p_xr3, g_xr3);
    cudaGetSymbolAddress((void**)&p_d,   g_d);

    const int MT = (NN + 127) / 128;   // 79

    // ---- CSR build (edges + self loops, grouped by target) ----
    k_zero_counts<<<(NN + 255) / 256, 256>>>();
    k_count_deg<<<(NE + 255) / 256, 256>>>(ei);
    k_scan_deg<<<1, 1024>>>();
    k_fill_list<<<(NE + 255) / 256, 256>>>(ei);

    // ---- layer 1 linear transforms: two GEMMs fused into one launch ----
    {
        GJobs j1 = {{ { w1l, b1l, p_xl1 }, { w1r, b1r, p_xr1 }, {}, {} }};
        gemmA<<<dim3(H1 / 128, MT, 2), 256>>>(x, j1, NN, NFEAT, H1);
    }

    // ---- GAT layer 1 -> BN -> ReLU ----
    {
        AJobs aj = {{ { p_xl1, p_xr1, a1, bias1, p_h }, {} }};
        gat_agg<H1><<<dim3(NN, 1), H1>>>(aj);
    }
    bn_stats<H1><<<H1, 256>>>(p_h);
    bn_apply_relu<H1><<<(NN * H1 + 255) / 256, 256>>>(p_h, bn1_g, bn1_b);

    // ---- layers 2 & 3 linear transforms: four GEMMs in one launch ----
    {
        GJobs j2 = {{ { w2l, b2l, p_xl2 }, { w2r, b2r, p_xr2 },
                      { w3l, b3l, p_xl3 }, { w3r, b3r, p_xr3 } }};
        gemmB<<<dim3(NHID2 / 64, MT, 4), 256>>>(p_h, j2, NN, H1, NHID2);
    }

    // ---- GAT layers 2 (mu) and 3 (logvar) in one launch ----
    {
        AJobs aj = {{ { p_xl2, p_xr2, a2, bias2, out + MU_OFF },
                      { p_xl3, p_xr3, a3, bias3, out + LV_OFF } }};
        gat_agg<NHID2><<<dim3(NN, 2), NHID2>>>(aj);
    }

    // ---- reparameterize: emb = eps*exp(logvar)+mu ----
    k_reparam<<<(NN * NHID2 + 255) / 256, 256>>>(eps, out);

    // ---- readj = sigmoid(emb @ emb^T), symmetric tiles ----
    gram_sigmoid_sym<<<dim3(MT, MT), 256>>>(out + EMB_OFF, out + READJ_OFF);

    // ---- decoder MLP ----
    {
        GJobs jd = {{ { dw1, db1, p_d }, {}, {}, {} }};
        gemmB<<<dim3(NHID1 / 64, MT, 1), 256>>>(out + EMB_OFF, jd, NN, NHID2, NHID1);
    }
    bn_stats<NHID1><<<NHID1, 256>>>(p_d);
    bn_apply_relu<NHID1><<<(NN * NHID1 + 255) / 256, 256>>>(p_d, dbn_g, dbn_b);
    {
        GJobs jd = {{ { dw2, db2, out + REX_OFF }, {}, {}, {} }};
        gemmA<<<dim3(NFEAT / 128, MT, 1), 256>>>(p_d, jd, NN, NHID1, NFEAT);
    }
}

// round 5
// speedup vs baseline: 1.3291x; 1.1777x over previous
#include <cuda_runtime.h>
#include <cuda_bf16.h>
#include <cstdint>
#include <math.h>

#define NN     10000
#define EE     320000
#define NE     (EE + NN)     // with self loops
#define NFEAT  512
#define NHID1  256
#define NHID2  64
#define H1     128           // 2*NHID2
#define NEG_SLOPE 0.2f
#define BN_EPS 1e-5f
#define MAXDEG 512

// output layout (flattened tuple: emb, re_x, readj, mu, logvar)
#define EMB_OFF   ((size_t)0)
#define REX_OFF   ((size_t)NN * NHID2)                       // 640000
#define READJ_OFF (REX_OFF + (size_t)NN * NFEAT)             // 5760000
#define MU_OFF    (READJ_OFF + (size_t)NN * NN)              // 105760000
#define LV_OFF    (MU_OFF + (size_t)NN * NHID2)              // 106400000

typedef unsigned long long u64;

// ---------------- f32x2 packed helpers ----------------
__device__ __forceinline__ u64 pk2(float x, float y) {
    u64 r; asm("mov.b64 %0, {%1, %2};" : "=l"(r) : "f"(x), "f"(y)); return r;
}
__device__ __forceinline__ u64 fma2_(u64 a, u64 b, u64 c) {
    u64 d; asm("fma.rn.f32x2 %0, %1, %2, %3;" : "=l"(d) : "l"(a), "l"(b), "l"(c)); return d;
}
__device__ __forceinline__ float2 upk2(u64 v) {
    float lo, hi; asm("mov.b64 {%0, %1}, %2;" : "=f"(lo), "=f"(hi) : "l"(v));
    float2 r; r.x = lo; r.y = hi; return r;
}
union F4U { float4 f4; u64 u[2]; };

// ---------------- warp MMA helpers (baseline PTX, works on sm_103) --------
__device__ __forceinline__ uint32_t smem_u32(const void* p) {
    uint32_t a;
    asm("{ .reg .u64 t; cvta.to.shared.u64 t, %1; cvt.u32.u64 %0, t; }" : "=r"(a) : "l"(p));
    return a;
}
__device__ __forceinline__ void ldsm_x4(uint32_t& r0, uint32_t& r1, uint32_t& r2, uint32_t& r3, uint32_t addr) {
    asm volatile("ldmatrix.sync.aligned.m8n8.x4.shared.b16 {%0,%1,%2,%3}, [%4];"
                 : "=r"(r0), "=r"(r1), "=r"(r2), "=r"(r3) : "r"(addr));
}
__device__ __forceinline__ void ldsm_x2(uint32_t& r0, uint32_t& r1, uint32_t addr) {
    asm volatile("ldmatrix.sync.aligned.m8n8.x2.shared.b16 {%0,%1}, [%2];"
                 : "=r"(r0), "=r"(r1) : "r"(addr));
}
__device__ __forceinline__ void mma_bf16(float* d, uint32_t a0, uint32_t a1, uint32_t a2, uint32_t a3,
                                         uint32_t b0, uint32_t b1) {
    asm volatile("mma.sync.aligned.m16n8k16.row.col.f32.bf16.bf16.f32 "
                 "{%0,%1,%2,%3}, {%4,%5,%6,%7}, {%8,%9}, {%0,%1,%2,%3};"
                 : "+f"(d[0]), "+f"(d[1]), "+f"(d[2]), "+f"(d[3])
                 : "r"(a0), "r"(a1), "r"(a2), "r"(a3), "r"(b0), "r"(b1));
}

// ---------------- scratch (device globals; no allocation allowed) ----------
__device__ float g_xl1[NN * H1];
__device__ float g_xr1[NN * H1];
__device__ float g_h  [NN * H1];
__device__ float g_xl2[NN * NHID2];
__device__ float g_xr2[NN * NHID2];
__device__ float g_xl3[NN * NHID2];
__device__ float g_xr3[NN * NHID2];
__device__ float g_d  [NN * NHID1];
__device__ int   g_deg[NN];
__device__ int   g_rowptr[NN + 1];
__device__ int   g_cursor[NN];
__device__ int   g_srclist[NE];
__device__ float g_mean[NHID1];
__device__ float g_rstd[NHID1];

// ---------------- CSR build ----------------
__global__ void k_zero_counts() {
    int i = blockIdx.x * blockDim.x + threadIdx.x;
    if (i < NN) { g_deg[i] = 0; g_cursor[i] = 0; }
}

__global__ void k_count_deg(const int* __restrict__ edge_index) {
    int i = blockIdx.x * blockDim.x + threadIdx.x;
    if (i >= NE) return;
    int tgt = (i < EE) ? edge_index[EE + i] : (i - EE);
    atomicAdd(&g_deg[tgt], 1);
}

__global__ void k_scan_deg() {
    __shared__ int s[1024];
    __shared__ int sc;
    int tid = threadIdx.x;
    if (tid == 0) { sc = 0; g_rowptr[0] = 0; }
    __syncthreads();
    for (int base = 0; base < NN; base += 1024) {
        int i = base + tid;
        s[tid] = (i < NN) ? g_deg[i] : 0;
        __syncthreads();
        for (int off = 1; off < 1024; off <<= 1) {
            int t = (tid >= off) ? s[tid - off] : 0;
            __syncthreads();
            s[tid] += t;
            __syncthreads();
        }
        int c = sc;
        if (i < NN) g_rowptr[i + 1] = c + s[tid];
        __syncthreads();
        if (tid == 0) sc = c + s[1023];
        __syncthreads();
    }
}

__global__ void k_fill_list(const int* __restrict__ edge_index) {
    int i = blockIdx.x * blockDim.x + threadIdx.x;
    if (i >= NE) return;
    int src, tgt;
    if (i < EE) { src = edge_index[i]; tgt = edge_index[EE + i]; }
    else        { src = i - EE;        tgt = i - EE; }
    int pos = atomicAdd(&g_cursor[tgt], 1);
    g_srclist[g_rowptr[tgt] + pos] = src;
}

// ---------------- GEMM job plumbing ----------------
struct GJob  { const float* B; const float* bias; float* C; };
struct GJobs { GJob j[4]; };

// ---------------- gemmA: 128x128 tile, BK=16, 256 thr, 8x8/thread, f32x2 --
__global__ __launch_bounds__(256)
void gemmA(const float* __restrict__ A, GJobs jobs, int M, int K, int Nc) {
    const GJob jb = jobs.j[blockIdx.z];
    const float* __restrict__ B = jb.B;
    __shared__ __align__(16) float As[16][132];
    __shared__ __align__(16) float Bs[16][132];
    int tid = threadIdx.x;
    int tx = tid & 15, ty = tid >> 4;
    int row0 = blockIdx.y * 128, col0 = blockIdx.x * 128;
    u64 acc[8][4];
#pragma unroll
    for (int i = 0; i < 8; i++)
#pragma unroll
        for (int j = 0; j < 4; j++) acc[i][j] = 0ull;

    for (int k0 = 0; k0 < K; k0 += 16) {
#pragma unroll
        for (int i = 0; i < 2; i++) {
            int idx = tid + i * 256;
            int m = idx >> 2;
            int kq = idx & 3;
            int r = row0 + m;
            float4 v = make_float4(0.f, 0.f, 0.f, 0.f);
            if (r < M) v = *(const float4*)(A + (size_t)r * K + k0 + kq * 4);
            As[kq * 4 + 0][m] = v.x;
            As[kq * 4 + 1][m] = v.y;
            As[kq * 4 + 2][m] = v.z;
            As[kq * 4 + 3][m] = v.w;
        }
#pragma unroll
        for (int i = 0; i < 2; i++) {
            int idx = tid + i * 256;
            int k = idx >> 5;
            int nq = idx & 31;
            *(float4*)&Bs[k][nq * 4] = *(const float4*)(B + (size_t)(k0 + k) * Nc + col0 + nq * 4);
        }
        __syncthreads();
#pragma unroll
        for (int kk = 0; kk < 16; kk++) {
            float4 a0 = *(const float4*)&As[kk][ty * 8];
            float4 a1 = *(const float4*)&As[kk][ty * 8 + 4];
            F4U b0, b1;
            b0.f4 = *(const float4*)&Bs[kk][tx * 8];
            b1.f4 = *(const float4*)&Bs[kk][tx * 8 + 4];
            u64 ap[8];
            ap[0] = pk2(a0.x, a0.x); ap[1] = pk2(a0.y, a0.y);
            ap[2] = pk2(a0.z, a0.z); ap[3] = pk2(a0.w, a0.w);
            ap[4] = pk2(a1.x, a1.x); ap[5] = pk2(a1.y, a1.y);
            ap[6] = pk2(a1.z, a1.z); ap[7] = pk2(a1.w, a1.w);
            u64 bu[4] = { b0.u[0], b0.u[1], b1.u[0], b1.u[1] };
#pragma unroll
            for (int i = 0; i < 8; i++)
#pragma unroll
                for (int j = 0; j < 4; j++) acc[i][j] = fma2_(ap[i], bu[j], acc[i][j]);
        }
        __syncthreads();
    }
#pragma unroll
    for (int i = 0; i < 8; i++) {
        int r = row0 + ty * 8 + i;
        if (r < M) {
            float* Crow = jb.C + (size_t)r * Nc;
#pragma unroll
            for (int j = 0; j < 4; j++) {
                int c = col0 + tx * 8 + 2 * j;
                float2 p = upk2(acc[i][j]);
                p.x += __ldg(&jb.bias[c]);
                p.y += __ldg(&jb.bias[c + 1]);
                *(float2*)&Crow[c] = p;
            }
        }
    }
}

// ---------------- gemmB: 128x64 tile, BK=16, 256 thr, 8x4/thread, f32x2 ---
__global__ __launch_bounds__(256)
void gemmB(const float* __restrict__ A, GJobs jobs, int M, int K, int Nc) {
    const GJob jb = jobs.j[blockIdx.z];
    const float* __restrict__ B = jb.B;
    __shared__ __align__(16) float As[16][132];
    __shared__ __align__(16) float Bs[16][68];
    int tid = threadIdx.x;
    int tx = tid & 15, ty = tid >> 4;
    int row0 = blockIdx.y * 128, col0 = blockIdx.x * 64;
    u64 acc[8][2];
#pragma unroll
    for (int i = 0; i < 8; i++) { acc[i][0] = 0ull; acc[i][1] = 0ull; }

    for (int k0 = 0; k0 < K; k0 += 16) {
#pragma unroll
        for (int i = 0; i < 2; i++) {
            int idx = tid + i * 256;
            int m = idx >> 2;
            int kq = idx & 3;
            int r = row0 + m;
            float4 v = make_float4(0.f, 0.f, 0.f, 0.f);
            if (r < M) v = *(const float4*)(A + (size_t)r * K + k0 + kq * 4);
            As[kq * 4 + 0][m] = v.x;
            As[kq * 4 + 1][m] = v.y;
            As[kq * 4 + 2][m] = v.z;
            As[kq * 4 + 3][m] = v.w;
        }
        {
            int k = tid >> 4;
            int nq = tid & 15;
            *(float4*)&Bs[k][nq * 4] = *(const float4*)(B + (size_t)(k0 + k) * Nc + col0 + nq * 4);
        }
        __syncthreads();
#pragma unroll
        for (int kk = 0; kk < 16; kk++) {
            float4 a0 = *(const float4*)&As[kk][ty * 8];
            float4 a1 = *(const float4*)&As[kk][ty * 8 + 4];
            F4U b0;
            b0.f4 = *(const float4*)&Bs[kk][tx * 4];
            u64 ap[8];
            ap[0] = pk2(a0.x, a0.x); ap[1] = pk2(a0.y, a0.y);
            ap[2] = pk2(a0.z, a0.z); ap[3] = pk2(a0.w, a0.w);
            ap[4] = pk2(a1.x, a1.x); ap[5] = pk2(a1.y, a1.y);
            ap[6] = pk2(a1.z, a1.z); ap[7] = pk2(a1.w, a1.w);
            u64 bu[2] = { b0.u[0], b0.u[1] };
#pragma unroll
            for (int i = 0; i < 8; i++) {
                acc[i][0] = fma2_(ap[i], bu[0], acc[i][0]);
                acc[i][1] = fma2_(ap[i], bu[1], acc[i][1]);
            }
        }
        __syncthreads();
    }
#pragma unroll
    for (int i = 0; i < 8; i++) {
        int r = row0 + ty * 8 + i;
        if (r < M) {
            float* Crow = jb.C + (size_t)r * Nc;
#pragma unroll
            for (int j = 0; j < 2; j++) {
                int c = col0 + tx * 4 + 2 * j;
                float2 p = upk2(acc[i][j]);
                p.x += __ldg(&jb.bias[c]);
                p.y += __ldg(&jb.bias[c + 1]);
                *(float2*)&Crow[c] = p;
            }
        }
    }
}

// ---------------- GATv2 aggregation (one block per target node) -----------
struct AJob  { const float* xl; const float* xr; const float* att; const float* bias; float* out; };
struct AJobs { AJob j[2]; };

template <int C>
__global__ void gat_agg(AJobs jobs) {
    constexpr int W  = C / 32;
    constexpr int NL = C / 4;
    const AJob jb = jobs.j[blockIdx.y];
    int t = blockIdx.x;
    int tid = threadIdx.x, lane = tid & 31, warp = tid >> 5;
    __shared__ float4 s_xr4[NL], s_att4[NL];
    __shared__ float  s_e[MAXDEG];
    __shared__ int    s_src[MAXDEG];
    __shared__ float  s_red[W];
    __shared__ float4 s_part[W][NL];
    if (tid < NL) {
        s_xr4[tid]  = *(const float4*)(jb.xr + (size_t)t * C + tid * 4);
        s_att4[tid] = *(const float4*)(jb.att + tid * 4);
    }
    int beg = g_rowptr[t];
    int deg = g_rowptr[t + 1] - beg;
    __syncthreads();

    float4 xr4 = make_float4(0.f, 0.f, 0.f, 0.f);
    float4 at4 = xr4;
    if (lane < NL) { xr4 = s_xr4[lane]; at4 = s_att4[lane]; }

    for (int j = warp; j < deg; j += W) {
        int src = g_srclist[beg + j];
        float p = 0.f;
        if (lane < NL) {
            float4 v = *(const float4*)(jb.xl + (size_t)src * C + lane * 4);
            float sx = v.x + xr4.x; sx = fmaxf(sx, NEG_SLOPE * sx);
            float sy = v.y + xr4.y; sy = fmaxf(sy, NEG_SLOPE * sy);
            float sz = v.z + xr4.z; sz = fmaxf(sz, NEG_SLOPE * sz);
            float sw = v.w + xr4.w; sw = fmaxf(sw, NEG_SLOPE * sw);
            p = at4.x * sx + at4.y * sy + at4.z * sz + at4.w * sw;
        }
#pragma unroll
        for (int o = 16; o; o >>= 1) p += __shfl_xor_sync(0xffffffffu, p, o);
        if (lane == 0) { s_e[j] = p; s_src[j] = src; }
    }
    __syncthreads();

    float m = -1e30f;
    for (int j = tid; j < deg; j += C) m = fmaxf(m, s_e[j]);
#pragma unroll
    for (int o = 16; o; o >>= 1) m = fmaxf(m, __shfl_xor_sync(0xffffffffu, m, o));
    if (lane == 0) s_red[warp] = m;
    __syncthreads();
    m = s_red[0];
#pragma unroll
    for (int w = 1; w < W; w++) m = fmaxf(m, s_red[w]);
    __syncthreads();

    float ssum = 0.f;
    for (int j = tid; j < deg; j += C) {
        float wj = __expf(s_e[j] - m);
        s_e[j] = wj;
        ssum += wj;
    }
#pragma unroll
    for (int o = 16; o; o >>= 1) ssum += __shfl_xor_sync(0xffffffffu, ssum, o);
    if (lane == 0) s_red[warp] = ssum;
    __syncthreads();
    ssum = 0.f;
#pragma unroll
    for (int w = 0; w < W; w++) ssum += s_red[w];
    float inv = 1.f / ssum;

    float4 facc = make_float4(0.f, 0.f, 0.f, 0.f);
    if (lane < NL) {
        for (int j = warp; j < deg; j += W) {
            float wj = s_e[j];
            float4 v = *(const float4*)(jb.xl + (size_t)s_src[j] * C + lane * 4);
            facc.x += wj * v.x;
            facc.y += wj * v.y;
            facc.z += wj * v.z;
            facc.w += wj * v.w;
        }
        s_part[warp][lane] = facc;
    }
    __syncthreads();
    if (warp == 0 && lane < NL) {
        float4 tt = s_part[0][lane];
#pragma unroll
        for (int w = 1; w < W; w++) {
            float4 q = s_part[w][lane];
            tt.x += q.x; tt.y += q.y; tt.z += q.z; tt.w += q.w;
        }
        float4 b4 = *(const float4*)(jb.bias + lane * 4);
        float4 o4;
        o4.x = tt.x * inv + b4.x;
        o4.y = tt.y * inv + b4.y;
        o4.z = tt.z * inv + b4.z;
        o4.w = tt.w * inv + b4.w;
        *(float4*)(jb.out + (size_t)t * C + lane * 4) = o4;
    }
}

// ---------------- batch norm ----------------
template <int C>
__global__ void bn_stats(const float* __restrict__ h) {
    int c = blockIdx.x;
    int tid = threadIdx.x;
    float s = 0.f, s2 = 0.f;
    for (int r = tid; r < NN; r += 256) {
        float v = h[(size_t)r * C + c];
        s += v; s2 += v * v;
    }
    __shared__ float sh[8], sh2[8];
#pragma unroll
    for (int o = 16; o; o >>= 1) {
        s  += __shfl_xor_sync(0xffffffffu, s,  o);
        s2 += __shfl_xor_sync(0xffffffffu, s2, o);
    }
    if ((tid & 31) == 0) { sh[tid >> 5] = s; sh2[tid >> 5] = s2; }
    __syncthreads();
    if (tid == 0) {
        float ts = 0.f, ts2 = 0.f;
        for (int w = 0; w < 8; w++) { ts += sh[w]; ts2 += sh2[w]; }
        float mean = ts / NN;
        float var = ts2 / NN - mean * mean;
        g_mean[c] = mean;
        g_rstd[c] = rsqrtf(var + BN_EPS);
    }
}

template <int C>
__global__ void bn_apply_relu(float* __restrict__ buf, const float* __restrict__ g,
                              const float* __restrict__ b) {
    int i = blockIdx.x * blockDim.x + threadIdx.x;
    if (i >= NN * C) return;
    int c = i & (C - 1);
    float v = (buf[i] - g_mean[c]) * g_rstd[c] * g[c] + b[c];
    buf[i] = fmaxf(v, 0.f);
}

// ---------------- reparameterize ----------------
__global__ void k_reparam(const float* __restrict__ eps, float* __restrict__ out) {
    int i = blockIdx.x * blockDim.x + threadIdx.x;
    if (i >= NN * NHID2) return;
    float mu = out[MU_OFF + i];
    float lv = out[LV_OFF + i];
    out[EMB_OFF + i] = eps[i] * __expf(lv) + mu;
}

// ---------------- readj = sigmoid(emb @ emb^T) via bf16 HMMA split --------
// 128x128 tile per block (256 thr = 8 warps, warp tile 64x32), upper-tri only.
// Split precision: 3 passes hi*hi + hi*lo + lo*hi in fp32 accumulators.
// smem layout (dynamic): Ahi/Alo/Bhi/Blo as [128][72] bf16 (row pad 72 for
// 16B-aligned ldmatrix rows + conflict-free banks). Reused as fp32 staging
// for the transposed mirror write after the MMA phase.
#define GP 72
#define G_AHI 0
#define G_ALO (G_AHI + 128 * GP * 2)     // 18432
#define G_BHI (G_ALO + 128 * GP * 2)
#define G_BLO (G_BHI + 128 * GP * 2)
#define G_SMEM (G_BLO + 128 * GP * 2)    // 73728

__global__ __launch_bounds__(256)
void gram_hmma(const float* __restrict__ E, float* __restrict__ out) {
    int by = blockIdx.y, bx = blockIdx.x;
    if (bx < by) return;
    extern __shared__ __align__(16) char smem[];
    uint32_t sb = smem_u32(smem);
    int tid = threadIdx.x, lane = tid & 31, warp = tid >> 5;
    int row0 = by * 128, col0 = bx * 128;

    // ---- fill: thread handles half a row (32 k-values) for A and B sides
    {
        int rrow = tid >> 1;               // 0..127
        int ks = (tid & 1) * 32;           // 0 or 32
        int rA = row0 + rrow, rB = col0 + rrow;
        const float4* pa = (const float4*)(E + (size_t)rA * 64 + ks);
        const float4* pb = (const float4*)(E + (size_t)rB * 64 + ks);
        bool va = rA < NN, vb = rB < NN;
        uint32_t base = (rrow * GP + ks) * 2;   // byte offset of first element
#pragma unroll
        for (int q = 0; q < 8; q++) {
            float4 a = va ? pa[q] : make_float4(0.f, 0.f, 0.f, 0.f);
            float4 b = vb ? pb[q] : make_float4(0.f, 0.f, 0.f, 0.f);
            float av[4] = { a.x, a.y, a.z, a.w };
            float bv[4] = { b.x, b.y, b.z, b.w };
#pragma unroll
            for (int h = 0; h < 2; h++) {
                __nv_bfloat16 h0 = __float2bfloat16_rn(av[2 * h]);
                __nv_bfloat16 h1 = __float2bfloat16_rn(av[2 * h + 1]);
                __nv_bfloat16 l0 = __float2bfloat16_rn(av[2 * h] - __bfloat162float(h0));
                __nv_bfloat16 l1 = __float2bfloat16_rn(av[2 * h + 1] - __bfloat162float(h1));
                uint32_t ah = (uint32_t)__bfloat16_as_ushort(h0) | ((uint32_t)__bfloat16_as_ushort(h1) << 16);
                uint32_t al = (uint32_t)__bfloat16_as_ushort(l0) | ((uint32_t)__bfloat16_as_ushort(l1) << 16);
                __nv_bfloat16 g0 = __float2bfloat16_rn(bv[2 * h]);
                __nv_bfloat16 g1 = __float2bfloat16_rn(bv[2 * h + 1]);
                __nv_bfloat16 m0 = __float2bfloat16_rn(bv[2 * h] - __bfloat162float(g0));
                __nv_bfloat16 m1 = __float2bfloat16_rn(bv[2 * h + 1] - __bfloat162float(g1));
                uint32_t bh = (uint32_t)__bfloat16_as_ushort(g0) | ((uint32_t)__bfloat16_as_ushort(g1) << 16);
                uint32_t bl = (uint32_t)__bfloat16_as_ushort(m0) | ((uint32_t)__bfloat16_as_ushort(m1) << 16);
                uint32_t off = base + (q * 4 + h * 2) * 2;
                *(uint32_t*)(smem + G_AHI + off) = ah;
                *(uint32_t*)(smem + G_ALO + off) = al;
                *(uint32_t*)(smem + G_BHI + off) = bh;
                *(uint32_t*)(smem + G_BLO + off) = bl;
            }
        }
    }
    __syncthreads();

    // ---- warp-tiled MMA: warp (wm, wn): rows wm*64.., cols wn*32..
    int wm = (warp & 1) * 64;
    int wn = (warp >> 1) * 32;
    float c[4][4][4];
#pragma unroll
    for (int mi = 0; mi < 4; mi++)
#pragma unroll
        for (int ni = 0; ni < 4; ni++)
#pragma unroll
            for (int e = 0; e < 4; e++) c[mi][ni][e] = 0.f;

    int grp = lane >> 3, rl = lane & 7;
#pragma unroll
    for (int pass = 0; pass < 3; pass++) {
        uint32_t aBase = sb + ((pass == 2) ? G_ALO : G_AHI);
        uint32_t bBase = sb + ((pass == 1) ? G_BLO : G_BHI);
#pragma unroll
        for (int k0 = 0; k0 < 64; k0 += 16) {
            uint32_t af[4][4], bf[4][2];
#pragma unroll
            for (int mi = 0; mi < 4; mi++) {
                int arow = wm + mi * 16 + (grp & 1) * 8 + rl;
                int acol = k0 + (grp >> 1) * 8;
                ldsm_x4(af[mi][0], af[mi][1], af[mi][2], af[mi][3],
                        aBase + (arow * GP + acol) * 2);
            }
#pragma unroll
            for (int ni = 0; ni < 4; ni++) {
                int brow = wn + ni * 8 + rl;
                int bcol = k0 + (grp & 1) * 8;
                ldsm_x2(bf[ni][0], bf[ni][1], bBase + (brow * GP + bcol) * 2);
            }
#pragma unroll
            for (int mi = 0; mi < 4; mi++)
#pragma unroll
                for (int ni = 0; ni < 4; ni++)
                    mma_bf16(c[mi][ni], af[mi][0], af[mi][1], af[mi][2], af[mi][3],
                             bf[ni][0], bf[ni][1]);
        }
    }
    __syncthreads();   // all ldmatrix reads done; smem can be reused

    // ---- epilogue: sigmoid, direct write + staging for mirror
    float* stag = (float*)smem;   // [128][128] xor-swizzled fp32
    bool diag = (bx == by);
    int qr = lane >> 2, qc = 2 * (lane & 3);
#pragma unroll
    for (int mi = 0; mi < 4; mi++) {
#pragma unroll
        for (int ni = 0; ni < 4; ni++) {
#pragma unroll
            for (int half = 0; half < 2; half++) {
                int row = wm + mi * 16 + qr + half * 8;
                int col = wn + ni * 8 + qc;
                float v0 = 1.f / (1.f + __expf(-c[mi][ni][2 * half]));
                float v1 = 1.f / (1.f + __expf(-c[mi][ni][2 * half + 1]));
                int r = row0 + row, cc = col0 + col;
                if (r < NN && cc < NN)
                    *(float2*)(out + (size_t)r * NN + cc) = make_float2(v0, v1);
                if (!diag) {
                    int s = row & 31;
                    stag[row * 128 + (col ^ s)] = v0;
                    stag[row * 128 + ((col + 1) ^ s)] = v1;
                }
            }
        }
    }
    if (diag) return;
    __syncthreads();

    // ---- mirror: 2 threads per mirror row, 64 contiguous floats each
    {
        int mr = tid >> 1;                 // 0..127 (col index within tile)
        int half = tid & 1;
        int cgl = col0 + mr;
        if (cgl < NN) {
            float* mrow = out + (size_t)cgl * NN + row0 + half * 64;
            int ibase = half * 64;
#pragma unroll
            for (int i = 0; i < 64; i += 4) {
                int i0 = ibase + i;
                if (row0 + i0 < NN) {
                    float4 w;
                    w.x = stag[(i0 + 0) * 128 + (mr ^ ((i0 + 0) & 31))];
                    w.y = stag[(i0 + 1) * 128 + (mr ^ ((i0 + 1) & 31))];
                    w.z = stag[(i0 + 2) * 128 + (mr ^ ((i0 + 2) & 31))];
                    w.w = stag[(i0 + 3) * 128 + (mr ^ ((i0 + 3) & 31))];
                    *(float4*)mrow = w;
                }
                mrow += 4;
            }
        }
    }
}

// ---------------- launch ----------------
extern "C" void kernel_launch(void* const* d_in, const int* in_sizes, int n_in,
                              void* d_out, int out_size) {
    const float* x   = (const float*)d_in[0];
    const int*   ei  = (const int*)  d_in[1];
    const float* eps = (const float*)d_in[2];
    const float* w1l = (const float*)d_in[3];
    const float* b1l = (const float*)d_in[4];
    const float* w1r = (const float*)d_in[5];
    const float* b1r = (const float*)d_in[6];
    const float* a1  = (const float*)d_in[7];
    const float* bias1 = (const float*)d_in[8];
    const float* bn1_g = (const float*)d_in[9];
    const float* bn1_b = (const float*)d_in[10];
    const float* w2l = (const float*)d_in[11];
    const float* b2l = (const float*)d_in[12];
    const float* w2r = (const float*)d_in[13];
    const float* b2r = (const float*)d_in[14];
    const float* a2  = (const float*)d_in[15];
    const float* bias2 = (const float*)d_in[16];
    const float* w3l = (const float*)d_in[17];
    const float* b3l = (const float*)d_in[18];
    const float* w3r = (const float*)d_in[19];
    const float* b3r = (const float*)d_in[20];
    const float* a3  = (const float*)d_in[21];
    const float* bias3 = (const float*)d_in[22];
    const float* dw1 = (const float*)d_in[23];
    const float* db1 = (const float*)d_in[24];
    const float* dbn_g = (const float*)d_in[25];
    const float* dbn_b = (const float*)d_in[26];
    const float* dw2 = (const float*)d_in[27];
    const float* db2 = (const float*)d_in[28];
    float* out = (float*)d_out;

    float *p_xl1, *p_xr1, *p_h, *p_xl2, *p_xr2, *p_xl3, *p_xr3, *p_d;
    cudaGetSymbolAddress((void**)&p_xl1, g_xl1);
    cudaGetSymbolAddress((void**)&p_xr1, g_xr1);
    cudaGetSymbolAddress((void**)&p_h,   g_h);
    cudaGetSymbolAddress((void**)&p_xl2, g_xl2);
    cudaGetSymbolAddress((void**)&p_xr2, g_xr2);
    cudaGetSymbolAddress((void**)&p_xl3, g_xl3);
    cudaGetSymbolAddress((void**)&p_xr3, g_xr3);
    cudaGetSymbolAddress((void**)&p_d,   g_d);

    cudaFuncSetAttribute(gram_hmma, cudaFuncAttributeMaxDynamicSharedMemorySize, G_SMEM);

    const int MT = (NN + 127) / 128;   // 79

    // ---- CSR build ----
    k_zero_counts<<<(NN + 255) / 256, 256>>>();
    k_count_deg<<<(NE + 255) / 256, 256>>>(ei);
    k_scan_deg<<<1, 1024>>>();
    k_fill_list<<<(NE + 255) / 256, 256>>>(ei);

    // ---- layer 1 linear transforms ----
    {
        GJobs j1 = {{ { w1l, b1l, p_xl1 }, { w1r, b1r, p_xr1 }, {}, {} }};
        gemmA<<<dim3(H1 / 128, MT, 2), 256>>>(x, j1, NN, NFEAT, H1);
    }

    // ---- GAT layer 1 -> BN -> ReLU ----
    {
        AJobs aj = {{ { p_xl1, p_xr1, a1, bias1, p_h }, {} }};
        gat_agg<H1><<<dim3(NN, 1), H1>>>(aj);
    }
    bn_stats<H1><<<H1, 256>>>(p_h);
    bn_apply_relu<H1><<<(NN * H1 + 255) / 256, 256>>>(p_h, bn1_g, bn1_b);

    // ---- layers 2 & 3 linear transforms ----
    {
        GJobs j2 = {{ { w2l, b2l, p_xl2 }, { w2r, b2r, p_xr2 },
                      { w3l, b3l, p_xl3 }, { w3r, b3r, p_xr3 } }};
        gemmB<<<dim3(NHID2 / 64, MT, 4), 256>>>(p_h, j2, NN, H1, NHID2);
    }

    // ---- GAT layers 2 (mu) and 3 (logvar) ----
    {
        AJobs aj = {{ { p_xl2, p_xr2, a2, bias2, out + MU_OFF },
                      { p_xl3, p_xr3, a3, bias3, out + LV_OFF } }};
        gat_agg<NHID2><<<dim3(NN, 2), NHID2>>>(aj);
    }

    // ---- reparameterize ----
    k_reparam<<<(NN * NHID2 + 255) / 256, 256>>>(eps, out);

    // ---- readj = sigmoid(emb @ emb^T) on tensor cores (HMMA) ----
    gram_hmma<<<dim3(MT, MT), 256, G_SMEM>>>(out + EMB_OFF, out + READJ_OFF);

    // ---- decoder MLP ----
    {
        GJobs jd = {{ { dw1, db1, p_d }, {}, {}, {} }};
        gemmB<<<dim3(NHID1 / 64, MT, 1), 256>>>(out + EMB_OFF, jd, NN, NHID2, NHID1);
    }
    bn_stats<NHID1><<<NHID1, 256>>>(p_d);
    bn_apply_relu<NHID1><<<(NN * NHID1 + 255) / 256, 256>>>(p_d, dbn_g, dbn_b);
    {
        GJobs jd = {{ { dw2, db2, out + REX_OFF }, {}, {}, {} }};
        gemmA<<<dim3(NFEAT / 128, MT, 1), 256>>>(p_d, jd, NN, NHID1, NFEAT);
    }
}

// round 6
// speedup vs baseline: 1.4883x; 1.1198x over previous
#include <cuda_runtime.h>
#include <cuda_bf16.h>
#include <cstdint>
#include <math.h>

#define NN     10000
#define EE     320000
#define NE     (EE + NN)     // with self loops
#define NFEAT  512
#define NHID1  256
#define NHID2  64
#define H1     128           // 2*NHID2
#define NEG_SLOPE 0.2f
#define BN_EPS 1e-5f
#define MAXDEG 512

// output layout (flattened tuple: emb, re_x, readj, mu, logvar)
#define EMB_OFF   ((size_t)0)
#define REX_OFF   ((size_t)NN * NHID2)                       // 640000
#define READJ_OFF (REX_OFF + (size_t)NN * NFEAT)             // 5760000
#define MU_OFF    (READJ_OFF + (size_t)NN * NN)              // 105760000
#define LV_OFF    (MU_OFF + (size_t)NN * NHID2)              // 106400000

typedef unsigned long long u64;

// ---------------- f32x2 packed helpers ----------------
__device__ __forceinline__ u64 pk2(float x, float y) {
    u64 r; asm("mov.b64 %0, {%1, %2};" : "=l"(r) : "f"(x), "f"(y)); return r;
}
__device__ __forceinline__ u64 fma2_(u64 a, u64 b, u64 c) {
    u64 d; asm("fma.rn.f32x2 %0, %1, %2, %3;" : "=l"(d) : "l"(a), "l"(b), "l"(c)); return d;
}
__device__ __forceinline__ float2 upk2(u64 v) {
    float lo, hi; asm("mov.b64 {%0, %1}, %2;" : "=f"(lo), "=f"(hi) : "l"(v));
    float2 r; r.x = lo; r.y = hi; return r;
}
union F4U { float4 f4; u64 u[2]; };

// ---------------- warp MMA helpers (baseline PTX, works on sm_103) --------
__device__ __forceinline__ uint32_t smem_u32(const void* p) {
    uint32_t a;
    asm("{ .reg .u64 t; cvta.to.shared.u64 t, %1; cvt.u32.u64 %0, t; }" : "=r"(a) : "l"(p));
    return a;
}
__device__ __forceinline__ void ldsm_x4(uint32_t& r0, uint32_t& r1, uint32_t& r2, uint32_t& r3, uint32_t addr) {
    asm volatile("ldmatrix.sync.aligned.m8n8.x4.shared.b16 {%0,%1,%2,%3}, [%4];"
                 : "=r"(r0), "=r"(r1), "=r"(r2), "=r"(r3) : "r"(addr));
}
__device__ __forceinline__ void ldsm_x2(uint32_t& r0, uint32_t& r1, uint32_t addr) {
    asm volatile("ldmatrix.sync.aligned.m8n8.x2.shared.b16 {%0,%1}, [%2];"
                 : "=r"(r0), "=r"(r1) : "r"(addr));
}
__device__ __forceinline__ void mma_bf16(float* d, uint32_t a0, uint32_t a1, uint32_t a2, uint32_t a3,
                                         uint32_t b0, uint32_t b1) {
    asm volatile("mma.sync.aligned.m16n8k16.row.col.f32.bf16.bf16.f32 "
                 "{%0,%1,%2,%3}, {%4,%5,%6,%7}, {%8,%9}, {%0,%1,%2,%3};"
                 : "+f"(d[0]), "+f"(d[1]), "+f"(d[2]), "+f"(d[3])
                 : "r"(a0), "r"(a1), "r"(a2), "r"(a3), "r"(b0), "r"(b1));
}
__device__ __forceinline__ void bf16split(float v, uint16_t& h, uint16_t& l) {
    __nv_bfloat16 hb = __float2bfloat16_rn(v);
    __nv_bfloat16 lb = __float2bfloat16_rn(v - __bfloat162float(hb));
    h = __bfloat16_as_ushort(hb);
    l = __bfloat16_as_ushort(lb);
}

// ---------------- scratch (device globals; no allocation allowed) ----------
__device__ float g_xl1[NN * H1];
__device__ float g_xr1[NN * H1];
__device__ float g_h  [NN * H1];
__device__ float g_xl2[NN * NHID2];
__device__ float g_xr2[NN * NHID2];
__device__ float g_xl3[NN * NHID2];
__device__ float g_xr3[NN * NHID2];
__device__ float g_d  [NN * NHID1];
__device__ int   g_deg[NN];
__device__ int   g_rowptr[NN + 1];
__device__ int   g_cursor[NN];
__device__ int   g_srclist[NE];
__device__ float g_mean[NHID1];
__device__ float g_rstd[NHID1];
// transposed bf16 hi/lo weights [Nc][K]
__device__ uint16_t g_w1lh[H1 * NFEAT], g_w1ll[H1 * NFEAT];
__device__ uint16_t g_w1rh[H1 * NFEAT], g_w1rl[H1 * NFEAT];
__device__ uint16_t g_dw2h[NFEAT * NHID1], g_dw2l[NFEAT * NHID1];

// ---------------- CSR build ----------------
__global__ void k_zero_counts() {
    int i = blockIdx.x * blockDim.x + threadIdx.x;
    if (i < NN) { g_deg[i] = 0; g_cursor[i] = 0; }
}

__global__ void k_count_deg(const int* __restrict__ edge_index) {
    int i = blockIdx.x * blockDim.x + threadIdx.x;
    if (i >= NE) return;
    int tgt = (i < EE) ? edge_index[EE + i] : (i - EE);
    atomicAdd(&g_deg[tgt], 1);
}

__global__ void k_scan_deg() {
    __shared__ int s[1024];
    __shared__ int sc;
    int tid = threadIdx.x;
    if (tid == 0) { sc = 0; g_rowptr[0] = 0; }
    __syncthreads();
    for (int base = 0; base < NN; base += 1024) {
        int i = base + tid;
        s[tid] = (i < NN) ? g_deg[i] : 0;
        __syncthreads();
        for (int off = 1; off < 1024; off <<= 1) {
            int t = (tid >= off) ? s[tid - off] : 0;
            __syncthreads();
            s[tid] += t;
            __syncthreads();
        }
        int c = sc;
        if (i < NN) g_rowptr[i + 1] = c + s[tid];
        __syncthreads();
        if (tid == 0) sc = c + s[1023];
        __syncthreads();
    }
}

__global__ void k_fill_list(const int* __restrict__ edge_index) {
    int i = blockIdx.x * blockDim.x + threadIdx.x;
    if (i >= NE) return;
    int src, tgt;
    if (i < EE) { src = edge_index[i]; tgt = edge_index[EE + i]; }
    else        { src = i - EE;        tgt = i - EE; }
    int pos = atomicAdd(&g_cursor[tgt], 1);
    g_srclist[g_rowptr[tgt] + pos] = src;
}

// ---------------- weight transpose + bf16 split: W[K][Nc] -> Wt[Nc][K] ----
__global__ void k_wsplit(const float* __restrict__ W, uint16_t* __restrict__ hi,
                         uint16_t* __restrict__ lo, int K, int Nc) {
    int i = blockIdx.x * blockDim.x + threadIdx.x;
    if (i >= K * Nc) return;
    int n = i / K, k = i - n * K;
    float v = W[(size_t)k * Nc + n];
    uint16_t h, l;
    bf16split(v, h, l);
    hi[i] = h; lo[i] = l;
}

// ---------------- GEMM job plumbing ----------------
struct GJob  { const float* B; const float* bias; float* C; };
struct GJobs { GJob j[4]; };
struct TJob  { const uint16_t* Bh; const uint16_t* Bl; const float* bias; float* C; };
struct TJobs { TJob j[2]; };

// ---------------- gemmT: HMMA bf16 split GEMM, 128x128 tile --------------
// A fp32 [M,K] (converted per tile), B pre-split bf16 [Nc][K].
// 256 thr = 8 warps (warp tile 64x32). K % 32 == 0, Nc % 128 == 0.
__global__ __launch_bounds__(256)
void gemmT(const float* __restrict__ A, TJobs jobs, int M, int K, int Nc) {
    const TJob jb = jobs.j[blockIdx.z];
    __shared__ __align__(16) uint16_t Ah[128][40], Al[128][40];
    __shared__ __align__(16) uint16_t Bh[128][40], Bl[128][40];
    int tid = threadIdx.x, lane = tid & 31, warp = tid >> 5;
    int row0 = blockIdx.y * 128, col0 = blockIdx.x * 128;
    int wm = (warp & 1) * 64, wn = (warp >> 1) * 32;
    int grp = lane >> 3, rl = lane & 7;
    float c[4][4][4];
#pragma unroll
    for (int mi = 0; mi < 4; mi++)
#pragma unroll
        for (int ni = 0; ni < 4; ni++)
#pragma unroll
            for (int e = 0; e < 4; e++) c[mi][ni][e] = 0.f;

    int ar = tid >> 1, kh = (tid & 1) * 16;
    int r = row0 + ar;
    bool va = r < M;

    for (int k0 = 0; k0 < K; k0 += 32) {
        // A tile: 128 rows x 32 k fp32 -> hi/lo bf16
        const float* pa = A + (size_t)r * K + k0 + kh;
#pragma unroll
        for (int q = 0; q < 4; q++) {
            float4 v = va ? *(const float4*)(pa + q * 4) : make_float4(0.f, 0.f, 0.f, 0.f);
            uint16_t h0, l0, h1, l1, h2, l2, h3, l3;
            bf16split(v.x, h0, l0); bf16split(v.y, h1, l1);
            bf16split(v.z, h2, l2); bf16split(v.w, h3, l3);
            uint32_t hh0 = (uint32_t)h0 | ((uint32_t)h1 << 16);
            uint32_t hh1 = (uint32_t)h2 | ((uint32_t)h3 << 16);
            uint32_t ll0 = (uint32_t)l0 | ((uint32_t)l1 << 16);
            uint32_t ll1 = (uint32_t)l2 | ((uint32_t)l3 << 16);
            *(uint32_t*)&Ah[ar][kh + q * 4]     = hh0;
            *(uint32_t*)&Ah[ar][kh + q * 4 + 2] = hh1;
            *(uint32_t*)&Al[ar][kh + q * 4]     = ll0;
            *(uint32_t*)&Al[ar][kh + q * 4 + 2] = ll1;
        }
        // B tile: 128 n-rows x 32 k bf16 (already [Nc][K])
        {
            const uint16_t* pbh = jb.Bh + (size_t)(col0 + ar) * K + k0 + kh;
            const uint16_t* pbl = jb.Bl + (size_t)(col0 + ar) * K + k0 + kh;
            *(uint4*)&Bh[ar][kh]     = *(const uint4*)pbh;
            *(uint4*)&Bh[ar][kh + 8] = *(const uint4*)(pbh + 8);
            *(uint4*)&Bl[ar][kh]     = *(const uint4*)pbl;
            *(uint4*)&Bl[ar][kh + 8] = *(const uint4*)(pbl + 8);
        }
        __syncthreads();
#pragma unroll
        for (int pass = 0; pass < 3; pass++) {
            const uint16_t (*Aq)[40] = (pass == 2) ? Al : Ah;
            const uint16_t (*Bq)[40] = (pass == 1) ? Bl : Bh;
#pragma unroll
            for (int k1 = 0; k1 < 32; k1 += 16) {
                uint32_t af[4][4], bf[4][2];
#pragma unroll
                for (int mi = 0; mi < 4; mi++) {
                    int arow = wm + mi * 16 + (grp & 1) * 8 + rl;
                    int acol = k1 + (grp >> 1) * 8;
                    ldsm_x4(af[mi][0], af[mi][1], af[mi][2], af[mi][3],
                            smem_u32(&Aq[arow][acol]));
                }
#pragma unroll
                for (int ni = 0; ni < 4; ni++) {
                    int brow = wn + ni * 8 + rl;
                    int bcol = k1 + (grp & 1) * 8;
                    ldsm_x2(bf[ni][0], bf[ni][1], smem_u32(&Bq[brow][bcol]));
                }
#pragma unroll
                for (int mi = 0; mi < 4; mi++)
#pragma unroll
                    for (int ni = 0; ni < 4; ni++)
                        mma_bf16(c[mi][ni], af[mi][0], af[mi][1], af[mi][2], af[mi][3],
                                 bf[ni][0], bf[ni][1]);
            }
        }
        __syncthreads();
    }
    // epilogue: bias + store
    int qr = lane >> 2, qc = 2 * (lane & 3);
#pragma unroll
    for (int mi = 0; mi < 4; mi++) {
#pragma unroll
        for (int half = 0; half < 2; half++) {
            int row = wm + mi * 16 + qr + half * 8;
            int rr = row0 + row;
            if (rr < M) {
                float* Crow = jb.C + (size_t)rr * Nc;
#pragma unroll
                for (int ni = 0; ni < 4; ni++) {
                    int cc = col0 + wn + ni * 8 + qc;
                    float2 p;
                    p.x = c[mi][ni][2 * half]     + __ldg(&jb.bias[cc]);
                    p.y = c[mi][ni][2 * half + 1] + __ldg(&jb.bias[cc + 1]);
                    *(float2*)&Crow[cc] = p;
                }
            }
        }
    }
}

// ---------------- gemmB: 128x64 tile, BK=16, 256 thr, 8x4/thread, f32x2 ---
__global__ __launch_bounds__(256)
void gemmB(const float* __restrict__ A, GJobs jobs, int M, int K, int Nc) {
    const GJob jb = jobs.j[blockIdx.z];
    const float* __restrict__ B = jb.B;
    __shared__ __align__(16) float As[16][132];
    __shared__ __align__(16) float Bs[16][68];
    int tid = threadIdx.x;
    int tx = tid & 15, ty = tid >> 4;
    int row0 = blockIdx.y * 128, col0 = blockIdx.x * 64;
    u64 acc[8][2];
#pragma unroll
    for (int i = 0; i < 8; i++) { acc[i][0] = 0ull; acc[i][1] = 0ull; }

    for (int k0 = 0; k0 < K; k0 += 16) {
#pragma unroll
        for (int i = 0; i < 2; i++) {
            int idx = tid + i * 256;
            int m = idx >> 2;
            int kq = idx & 3;
            int r = row0 + m;
            float4 v = make_float4(0.f, 0.f, 0.f, 0.f);
            if (r < M) v = *(const float4*)(A + (size_t)r * K + k0 + kq * 4);
            As[kq * 4 + 0][m] = v.x;
            As[kq * 4 + 1][m] = v.y;
            As[kq * 4 + 2][m] = v.z;
            As[kq * 4 + 3][m] = v.w;
        }
        {
            int k = tid >> 4;
            int nq = tid & 15;
            *(float4*)&Bs[k][nq * 4] = *(const float4*)(B + (size_t)(k0 + k) * Nc + col0 + nq * 4);
        }
        __syncthreads();
#pragma unroll
        for (int kk = 0; kk < 16; kk++) {
            float4 a0 = *(const float4*)&As[kk][ty * 8];
            float4 a1 = *(const float4*)&As[kk][ty * 8 + 4];
            F4U b0;
            b0.f4 = *(const float4*)&Bs[kk][tx * 4];
            u64 ap[8];
            ap[0] = pk2(a0.x, a0.x); ap[1] = pk2(a0.y, a0.y);
            ap[2] = pk2(a0.z, a0.z); ap[3] = pk2(a0.w, a0.w);
            ap[4] = pk2(a1.x, a1.x); ap[5] = pk2(a1.y, a1.y);
            ap[6] = pk2(a1.z, a1.z); ap[7] = pk2(a1.w, a1.w);
            u64 bu[2] = { b0.u[0], b0.u[1] };
#pragma unroll
            for (int i = 0; i < 8; i++) {
                acc[i][0] = fma2_(ap[i], bu[0], acc[i][0]);
                acc[i][1] = fma2_(ap[i], bu[1], acc[i][1]);
            }
        }
        __syncthreads();
    }
#pragma unroll
    for (int i = 0; i < 8; i++) {
        int r = row0 + ty * 8 + i;
        if (r < M) {
            float* Crow = jb.C + (size_t)r * Nc;
#pragma unroll
            for (int j = 0; j < 2; j++) {
                int c = col0 + tx * 4 + 2 * j;
                float2 p = upk2(acc[i][j]);
                p.x += __ldg(&jb.bias[c]);
                p.y += __ldg(&jb.bias[c + 1]);
                *(float2*)&Crow[c] = p;
            }
        }
    }
}

// ---------------- GATv2 aggregation (one block per target node) -----------
struct AJob  { const float* xl; const float* xr; const float* att; const float* bias; float* out; };
struct AJobs { AJob j[2]; };

template <int C>
__global__ void gat_agg(AJobs jobs) {
    constexpr int W  = C / 32;
    constexpr int NL = C / 4;
    const AJob jb = jobs.j[blockIdx.y];
    int t = blockIdx.x;
    int tid = threadIdx.x, lane = tid & 31, warp = tid >> 5;
    __shared__ float4 s_xr4[NL], s_att4[NL];
    __shared__ float  s_e[MAXDEG];
    __shared__ int    s_src[MAXDEG];
    __shared__ float  s_red[W];
    __shared__ float4 s_part[W][NL];
    if (tid < NL) {
        s_xr4[tid]  = *(const float4*)(jb.xr + (size_t)t * C + tid * 4);
        s_att4[tid] = *(const float4*)(jb.att + tid * 4);
    }
    int beg = g_rowptr[t];
    int deg = g_rowptr[t + 1] - beg;
    __syncthreads();

    float4 xr4 = make_float4(0.f, 0.f, 0.f, 0.f);
    float4 at4 = xr4;
    if (lane < NL) { xr4 = s_xr4[lane]; at4 = s_att4[lane]; }

    // pass A: scores, two edges in flight per warp
    int j = warp;
    for (; j + W < deg; j += 2 * W) {
        int s0 = g_srclist[beg + j], s1 = g_srclist[beg + j + W];
        float p0 = 0.f, p1 = 0.f;
        if (lane < NL) {
            float4 v0 = *(const float4*)(jb.xl + (size_t)s0 * C + lane * 4);
            float4 v1 = *(const float4*)(jb.xl + (size_t)s1 * C + lane * 4);
            float a, b, cc, d;
            a = v0.x + xr4.x; a = fmaxf(a, NEG_SLOPE * a);
            b = v0.y + xr4.y; b = fmaxf(b, NEG_SLOPE * b);
            cc = v0.z + xr4.z; cc = fmaxf(cc, NEG_SLOPE * cc);
            d = v0.w + xr4.w; d = fmaxf(d, NEG_SLOPE * d);
            p0 = at4.x * a + at4.y * b + at4.z * cc + at4.w * d;
            a = v1.x + xr4.x; a = fmaxf(a, NEG_SLOPE * a);
            b = v1.y + xr4.y; b = fmaxf(b, NEG_SLOPE * b);
            cc = v1.z + xr4.z; cc = fmaxf(cc, NEG_SLOPE * cc);
            d = v1.w + xr4.w; d = fmaxf(d, NEG_SLOPE * d);
            p1 = at4.x * a + at4.y * b + at4.z * cc + at4.w * d;
        }
#pragma unroll
        for (int o = 16; o; o >>= 1) {
            p0 += __shfl_xor_sync(0xffffffffu, p0, o);
            p1 += __shfl_xor_sync(0xffffffffu, p1, o);
        }
        if (lane == 0) {
            s_e[j] = p0; s_src[j] = s0;
            s_e[j + W] = p1; s_src[j + W] = s1;
        }
    }
    if (j < deg) {
        int s0 = g_srclist[beg + j];
        float p0 = 0.f;
        if (lane < NL) {
            float4 v0 = *(const float4*)(jb.xl + (size_t)s0 * C + lane * 4);
            float a, b, cc, d;
            a = v0.x + xr4.x; a = fmaxf(a, NEG_SLOPE * a);
            b = v0.y + xr4.y; b = fmaxf(b, NEG_SLOPE * b);
            cc = v0.z + xr4.z; cc = fmaxf(cc, NEG_SLOPE * cc);
            d = v0.w + xr4.w; d = fmaxf(d, NEG_SLOPE * d);
            p0 = at4.x * a + at4.y * b + at4.z * cc + at4.w * d;
        }
#pragma unroll
        for (int o = 16; o; o >>= 1) p0 += __shfl_xor_sync(0xffffffffu, p0, o);
        if (lane == 0) { s_e[j] = p0; s_src[j] = s0; }
    }
    __syncthreads();

    float m = -1e30f;
    for (int q = tid; q < deg; q += C) m = fmaxf(m, s_e[q]);
#pragma unroll
    for (int o = 16; o; o >>= 1) m = fmaxf(m, __shfl_xor_sync(0xffffffffu, m, o));
    if (lane == 0) s_red[warp] = m;
    __syncthreads();
    m = s_red[0];
#pragma unroll
    for (int w = 1; w < W; w++) m = fmaxf(m, s_red[w]);
    __syncthreads();

    float ssum = 0.f;
    for (int q = tid; q < deg; q += C) {
        float wj = __expf(s_e[q] - m);
        s_e[q] = wj;
        ssum += wj;
    }
#pragma unroll
    for (int o = 16; o; o >>= 1) ssum += __shfl_xor_sync(0xffffffffu, ssum, o);
    if (lane == 0) s_red[warp] = ssum;
    __syncthreads();
    ssum = 0.f;
#pragma unroll
    for (int w = 0; w < W; w++) ssum += s_red[w];
    float inv = 1.f / ssum;

    // pass B: weighted aggregation, two edges in flight
    float4 f0 = make_float4(0.f, 0.f, 0.f, 0.f);
    float4 f1 = f0;
    if (lane < NL) {
        int q = warp;
        for (; q + W < deg; q += 2 * W) {
            float w0 = s_e[q], w1 = s_e[q + W];
            float4 v0 = *(const float4*)(jb.xl + (size_t)s_src[q] * C + lane * 4);
            float4 v1 = *(const float4*)(jb.xl + (size_t)s_src[q + W] * C + lane * 4);
            f0.x += w0 * v0.x; f0.y += w0 * v0.y; f0.z += w0 * v0.z; f0.w += w0 * v0.w;
            f1.x += w1 * v1.x; f1.y += w1 * v1.y; f1.z += w1 * v1.z; f1.w += w1 * v1.w;
        }
        if (q < deg) {
            float w0 = s_e[q];
            float4 v0 = *(const float4*)(jb.xl + (size_t)s_src[q] * C + lane * 4);
            f0.x += w0 * v0.x; f0.y += w0 * v0.y; f0.z += w0 * v0.z; f0.w += w0 * v0.w;
        }
        f0.x += f1.x; f0.y += f1.y; f0.z += f1.z; f0.w += f1.w;
        s_part[warp][lane] = f0;
    }
    __syncthreads();
    if (warp == 0 && lane < NL) {
        float4 tt = s_part[0][lane];
#pragma unroll
        for (int w = 1; w < W; w++) {
            float4 q4 = s_part[w][lane];
            tt.x += q4.x; tt.y += q4.y; tt.z += q4.z; tt.w += q4.w;
        }
        float4 b4 = *(const float4*)(jb.bias + lane * 4);
        float4 o4;
        o4.x = tt.x * inv + b4.x;
        o4.y = tt.y * inv + b4.y;
        o4.z = tt.z * inv + b4.z;
        o4.w = tt.w * inv + b4.w;
        *(float4*)(jb.out + (size_t)t * C + lane * 4) = o4;
    }
}

// ---------------- batch norm ----------------
template <int C>
__global__ void bn_stats(const float* __restrict__ h) {
    int c = blockIdx.x;
    int tid = threadIdx.x;
    float s = 0.f, s2 = 0.f;
    for (int r = tid; r < NN; r += 256) {
        float v = h[(size_t)r * C + c];
        s += v; s2 += v * v;
    }
    __shared__ float sh[8], sh2[8];
#pragma unroll
    for (int o = 16; o; o >>= 1) {
        s  += __shfl_xor_sync(0xffffffffu, s,  o);
        s2 += __shfl_xor_sync(0xffffffffu, s2, o);
    }
    if ((tid & 31) == 0) { sh[tid >> 5] = s; sh2[tid >> 5] = s2; }
    __syncthreads();
    if (tid == 0) {
        float ts = 0.f, ts2 = 0.f;
        for (int w = 0; w < 8; w++) { ts += sh[w]; ts2 += sh2[w]; }
        float mean = ts / NN;
        float var = ts2 / NN - mean * mean;
        g_mean[c] = mean;
        g_rstd[c] = rsqrtf(var + BN_EPS);
    }
}

template <int C>
__global__ void bn_apply_relu(float* __restrict__ buf, const float* __restrict__ g,
                              const float* __restrict__ b) {
    int i = blockIdx.x * blockDim.x + threadIdx.x;
    if (i >= NN * C) return;
    int c = i & (C - 1);
    float v = (buf[i] - g_mean[c]) * g_rstd[c] * g[c] + b[c];
    buf[i] = fmaxf(v, 0.f);
}

// ---------------- reparameterize ----------------
__global__ void k_reparam(const float* __restrict__ eps, float* __restrict__ out) {
    int i = blockIdx.x * blockDim.x + threadIdx.x;
    if (i >= NN * NHID2) return;
    float mu = out[MU_OFF + i];
    float lv = out[LV_OFF + i];
    out[EMB_OFF + i] = eps[i] * __expf(lv) + mu;
}

// ---------------- readj = sigmoid(emb @ emb^T) via bf16 HMMA split --------
#define GP 72
#define G_AHI 0
#define G_ALO (G_AHI + 128 * GP * 2)
#define G_BHI (G_ALO + 128 * GP * 2)
#define G_BLO (G_BHI + 128 * GP * 2)
#define G_SMEM (G_BLO + 128 * GP * 2)    // 73728

__global__ __launch_bounds__(256)
void gram_hmma(const float* __restrict__ E, float* __restrict__ out) {
    int by = blockIdx.y, bx = blockIdx.x;
    if (bx < by) return;
    extern __shared__ __align__(16) char smem[];
    uint32_t sb = smem_u32(smem);
    int tid = threadIdx.x, lane = tid & 31, warp = tid >> 5;
    int row0 = by * 128, col0 = bx * 128;

    {
        int rrow = tid >> 1;
        int ks = (tid & 1) * 32;
        int rA = row0 + rrow, rB = col0 + rrow;
        const float4* pa = (const float4*)(E + (size_t)rA * 64 + ks);
        const float4* pb = (const float4*)(E + (size_t)rB * 64 + ks);
        bool va = rA < NN, vb = rB < NN;
        uint32_t base = (rrow * GP + ks) * 2;
#pragma unroll
        for (int q = 0; q < 8; q++) {
            float4 a = va ? pa[q] : make_float4(0.f, 0.f, 0.f, 0.f);
            float4 b = vb ? pb[q] : make_float4(0.f, 0.f, 0.f, 0.f);
            float av[4] = { a.x, a.y, a.z, a.w };
            float bv[4] = { b.x, b.y, b.z, b.w };
#pragma unroll
            for (int h = 0; h < 2; h++) {
                uint16_t h0, l0, h1, l1;
                bf16split(av[2 * h], h0, l0);
                bf16split(av[2 * h + 1], h1, l1);
                uint32_t ah = (uint32_t)h0 | ((uint32_t)h1 << 16);
                uint32_t al = (uint32_t)l0 | ((uint32_t)l1 << 16);
                bf16split(bv[2 * h], h0, l0);
                bf16split(bv[2 * h + 1], h1, l1);
                uint32_t bh = (uint32_t)h0 | ((uint32_t)h1 << 16);
                uint32_t bl = (uint32_t)l0 | ((uint32_t)l1 << 16);
                uint32_t off = base + (q * 4 + h * 2) * 2;
                *(uint32_t*)(smem + G_AHI + off) = ah;
                *(uint32_t*)(smem + G_ALO + off) = al;
                *(uint32_t*)(smem + G_BHI + off) = bh;
                *(uint32_t*)(smem + G_BLO + off) = bl;
            }
        }
    }
    __syncthreads();

    int wm = (warp & 1) * 64;
    int wn = (warp >> 1) * 32;
    float c[4][4][4];
#pragma unroll
    for (int mi = 0; mi < 4; mi++)
#pragma unroll
        for (int ni = 0; ni < 4; ni++)
#pragma unroll
            for (int e = 0; e < 4; e++) c[mi][ni][e] = 0.f;

    int grp = lane >> 3, rl = lane & 7;
#pragma unroll
    for (int pass = 0; pass < 3; pass++) {
        uint32_t aBase = sb + ((pass == 2) ? G_ALO : G_AHI);
        uint32_t bBase = sb + ((pass == 1) ? G_BLO : G_BHI);
#pragma unroll
        for (int k0 = 0; k0 < 64; k0 += 16) {
            uint32_t af[4][4], bf[4][2];
#pragma unroll
            for (int mi = 0; mi < 4; mi++) {
                int arow = wm + mi * 16 + (grp & 1) * 8 + rl;
                int acol = k0 + (grp >> 1) * 8;
                ldsm_x4(af[mi][0], af[mi][1], af[mi][2], af[mi][3],
                        aBase + (arow * GP + acol) * 2);
            }
#pragma unroll
            for (int ni = 0; ni < 4; ni++) {
                int brow = wn + ni * 8 + rl;
                int bcol = k0 + (grp & 1) * 8;
                ldsm_x2(bf[ni][0], bf[ni][1], bBase + (brow * GP + bcol) * 2);
            }
#pragma unroll
            for (int mi = 0; mi < 4; mi++)
#pragma unroll
                for (int ni = 0; ni < 4; ni++)
                    mma_bf16(c[mi][ni], af[mi][0], af[mi][1], af[mi][2], af[mi][3],
                             bf[ni][0], bf[ni][1]);
        }
    }
    __syncthreads();

    float* stag = (float*)smem;
    bool diag = (bx == by);
    int qr = lane >> 2, qc = 2 * (lane & 3);
#pragma unroll
    for (int mi = 0; mi < 4; mi++) {
#pragma unroll
        for (int ni = 0; ni < 4; ni++) {
#pragma unroll
            for (int half = 0; half < 2; half++) {
                int row = wm + mi * 16 + qr + half * 8;
                int col = wn + ni * 8 + qc;
                float v0 = 1.f / (1.f + __expf(-c[mi][ni][2 * half]));
                float v1 = 1.f / (1.f + __expf(-c[mi][ni][2 * half + 1]));
                int r = row0 + row, cc = col0 + col;
                if (r < NN && cc < NN)
                    *(float2*)(out + (size_t)r * NN + cc) = make_float2(v0, v1);
                if (!diag) {
                    int s = row & 31;
                    stag[row * 128 + (col ^ s)] = v0;
                    stag[row * 128 + ((col + 1) ^ s)] = v1;
                }
            }
        }
    }
    if (diag) return;
    __syncthreads();

    {
        int mr = tid >> 1;
        int half = tid & 1;
        int cgl = col0 + mr;
        if (cgl < NN) {
            float* mrow = out + (size_t)cgl * NN + row0 + half * 64;
            int ibase = half * 64;
#pragma unroll
            for (int i = 0; i < 64; i += 4) {
                int i0 = ibase + i;
                if (row0 + i0 < NN) {
                    float4 w;
                    w.x = stag[(i0 + 0) * 128 + (mr ^ ((i0 + 0) & 31))];
                    w.y = stag[(i0 + 1) * 128 + (mr ^ ((i0 + 1) & 31))];
                    w.z = stag[(i0 + 2) * 128 + (mr ^ ((i0 + 2) & 31))];
                    w.w = stag[(i0 + 3) * 128 + (mr ^ ((i0 + 3) & 31))];
                    *(float4*)mrow = w;
                }
                mrow += 4;
            }
        }
    }
}

// ---------------- launch ----------------
extern "C" void kernel_launch(void* const* d_in, const int* in_sizes, int n_in,
                              void* d_out, int out_size) {
    const float* x   = (const float*)d_in[0];
    const int*   ei  = (const int*)  d_in[1];
    const float* eps = (const float*)d_in[2];
    const float* w1l = (const float*)d_in[3];
    const float* b1l = (const float*)d_in[4];
    const float* w1r = (const float*)d_in[5];
    const float* b1r = (const float*)d_in[6];
    const float* a1  = (const float*)d_in[7];
    const float* bias1 = (const float*)d_in[8];
    const float* bn1_g = (const float*)d_in[9];
    const float* bn1_b = (const float*)d_in[10];
    const float* w2l = (const float*)d_in[11];
    const float* b2l = (const float*)d_in[12];
    const float* w2r = (const float*)d_in[13];
    const float* b2r = (const float*)d_in[14];
    const float* a2  = (const float*)d_in[15];
    const float* bias2 = (const float*)d_in[16];
    const float* w3l = (const float*)d_in[17];
    const float* b3l = (const float*)d_in[18];
    const float* w3r = (const float*)d_in[19];
    const float* b3r = (const float*)d_in[20];
    const float* a3  = (const float*)d_in[21];
    const float* bias3 = (const float*)d_in[22];
    const float* dw1 = (const float*)d_in[23];
    const float* db1 = (const float*)d_in[24];
    const float* dbn_g = (const float*)d_in[25];
    const float* dbn_b = (const float*)d_in[26];
    const float* dw2 = (const float*)d_in[27];
    const float* db2 = (const float*)d_in[28];
    float* out = (float*)d_out;

    float *p_xl1, *p_xr1, *p_h, *p_xl2, *p_xr2, *p_xl3, *p_xr3, *p_d;
    cudaGetSymbolAddress((void**)&p_xl1, g_xl1);
    cudaGetSymbolAddress((void**)&p_xr1, g_xr1);
    cudaGetSymbolAddress((void**)&p_h,   g_h);
    cudaGetSymbolAddress((void**)&p_xl2, g_xl2);
    cudaGetSymbolAddress((void**)&p_xr2, g_xr2);
    cudaGetSymbolAddress((void**)&p_xl3, g_xl3);
    cudaGetSymbolAddress((void**)&p_xr3, g_xr3);
    cudaGetSymbolAddress((void**)&p_d,   g_d);
    uint16_t *p_w1lh, *p_w1ll, *p_w1rh, *p_w1rl, *p_dw2h, *p_dw2l;
    cudaGetSymbolAddress((void**)&p_w1lh, g_w1lh);
    cudaGetSymbolAddress((void**)&p_w1ll, g_w1ll);
    cudaGetSymbolAddress((void**)&p_w1rh, g_w1rh);
    cudaGetSymbolAddress((void**)&p_w1rl, g_w1rl);
    cudaGetSymbolAddress((void**)&p_dw2h, g_dw2h);
    cudaGetSymbolAddress((void**)&p_dw2l, g_dw2l);

    cudaFuncSetAttribute(gram_hmma, cudaFuncAttributeMaxDynamicSharedMemorySize, G_SMEM);

    const int MT = (NN + 127) / 128;   // 79

    // ---- weight transpose + split (tiny) ----
    k_wsplit<<<(NFEAT * H1 + 255) / 256, 256>>>(w1l, p_w1lh, p_w1ll, NFEAT, H1);
    k_wsplit<<<(NFEAT * H1 + 255) / 256, 256>>>(w1r, p_w1rh, p_w1rl, NFEAT, H1);
    k_wsplit<<<(NHID1 * NFEAT + 255) / 256, 256>>>(dw2, p_dw2h, p_dw2l, NHID1, NFEAT);

    // ---- CSR build ----
    k_zero_counts<<<(NN + 255) / 256, 256>>>();
    k_count_deg<<<(NE + 255) / 256, 256>>>(ei);
    k_scan_deg<<<1, 1024>>>();
    k_fill_list<<<(NE + 255) / 256, 256>>>(ei);

    // ---- layer 1 linear transforms (HMMA) ----
    {
        TJobs j1 = {{ { p_w1lh, p_w1ll, b1l, p_xl1 }, { p_w1rh, p_w1rl, b1r, p_xr1 } }};
        gemmT<<<dim3(H1 / 128, MT, 2), 256>>>(x, j1, NN, NFEAT, H1);
    }

    // ---- GAT layer 1 -> BN -> ReLU ----
    {
        AJobs aj = {{ { p_xl1, p_xr1, a1, bias1, p_h }, {} }};
        gat_agg<H1><<<dim3(NN, 1), H1>>>(aj);
    }
    bn_stats<H1><<<H1, 256>>>(p_h);
    bn_apply_relu<H1><<<(NN * H1 + 255) / 256, 256>>>(p_h, bn1_g, bn1_b);

    // ---- layers 2 & 3 linear transforms ----
    {
        GJobs j2 = {{ { w2l, b2l, p_xl2 }, { w2r, b2r, p_xr2 },
                      { w3l, b3l, p_xl3 }, { w3r, b3r, p_xr3 } }};
        gemmB<<<dim3(NHID2 / 64, MT, 4), 256>>>(p_h, j2, NN, H1, NHID2);
    }

    // ---- GAT layers 2 (mu) and 3 (logvar) ----
    {
        AJobs aj = {{ { p_xl2, p_xr2, a2, bias2, out + MU_OFF },
                      { p_xl3, p_xr3, a3, bias3, out + LV_OFF } }};
        gat_agg<NHID2><<<dim3(NN, 2), NHID2>>>(aj);
    }

    // ---- reparameterize ----
    k_reparam<<<(NN * NHID2 + 255) / 256, 256>>>(eps, out);

    // ---- readj = sigmoid(emb @ emb^T) on tensor cores (HMMA) ----
    gram_hmma<<<dim3(MT, MT), 256, G_SMEM>>>(out + EMB_OFF, out + READJ_OFF);

    // ---- decoder MLP ----
    {
        GJobs jd = {{ { dw1, db1, p_d }, {}, {}, {} }};
        gemmB<<<dim3(NHID1 / 64, MT, 1), 256>>>(out + EMB_OFF, jd, NN, NHID2, NHID1);
    }
    bn_stats<NHID1><<<NHID1, 256>>>(p_d);
    bn_apply_relu<NHID1><<<(NN * NHID1 + 255) / 256, 256>>>(p_d, dbn_g, dbn_b);
    {
        TJobs jd = {{ { p_dw2h, p_dw2l, db2, out + REX_OFF }, {} }};
        gemmT<<<dim3(NFEAT / 128, MT, 1), 256>>>(p_d, jd, NN, NHID1, NFEAT);
    }
}

// round 8
// speedup vs baseline: 1.4899x; 1.0011x over previous
#include <cuda_runtime.h>
#include <cuda_bf16.h>
#include <cstdint>
#include <math.h>

#define NN     10000
#define EE     320000
#define NE     (EE + NN)     // with self loops
#define NFEAT  512
#define NHID1  256
#define NHID2  64
#define H1     128           // 2*nhid2
#define NEG_SLOPE 0.2f
#define BN_EPS 1e-5f
#define MAXDEG 512

// output layout (flattened tuple: emb, re_x, readj, mu, logvar)
#define EMB_OFF   ((size_t)0)
#define REX_OFF   ((size_t)NN * NHID2)
#define READJ_OFF (REX_OFF + (size_t)NN * NFEAT)
#define MU_OFF    (READJ_OFF + (size_t)NN * NN)
#define LV_OFF    (MU_OFF + (size_t)NN * NHID2)

typedef unsigned long long u64;

// ---------------- warp MMA helpers (baseline PTX, works on sm_103) --------
__device__ __forceinline__ uint32_t smem_u32(const void* p) {
    uint32_t a;
    asm("{ .reg .u64 t; cvta.to.shared.u64 t, %1; cvt.u32.u64 %0, t; }" : "=r"(a) : "l"(p));
    return a;
}
__device__ __forceinline__ void ldsm_x4(uint32_t& r0, uint32_t& r1, uint32_t& r2, uint32_t& r3, uint32_t addr) {
    asm volatile("ldmatrix.sync.aligned.m8n8.x4.shared.b16 {%0,%1,%2,%3}, [%4];"
                 : "=r"(r0), "=r"(r1), "=r"(r2), "=r"(r3) : "r"(addr));
}
__device__ __forceinline__ void ldsm_x2(uint32_t& r0, uint32_t& r1, uint32_t addr) {
    asm volatile("ldmatrix.sync.aligned.m8n8.x2.shared.b16 {%0,%1}, [%2];"
                 : "=r"(r0), "=r"(r1) : "r"(addr));
}
__device__ __forceinline__ void mma_bf16(float* d, uint32_t a0, uint32_t a1, uint32_t a2, uint32_t a3,
                                         uint32_t b0, uint32_t b1) {
    asm volatile("mma.sync.aligned.m16n8k16.row.col.f32.bf16.bf16.f32 "
                 "{%0,%1,%2,%3}, {%4,%5,%6,%7}, {%8,%9}, {%0,%1,%2,%3};"
                 : "+f"(d[0]), "+f"(d[1]), "+f"(d[2]), "+f"(d[3])
                 : "r"(a0), "r"(a1), "r"(a2), "r"(a3), "r"(b0), "r"(b1));
}
__device__ __forceinline__ void bf16split(float v, uint16_t& h, uint16_t& l) {
    __nv_bfloat16 hb = __float2bfloat16_rn(v);
    __nv_bfloat16 lb = __float2bfloat16_rn(v - __bfloat162float(hb));
    h = __bfloat16_as_ushort(hb);
    l = __bfloat16_as_ushort(lb);
}

// ---------------- scratch (device globals; no allocation allowed) ----------
__device__ float g_xl1[NN * H1];
__device__ float g_xr1[NN * H1];
__device__ float g_h  [NN * H1];
__device__ float g_x23[NN * 256];        // packed: xl2|xr2|xl3|xr3 (64 each)
__device__ float g_d  [NN * NHID1];
__device__ int   g_deg[NN];
__device__ int   g_rowptr[NN + 1];
__device__ int   g_cursor[NN];
__device__ int   g_srclist[NE];
__device__ float g_mean[NHID1];
__device__ float g_rstd[NHID1];
__device__ float g_bias23[256];
// transposed bf16 hi/lo weights [Nc][K]
__device__ uint16_t g_w1lh[H1 * NFEAT],  g_w1ll[H1 * NFEAT];
__device__ uint16_t g_w1rh[H1 * NFEAT],  g_w1rl[H1 * NFEAT];
__device__ uint16_t g_w23h[256 * H1],    g_w23l[256 * H1];
__device__ uint16_t g_dw1h[NHID1 * NHID2], g_dw1l[NHID1 * NHID2];
__device__ uint16_t g_dw2h[NFEAT * NHID1], g_dw2l[NFEAT * NHID1];

// ---------------- CSR build ----------------
__global__ void k_zero_counts() {
    int i = blockIdx.x * blockDim.x + threadIdx.x;
    if (i < NN) { g_deg[i] = 0; g_cursor[i] = 0; }
}

__global__ void k_count_deg(const int* __restrict__ edge_index) {
    int i = blockIdx.x * blockDim.x + threadIdx.x;
    if (i >= NE) return;
    int tgt = (i < EE) ? edge_index[EE + i] : (i - EE);
    atomicAdd(&g_deg[tgt], 1);
}

__global__ void k_scan_deg() {
    __shared__ int wsum[32];
    __shared__ int sc;
    int tid = threadIdx.x, lane = tid & 31, w = tid >> 5;
    if (tid == 0) { sc = 0; g_rowptr[0] = 0; }
    __syncthreads();
    for (int base = 0; base < NN; base += 1024) {
        int i = base + tid;
        int v = (i < NN) ? g_deg[i] : 0;
        int x = v;
#pragma unroll
        for (int o = 1; o < 32; o <<= 1) {
            int t = __shfl_up_sync(0xffffffffu, x, o);
            if (lane >= o) x += t;
        }
        if (lane == 31) wsum[w] = x;
        __syncthreads();
        if (w == 0) {
            int y = wsum[lane];
#pragma unroll
            for (int o = 1; o < 32; o <<= 1) {
                int t = __shfl_up_sync(0xffffffffu, y, o);
                if (lane >= o) y += t;
            }
            wsum[lane] = y;
        }
        __syncthreads();
        int pre = (w > 0) ? wsum[w - 1] : 0;
        int c = sc;
        if (i < NN) g_rowptr[i + 1] = c + pre + x;
        int total = wsum[31];
        __syncthreads();
        if (tid == 0) sc = c + total;
        __syncthreads();
    }
}

__global__ void k_fill_list(const int* __restrict__ edge_index) {
    int i = blockIdx.x * blockDim.x + threadIdx.x;
    if (i >= NE) return;
    int src, tgt;
    if (i < EE) { src = edge_index[i]; tgt = edge_index[EE + i]; }
    else        { src = i - EE;        tgt = i - EE; }
    int pos = atomicAdd(&g_cursor[tgt], 1);
    g_srclist[g_rowptr[tgt] + pos] = src;
}

// ---------------- weight transpose + bf16 split ----------------
// W[K][Nc] -> Wt[Nc][K] hi/lo
__global__ void k_wsplit(const float* __restrict__ W, uint16_t* __restrict__ hi,
                         uint16_t* __restrict__ lo, int K, int Nc) {
    int i = blockIdx.x * blockDim.x + threadIdx.x;
    if (i >= K * Nc) return;
    int n = i / K, k = i - n * K;
    uint16_t h, l;
    bf16split(W[(size_t)k * Nc + n], h, l);
    hi[i] = h; lo[i] = l;
}
// pack 4 [K=128][64] weights into [256][128] transposed hi/lo
__global__ void k_wsplit4(const float* __restrict__ W0, const float* __restrict__ W1,
                          const float* __restrict__ W2, const float* __restrict__ W3,
                          uint16_t* __restrict__ hi, uint16_t* __restrict__ lo) {
    int i = blockIdx.x * blockDim.x + threadIdx.x;
    if (i >= 256 * H1) return;
    int np = i >> 7, k = i & 127;
    int jj = np >> 6, n = np & 63;
    const float* W = (jj == 0) ? W0 : (jj == 1) ? W1 : (jj == 2) ? W2 : W3;
    uint16_t h, l;
    bf16split(W[(size_t)k * 64 + n], h, l);
    hi[i] = h; lo[i] = l;
}

// ---------------- gemmT: HMMA bf16 split GEMM, 128x128 tile --------------
// A fp32 [M,K] (converted per tile, optional fused BN+ReLU on A channels),
// B pre-split bf16 [Nc][K]. 256 thr = 8 warps. K%32==0, Nc%128==0.
struct TJob  { const uint16_t* Bh; const uint16_t* Bl; const float* bias; float* C; };
struct TJobs { TJob j[2]; };

__global__ __launch_bounds__(256)
void gemmT(const float* __restrict__ A, TJobs jobs, int M, int K, int Nc,
           const float* __restrict__ bnG, const float* __restrict__ bnB) {
    const TJob jb = jobs.j[blockIdx.z];
    __shared__ __align__(16) uint16_t Ah[128][40], Al[128][40];
    __shared__ __align__(16) uint16_t Bh[128][40], Bl[128][40];
    int tid = threadIdx.x, lane = tid & 31, warp = tid >> 5;
    int row0 = blockIdx.y * 128, col0 = blockIdx.x * 128;
    int wm = (warp & 1) * 64, wn = (warp >> 1) * 32;
    int grp = lane >> 3, rl = lane & 7;
    float c[4][4][4];
#pragma unroll
    for (int mi = 0; mi < 4; mi++)
#pragma unroll
        for (int ni = 0; ni < 4; ni++)
#pragma unroll
            for (int e = 0; e < 4; e++) c[mi][ni][e] = 0.f;

    int ar = tid >> 1, kh = (tid & 1) * 16;
    int r = row0 + ar;
    bool va = r < M;

    for (int k0 = 0; k0 < K; k0 += 32) {
        const float* pa = A + (size_t)r * K + k0 + kh;
#pragma unroll
        for (int q = 0; q < 4; q++) {
            float4 v = va ? *(const float4*)(pa + q * 4) : make_float4(0.f, 0.f, 0.f, 0.f);
            if (bnG) {
                int ch = k0 + kh + q * 4;
                float4 mm = *(const float4*)(g_mean + ch);
                float4 rs = *(const float4*)(g_rstd + ch);
                float4 gg = *(const float4*)(bnG + ch);
                float4 bb = *(const float4*)(bnB + ch);
                v.x = fmaxf((v.x - mm.x) * rs.x * gg.x + bb.x, 0.f);
                v.y = fmaxf((v.y - mm.y) * rs.y * gg.y + bb.y, 0.f);
                v.z = fmaxf((v.z - mm.z) * rs.z * gg.z + bb.z, 0.f);
                v.w = fmaxf((v.w - mm.w) * rs.w * gg.w + bb.w, 0.f);
            }
            uint16_t h0, l0, h1, l1, h2, l2, h3, l3;
            bf16split(v.x, h0, l0); bf16split(v.y, h1, l1);
            bf16split(v.z, h2, l2); bf16split(v.w, h3, l3);
            *(uint32_t*)&Ah[ar][kh + q * 4]     = (uint32_t)h0 | ((uint32_t)h1 << 16);
            *(uint32_t*)&Ah[ar][kh + q * 4 + 2] = (uint32_t)h2 | ((uint32_t)h3 << 16);
            *(uint32_t*)&Al[ar][kh + q * 4]     = (uint32_t)l0 | ((uint32_t)l1 << 16);
            *(uint32_t*)&Al[ar][kh + q * 4 + 2] = (uint32_t)l2 | ((uint32_t)l3 << 16);
        }
        {
            const uint16_t* pbh = jb.Bh + (size_t)(col0 + ar) * K + k0 + kh;
            const uint16_t* pbl = jb.Bl + (size_t)(col0 + ar) * K + k0 + kh;
            *(uint4*)&Bh[ar][kh]     = *(const uint4*)pbh;
            *(uint4*)&Bh[ar][kh + 8] = *(const uint4*)(pbh + 8);
            *(uint4*)&Bl[ar][kh]     = *(const uint4*)pbl;
            *(uint4*)&Bl[ar][kh + 8] = *(const uint4*)(pbl + 8);
        }
        __syncthreads();
#pragma unroll
        for (int pass = 0; pass < 3; pass++) {
            const uint16_t (*Aq)[40] = (pass == 2) ? Al : Ah;
            const uint16_t (*Bq)[40] = (pass == 1) ? Bl : Bh;
#pragma unroll
            for (int k1 = 0; k1 < 32; k1 += 16) {
                uint32_t af[4][4], bf[4][2];
#pragma unroll
                for (int mi = 0; mi < 4; mi++) {
                    int arow = wm + mi * 16 + (grp & 1) * 8 + rl;
                    int acol = k1 + (grp >> 1) * 8;
                    ldsm_x4(af[mi][0], af[mi][1], af[mi][2], af[mi][3],
                            smem_u32(&Aq[arow][acol]));
                }
#pragma unroll
                for (int ni = 0; ni < 4; ni++) {
                    int brow = wn + ni * 8 + rl;
                    int bcol = k1 + (grp & 1) * 8;
                    ldsm_x2(bf[ni][0], bf[ni][1], smem_u32(&Bq[brow][bcol]));
                }
#pragma unroll
                for (int mi = 0; mi < 4; mi++)
#pragma unroll
                    for (int ni = 0; ni < 4; ni++)
                        mma_bf16(c[mi][ni], af[mi][0], af[mi][1], af[mi][2], af[mi][3],
                                 bf[ni][0], bf[ni][1]);
            }
        }
        __syncthreads();
    }
    int qr = lane >> 2, qc = 2 * (lane & 3);
#pragma unroll
    for (int mi = 0; mi < 4; mi++) {
#pragma unroll
        for (int half = 0; half < 2; half++) {
            int row = wm + mi * 16 + qr + half * 8;
            int rr = row0 + row;
            if (rr < M) {
                float* Crow = jb.C + (size_t)rr * Nc;
#pragma unroll
                for (int ni = 0; ni < 4; ni++) {
                    int cc = col0 + wn + ni * 8 + qc;
                    float2 p;
                    p.x = c[mi][ni][2 * half]     + __ldg(&jb.bias[cc]);
                    p.y = c[mi][ni][2 * half + 1] + __ldg(&jb.bias[cc + 1]);
                    *(float2*)&Crow[cc] = p;
                }
            }
        }
    }
}

// ---------------- GATv2 aggregation (one block per target node) -----------
struct AJob  { const float* xl; const float* xr; int ld; const float* att;
               const float* bias; float* out; int ldo; };
struct AJobs { AJob j[2]; };

template <int C>
__global__ void gat_agg(AJobs jobs) {
    constexpr int W  = C / 32;
    constexpr int NL = C / 4;
    const AJob jb = jobs.j[blockIdx.y];
    int t = blockIdx.x;
    int tid = threadIdx.x, lane = tid & 31, warp = tid >> 5;
    __shared__ float4 s_xr4[NL], s_att4[NL];
    __shared__ float  s_e[MAXDEG];
    __shared__ int    s_src[MAXDEG];
    __shared__ float  s_red[W];
    __shared__ float4 s_part[W][NL];
    if (tid < NL) {
        s_xr4[tid]  = *(const float4*)(jb.xr + (size_t)t * jb.ld + tid * 4);
        s_att4[tid] = *(const float4*)(jb.att + tid * 4);
    }
    int beg = g_rowptr[t];
    int deg = g_rowptr[t + 1] - beg;
    __syncthreads();

    float4 xr4 = make_float4(0.f, 0.f, 0.f, 0.f);
    float4 at4 = xr4;
    if (lane < NL) { xr4 = s_xr4[lane]; at4 = s_att4[lane]; }
    const float* xl = jb.xl;
    int ld = jb.ld;

    // pass A: scores, two edges in flight per warp
    int j = warp;
    for (; j + W < deg; j += 2 * W) {
        int s0 = g_srclist[beg + j], s1 = g_srclist[beg + j + W];
        float p0 = 0.f, p1 = 0.f;
        if (lane < NL) {
            float4 v0 = *(const float4*)(xl + (size_t)s0 * ld + lane * 4);
            float4 v1 = *(const float4*)(xl + (size_t)s1 * ld + lane * 4);
            float a, b, cc, d;
            a = v0.x + xr4.x; a = fmaxf(a, NEG_SLOPE * a);
            b = v0.y + xr4.y; b = fmaxf(b, NEG_SLOPE * b);
            cc = v0.z + xr4.z; cc = fmaxf(cc, NEG_SLOPE * cc);
            d = v0.w + xr4.w; d = fmaxf(d, NEG_SLOPE * d);
            p0 = at4.x * a + at4.y * b + at4.z * cc + at4.w * d;
            a = v1.x + xr4.x; a = fmaxf(a, NEG_SLOPE * a);
            b = v1.y + xr4.y; b = fmaxf(b, NEG_SLOPE * b);
            cc = v1.z + xr4.z; cc = fmaxf(cc, NEG_SLOPE * cc);
            d = v1.w + xr4.w; d = fmaxf(d, NEG_SLOPE * d);
            p1 = at4.x * a + at4.y * b + at4.z * cc + at4.w * d;
        }
#pragma unroll
        for (int o = 16; o; o >>= 1) {
            p0 += __shfl_xor_sync(0xffffffffu, p0, o);
            p1 += __shfl_xor_sync(0xffffffffu, p1, o);
        }
        if (lane == 0) {
            s_e[j] = p0; s_src[j] = s0;
            s_e[j + W] = p1; s_src[j + W] = s1;
        }
    }
    if (j < deg) {
        int s0 = g_srclist[beg + j];
        float p0 = 0.f;
        if (lane < NL) {
            float4 v0 = *(const float4*)(xl + (size_t)s0 * ld + lane * 4);
            float a, b, cc, d;
            a = v0.x + xr4.x; a = fmaxf(a, NEG_SLOPE * a);
            b = v0.y + xr4.y; b = fmaxf(b, NEG_SLOPE * b);
            cc = v0.z + xr4.z; cc = fmaxf(cc, NEG_SLOPE * cc);
            d = v0.w + xr4.w; d = fmaxf(d, NEG_SLOPE * d);
            p0 = at4.x * a + at4.y * b + at4.z * cc + at4.w * d;
        }
#pragma unroll
        for (int o = 16; o; o >>= 1) p0 += __shfl_xor_sync(0xffffffffu, p0, o);
        if (lane == 0) { s_e[j] = p0; s_src[j] = s0; }
    }
    __syncthreads();

    float m = -1e30f;
    for (int q = tid; q < deg; q += C) m = fmaxf(m, s_e[q]);
#pragma unroll
    for (int o = 16; o; o >>= 1) m = fmaxf(m, __shfl_xor_sync(0xffffffffu, m, o));
    if (lane == 0) s_red[warp] = m;
    __syncthreads();
    m = s_red[0];
#pragma unroll
    for (int w = 1; w < W; w++) m = fmaxf(m, s_red[w]);
    __syncthreads();

    float ssum = 0.f;
    for (int q = tid; q < deg; q += C) {
        float wj = __expf(s_e[q] - m);
        s_e[q] = wj;
        ssum += wj;
    }
#pragma unroll
    for (int o = 16; o; o >>= 1) ssum += __shfl_xor_sync(0xffffffffu, ssum, o);
    if (lane == 0) s_red[warp] = ssum;
    __syncthreads();
    ssum = 0.f;
#pragma unroll
    for (int w = 0; w < W; w++) ssum += s_red[w];
    float inv = 1.f / ssum;

    float4 f0 = make_float4(0.f, 0.f, 0.f, 0.f);
    float4 f1 = f0;
    if (lane < NL) {
        int q = warp;
        for (; q + W < deg; q += 2 * W) {
            float w0 = s_e[q], w1 = s_e[q + W];
            float4 v0 = *(const float4*)(xl + (size_t)s_src[q] * ld + lane * 4);
            float4 v1 = *(const float4*)(xl + (size_t)s_src[q + W] * ld + lane * 4);
            f0.x += w0 * v0.x; f0.y += w0 * v0.y; f0.z += w0 * v0.z; f0.w += w0 * v0.w;
            f1.x += w1 * v1.x; f1.y += w1 * v1.y; f1.z += w1 * v1.z; f1.w += w1 * v1.w;
        }
        if (q < deg) {
            float w0 = s_e[q];
            float4 v0 = *(const float4*)(xl + (size_t)s_src[q] * ld + lane * 4);
            f0.x += w0 * v0.x; f0.y += w0 * v0.y; f0.z += w0 * v0.z; f0.w += w0 * v0.w;
        }
        f0.x += f1.x; f0.y += f1.y; f0.z += f1.z; f0.w += f1.w;
        s_part[warp][lane] = f0;
    }
    __syncthreads();
    if (warp == 0 && lane < NL) {
        float4 tt = s_part[0][lane];
#pragma unroll
        for (int w = 1; w < W; w++) {
            float4 q4 = s_part[w][lane];
            tt.x += q4.x; tt.y += q4.y; tt.z += q4.z; tt.w += q4.w;
        }
        float4 b4 = *(const float4*)(jb.bias + lane * 4);
        float4 o4;
        o4.x = tt.x * inv + b4.x;
        o4.y = tt.y * inv + b4.y;
        o4.z = tt.z * inv + b4.z;
        o4.w = tt.w * inv + b4.w;
        *(float4*)(jb.out + (size_t)t * jb.ldo + lane * 4) = o4;
    }
}

// ---------------- batch norm stats ----------------
template <int C>
__global__ void bn_stats(const float* __restrict__ h) {
    int c = blockIdx.x;
    int tid = threadIdx.x;
    float s = 0.f, s2 = 0.f;
    for (int r = tid; r < NN; r += 256) {
        float v = h[(size_t)r * C + c];
        s += v; s2 += v * v;
    }
    __shared__ float sh[8], sh2[8];
#pragma unroll
    for (int o = 16; o; o >>= 1) {
        s  += __shfl_xor_sync(0xffffffffu, s,  o);
        s2 += __shfl_xor_sync(0xffffffffu, s2, o);
    }
    if ((tid & 31) == 0) { sh[tid >> 5] = s; sh2[tid >> 5] = s2; }
    __syncthreads();
    if (tid == 0) {
        float ts = 0.f, ts2 = 0.f;
        for (int w = 0; w < 8; w++) { ts += sh[w]; ts2 += sh2[w]; }
        float mean = ts / NN;
        float var = ts2 / NN - mean * mean;
        g_mean[c] = mean;
        g_rstd[c] = rsqrtf(var + BN_EPS);
    }
}

// ---------------- reparameterize ----------------
__global__ void k_reparam(const float* __restrict__ eps, float* __restrict__ out) {
    int i = blockIdx.x * blockDim.x + threadIdx.x;
    if (i >= NN * NHID2) return;
    float mu = out[MU_OFF + i];
    float lv = out[LV_OFF + i];
    out[EMB_OFF + i] = eps[i] * __expf(lv) + mu;
}

// ---------------- readj = sigmoid(emb @ emb^T) via bf16 HMMA split --------
#define GP 72
#define G_AHI 0
#define G_ALO (G_AHI + 128 * GP * 2)
#define G_BHI (G_ALO + 128 * GP * 2)
#define G_BLO (G_BHI + 128 * GP * 2)
#define G_SMEM (G_BLO + 128 * GP * 2)    // 73728

__global__ __launch_bounds__(256)
void gram_hmma(const float* __restrict__ E, float* __restrict__ out) {
    int by = blockIdx.y, bx = blockIdx.x;
    if (bx < by) return;
    extern __shared__ __align__(16) char smem[];
    uint32_t sb = smem_u32(smem);
    int tid = threadIdx.x, lane = tid & 31, warp = tid >> 5;
    int row0 = by * 128, col0 = bx * 128;

    {
        int rrow = tid >> 1;
        int ks = (tid & 1) * 32;
        int rA = row0 + rrow, rB = col0 + rrow;
        const float4* pa = (const float4*)(E + (size_t)rA * 64 + ks);
        const float4* pb = (const float4*)(E + (size_t)rB * 64 + ks);
        bool va = rA < NN, vb = rB < NN;
        uint32_t base = (rrow * GP + ks) * 2;
#pragma unroll
        for (int q = 0; q < 8; q++) {
            float4 a = va ? pa[q] : make_float4(0.f, 0.f, 0.f, 0.f);
            float4 b = vb ? pb[q] : make_float4(0.f, 0.f, 0.f, 0.f);
            float av[4] = { a.x, a.y, a.z, a.w };
            float bv[4] = { b.x, b.y, b.z, b.w };
#pragma unroll
            for (int h = 0; h < 2; h++) {
                uint16_t h0, l0, h1, l1;
                bf16split(av[2 * h], h0, l0);
                bf16split(av[2 * h + 1], h1, l1);
                uint32_t ah = (uint32_t)h0 | ((uint32_t)h1 << 16);
                uint32_t al = (uint32_t)l0 | ((uint32_t)l1 << 16);
                bf16split(bv[2 * h], h0, l0);
                bf16split(bv[2 * h + 1], h1, l1);
                uint32_t bh = (uint32_t)h0 | ((uint32_t)h1 << 16);
                uint32_t bl = (uint32_t)l0 | ((uint32_t)l1 << 16);
                uint32_t off = base + (q * 4 + h * 2) * 2;
                *(uint32_t*)(smem + G_AHI + off) = ah;
                *(uint32_t*)(smem + G_ALO + off) = al;
                *(uint32_t*)(smem + G_BHI + off) = bh;
                *(uint32_t*)(smem + G_BLO + off) = bl;
            }
        }
    }
    __syncthreads();

    int wm = (warp & 1) * 64;
    int wn = (warp >> 1) * 32;
    float c[4][4][4];
#pragma unroll
    for (int mi = 0; mi < 4; mi++)
#pragma unroll
        for (int ni = 0; ni < 4; ni++)
#pragma unroll
            for (int e = 0; e < 4; e++) c[mi][ni][e] = 0.f;

    int grp = lane >> 3, rl = lane & 7;
#pragma unroll
    for (int pass = 0; pass < 3; pass++) {
        uint32_t aBase = sb + ((pass == 2) ? G_ALO : G_AHI);
        uint32_t bBase = sb + ((pass == 1) ? G_BLO : G_BHI);
#pragma unroll
        for (int k0 = 0; k0 < 64; k0 += 16) {
            uint32_t af[4][4], bf[4][2];
#pragma unroll
            for (int mi = 0; mi < 4; mi++) {
                int arow = wm + mi * 16 + (grp & 1) * 8 + rl;
                int acol = k0 + (grp >> 1) * 8;
                ldsm_x4(af[mi][0], af[mi][1], af[mi][2], af[mi][3],
                        aBase + (arow * GP + acol) * 2);
            }
#pragma unroll
            for (int ni = 0; ni < 4; ni++) {
                int brow = wn + ni * 8 + rl;
                int bcol = k0 + (grp & 1) * 8;
                ldsm_x2(bf[ni][0], bf[ni][1], bBase + (brow * GP + bcol) * 2);
            }
#pragma unroll
            for (int mi = 0; mi < 4; mi++)
#pragma unroll
                for (int ni = 0; ni < 4; ni++)
                    mma_bf16(c[mi][ni], af[mi][0], af[mi][1], af[mi][2], af[mi][3],
                             bf[ni][0], bf[ni][1]);
        }
    }
    __syncthreads();

    float* stag = (float*)smem;
    bool diag = (bx == by);
    int qr = lane >> 2, qc = 2 * (lane & 3);
#pragma unroll
    for (int mi = 0; mi < 4; mi++) {
#pragma unroll
        for (int ni = 0; ni < 4; ni++) {
#pragma unroll
            for (int half = 0; half < 2; half++) {
                int row = wm + mi * 16 + qr + half * 8;
                int col = wn + ni * 8 + qc;
                float v0 = 1.f / (1.f + __expf(-c[mi][ni][2 * half]));
                float v1 = 1.f / (1.f + __expf(-c[mi][ni][2 * half + 1]));
                int r = row0 + row, cc = col0 + col;
                if (r < NN && cc < NN)
                    *(float2*)(out + (size_t)r * NN + cc) = make_float2(v0, v1);
                if (!diag) {
                    int s = row & 31;
                    stag[row * 128 + (col ^ s)] = v0;
                    stag[row * 128 + ((col + 1) ^ s)] = v1;
                }
            }
        }
    }
    if (diag) return;
    __syncthreads();

    {
        int mr = tid >> 1;
        int half = tid & 1;
        int cgl = col0 + mr;
        if (cgl < NN) {
            float* mrow = out + (size_t)cgl * NN + row0 + half * 64;
            int ibase = half * 64;
#pragma unroll
            for (int i = 0; i < 64; i += 4) {
                int i0 = ibase + i;
                if (row0 + i0 < NN) {
                    float4 w;
                    w.x = stag[(i0 + 0) * 128 + (mr ^ ((i0 + 0) & 31))];
                    w.y = stag[(i0 + 1) * 128 + (mr ^ ((i0 + 1) & 31))];
                    w.z = stag[(i0 + 2) * 128 + (mr ^ ((i0 + 2) & 31))];
                    w.w = stag[(i0 + 3) * 128 + (mr ^ ((i0 + 3) & 31))];
                    *(float4*)mrow = w;
                }
                mrow += 4;
            }
        }
    }
}

// ---------------- launch ----------------
extern "C" void kernel_launch(void* const* d_in, const int* in_sizes, int n_in,
                              void* d_out, int out_size) {
    const float* x   = (const float*)d_in[0];
    const int*   ei  = (const int*)  d_in[1];
    const float* eps = (const float*)d_in[2];
    const float* w1l = (const float*)d_in[3];
    const float* b1l = (const float*)d_in[4];
    const float* w1r = (const float*)d_in[5];
    const float* b1r = (const float*)d_in[6];
    const float* a1  = (const float*)d_in[7];
    const float* bias1 = (const float*)d_in[8];
    const float* bn1_g = (const float*)d_in[9];
    const float* bn1_b = (const float*)d_in[10];
    const float* w2l = (const float*)d_in[11];
    const float* b2l = (const float*)d_in[12];
    const float* w2r = (const float*)d_in[13];
    const float* b2r = (const float*)d_in[14];
    const float* a2  = (const float*)d_in[15];
    const float* bias2 = (const float*)d_in[16];
    const float* w3l = (const float*)d_in[17];
    const float* b3l = (const float*)d_in[18];
    const float* w3r = (const float*)d_in[19];
    const float* b3r = (const float*)d_in[20];
    const float* a3  = (const float*)d_in[21];
    const float* bias3 = (const float*)d_in[22];
    const float* dw1 = (const float*)d_in[23];
    const float* db1 = (const float*)d_in[24];
    const float* dbn_g = (const float*)d_in[25];
    const float* dbn_b = (const float*)d_in[26];
    const float* dw2 = (const float*)d_in[27];
    const float* db2 = (const float*)d_in[28];
    float* out = (float*)d_out;

    float *p_xl1, *p_xr1, *p_h, *p_x23, *p_d, *p_b23;
    cudaGetSymbolAddress((void**)&p_xl1, g_xl1);
    cudaGetSymbolAddress((void**)&p_xr1, g_xr1);
    cudaGetSymbolAddress((void**)&p_h,   g_h);
    cudaGetSymbolAddress((void**)&p_x23, g_x23);
    cudaGetSymbolAddress((void**)&p_d,   g_d);
    cudaGetSymbolAddress((void**)&p_b23, g_bias23);
    uint16_t *p_w1lh, *p_w1ll, *p_w1rh, *p_w1rl, *p_w23h, *p_w23l;
    uint16_t *p_dw1h, *p_dw1l, *p_dw2h, *p_dw2l;
    cudaGetSymbolAddress((void**)&p_w1lh, g_w1lh);
    cudaGetSymbolAddress((void**)&p_w1ll, g_w1ll);
    cudaGetSymbolAddress((void**)&p_w1rh, g_w1rh);
    cudaGetSymbolAddress((void**)&p_w1rl, g_w1rl);
    cudaGetSymbolAddress((void**)&p_w23h, g_w23h);
    cudaGetSymbolAddress((void**)&p_w23l, g_w23l);
    cudaGetSymbolAddress((void**)&p_dw1h, g_dw1h);
    cudaGetSymbolAddress((void**)&p_dw1l, g_dw1l);
    cudaGetSymbolAddress((void**)&p_dw2h, g_dw2h);
    cudaGetSymbolAddress((void**)&p_dw2l, g_dw2l);

    cudaFuncSetAttribute(gram_hmma, cudaFuncAttributeMaxDynamicSharedMemorySize, G_SMEM);

    // lazy one-time stream/event creation (host objects only; no device mem)
    static cudaStream_t s_side = nullptr;
    static cudaEvent_t evA = nullptr, evB = nullptr, evC = nullptr, evD = nullptr;
    if (!s_side) {
        cudaStreamCreateWithFlags(&s_side, cudaStreamNonBlocking);
        cudaEventCreateWithFlags(&evA, cudaEventDisableTiming);
        cudaEventCreateWithFlags(&evB, cudaEventDisableTiming);
        cudaEventCreateWithFlags(&evC, cudaEventDisableTiming);
        cudaEventCreateWithFlags(&evD, cudaEventDisableTiming);
    }

    const int MT = (NN + 127) / 128;   // 79

    // ---- fork: CSR build on side stream ----
    cudaEventRecord(evA, 0);
    cudaStreamWaitEvent(s_side, evA, 0);
    k_zero_counts<<<(NN + 255) / 256, 256, 0, s_side>>>();
    k_count_deg<<<(NE + 255) / 256, 256, 0, s_side>>>(ei);
    k_scan_deg<<<1, 1024, 0, s_side>>>();
    k_fill_list<<<(NE + 255) / 256, 256, 0, s_side>>>(ei);
    cudaEventRecord(evB, s_side);

    // ---- main: weight splits + bias pack + layer-1 HMMA GEMM ----
    k_wsplit<<<(NFEAT * H1 + 255) / 256, 256>>>(w1l, p_w1lh, p_w1ll, NFEAT, H1);
    k_wsplit<<<(NFEAT * H1 + 255) / 256, 256>>>(w1r, p_w1rh, p_w1rl, NFEAT, H1);
    k_wsplit4<<<(256 * H1 + 255) / 256, 256>>>(w2l, w2r, w3l, w3r, p_w23h, p_w23l);
    k_wsplit<<<(NHID1 * NHID2 + 255) / 256, 256>>>(dw1, p_dw1h, p_dw1l, NHID2, NHID1);
    k_wsplit<<<(NHID1 * NFEAT + 255) / 256, 256>>>(dw2, p_dw2h, p_dw2l, NHID1, NFEAT);
    cudaMemcpyAsync(p_b23,       b2l, 64 * sizeof(float), cudaMemcpyDeviceToDevice, 0);
    cudaMemcpyAsync(p_b23 + 64,  b2r, 64 * sizeof(float), cudaMemcpyDeviceToDevice, 0);
    cudaMemcpyAsync(p_b23 + 128, b3l, 64 * sizeof(float), cudaMemcpyDeviceToDevice, 0);
    cudaMemcpyAsync(p_b23 + 192, b3r, 64 * sizeof(float), cudaMemcpyDeviceToDevice, 0);
    {
        TJobs j1 = {{ { p_w1lh, p_w1ll, b1l, p_xl1 }, { p_w1rh, p_w1rl, b1r, p_xr1 } }};
        gemmT<<<dim3(1, MT, 2), 256>>>(x, j1, NN, NFEAT, H1, nullptr, nullptr);
    }
    cudaStreamWaitEvent(0, evB, 0);   // join CSR

    // ---- GAT layer 1 -> BN stats (apply fused into next GEMM) ----
    {
        AJobs aj = {{ { p_xl1, p_xr1, H1, a1, bias1, p_h, H1 }, {} }};
        gat_agg<H1><<<dim3(NN, 1), H1>>>(aj);
    }
    bn_stats<H1><<<H1, 256>>>(p_h);

    // ---- layers 2 & 3 packed GEMM (BN+ReLU fused on A) ----
    {
        TJobs j2 = {{ { p_w23h, p_w23l, p_b23, p_x23 }, {} }};
        gemmT<<<dim3(2, MT, 1), 256>>>(p_h, j2, NN, H1, 256, bn1_g, bn1_b);
    }

    // ---- GAT layers 2 (mu) and 3 (logvar) ----
    {
        AJobs aj = {{ { p_x23 + 0,   p_x23 + 64,  256, a2, bias2, out + MU_OFF, 64 },
                      { p_x23 + 128, p_x23 + 192, 256, a3, bias3, out + LV_OFF, 64 } }};
        gat_agg<NHID2><<<dim3(NN, 2), NHID2>>>(aj);
    }

    // ---- reparameterize ----
    k_reparam<<<(NN * NHID2 + 255) / 256, 256>>>(eps, out);

    // ---- fork: decoder MLP on side stream, gram on main ----
    cudaEventRecord(evC, 0);
    cudaStreamWaitEvent(s_side, evC, 0);
    {
        TJobs jd = {{ { p_dw1h, p_dw1l, db1, p_d }, {} }};
        gemmT<<<dim3(2, MT, 1), 256, 0, s_side>>>(out + EMB_OFF, jd, NN, NHID2, NHID1,
                                                  nullptr, nullptr);
    }
    bn_stats<NHID1><<<NHID1, 256, 0, s_side>>>(p_d);
    {
        TJobs jd = {{ { p_dw2h, p_dw2l, db2, out + REX_OFF }, {} }};
        gemmT<<<dim3(4, MT, 1), 256, 0, s_side>>>(p_d, jd, NN, NHID1, NFEAT,
                                                  dbn_g, dbn_b);
    }
    cudaEventRecord(evD, s_side);

    gram_hmma<<<dim3(MT, MT), 256, G_SMEM>>>(out + EMB_OFF, out + READJ_OFF);

    cudaStreamWaitEvent(0, evD, 0);   // join decoder
}

// round 9
// speedup vs baseline: 1.7417x; 1.1690x over previous
#include <cuda_runtime.h>
#include <cuda_bf16.h>
#include <cuda_fp16.h>
#include <cstdint>
#include <math.h>

#define NN     10000
#define EE     320000
#define NE     (EE + NN)     // with self loops
#define NFEAT  512
#define NHID1  256
#define NHID2  64
#define H1     128           // 2*nhid2
#define NEG_SLOPE 0.2f
#define BN_EPS 1e-5f
#define MAXDEG 512

// output layout (flattened tuple: emb, re_x, readj, mu, logvar)
#define EMB_OFF   ((size_t)0)
#define REX_OFF   ((size_t)NN * NHID2)
#define READJ_OFF (REX_OFF + (size_t)NN * NFEAT)
#define MU_OFF    (READJ_OFF + (size_t)NN * NN)
#define LV_OFF    (MU_OFF + (size_t)NN * NHID2)

typedef unsigned long long u64;

// ---------------- warp MMA helpers (baseline PTX, works on sm_103) --------
__device__ __forceinline__ uint32_t smem_u32(const void* p) {
    uint32_t a;
    asm("{ .reg .u64 t; cvta.to.shared.u64 t, %1; cvt.u32.u64 %0, t; }" : "=r"(a) : "l"(p));
    return a;
}
__device__ __forceinline__ void ldsm_x4(uint32_t& r0, uint32_t& r1, uint32_t& r2, uint32_t& r3, uint32_t addr) {
    asm volatile("ldmatrix.sync.aligned.m8n8.x4.shared.b16 {%0,%1,%2,%3}, [%4];"
                 : "=r"(r0), "=r"(r1), "=r"(r2), "=r"(r3) : "r"(addr));
}
__device__ __forceinline__ void ldsm_x2(uint32_t& r0, uint32_t& r1, uint32_t addr) {
    asm volatile("ldmatrix.sync.aligned.m8n8.x2.shared.b16 {%0,%1}, [%2];"
                 : "=r"(r0), "=r"(r1) : "r"(addr));
}
__device__ __forceinline__ void mma_bf16(float* d, uint32_t a0, uint32_t a1, uint32_t a2, uint32_t a3,
                                         uint32_t b0, uint32_t b1) {
    asm volatile("mma.sync.aligned.m16n8k16.row.col.f32.bf16.bf16.f32 "
                 "{%0,%1,%2,%3}, {%4,%5,%6,%7}, {%8,%9}, {%0,%1,%2,%3};"
                 : "+f"(d[0]), "+f"(d[1]), "+f"(d[2]), "+f"(d[3])
                 : "r"(a0), "r"(a1), "r"(a2), "r"(a3), "r"(b0), "r"(b1));
}
__device__ __forceinline__ void mma_f16(float* d, uint32_t a0, uint32_t a1, uint32_t a2, uint32_t a3,
                                        uint32_t b0, uint32_t b1) {
    asm volatile("mma.sync.aligned.m16n8k16.row.col.f32.f16.f16.f32 "
                 "{%0,%1,%2,%3}, {%4,%5,%6,%7}, {%8,%9}, {%0,%1,%2,%3};"
                 : "+f"(d[0]), "+f"(d[1]), "+f"(d[2]), "+f"(d[3])
                 : "r"(a0), "r"(a1), "r"(a2), "r"(a3), "r"(b0), "r"(b1));
}
__device__ __forceinline__ void bf16split(float v, uint16_t& h, uint16_t& l) {
    __nv_bfloat16 hb = __float2bfloat16_rn(v);
    __nv_bfloat16 lb = __float2bfloat16_rn(v - __bfloat162float(hb));
    h = __bfloat16_as_ushort(hb);
    l = __bfloat16_as_ushort(lb);
}

// ---------------- scratch (device globals; no allocation allowed) ----------
__device__ float g_xl1[NN * H1];
__device__ float g_xr1[NN * H1];
__device__ float g_h  [NN * H1];
__device__ float g_x23[NN * 256];        // packed: xl2|xr2|xl3|xr3 (64 each)
__device__ float g_d  [NN * NHID1];
__device__ int   g_deg[NN];
__device__ int   g_rowptr[NN + 1];
__device__ int   g_cursor[NN];
__device__ int   g_srclist[NE];
__device__ float g_mean[NHID1];
__device__ float g_rstd[NHID1];
__device__ float g_bias23[256];
// emb fp16 hi/lo (pre-split for gram)
__device__ uint16_t g_ebh[NN * NHID2], g_ebl[NN * NHID2];
// transposed bf16 hi/lo weights [Nc][K]
__device__ uint16_t g_w1lh[H1 * NFEAT],  g_w1ll[H1 * NFEAT];
__device__ uint16_t g_w1rh[H1 * NFEAT],  g_w1rl[H1 * NFEAT];
__device__ uint16_t g_w23h[256 * H1],    g_w23l[256 * H1];
__device__ uint16_t g_dw1h[NHID1 * NHID2], g_dw1l[NHID1 * NHID2];
__device__ uint16_t g_dw2h[NFEAT * NHID1], g_dw2l[NFEAT * NHID1];

// ---------------- CSR build ----------------
__global__ void k_zero_counts() {
    int i = blockIdx.x * blockDim.x + threadIdx.x;
    if (i < NN) { g_deg[i] = 0; g_cursor[i] = 0; }
}

__global__ void k_count_deg(const int* __restrict__ edge_index) {
    int i = blockIdx.x * blockDim.x + threadIdx.x;
    if (i >= NE) return;
    int tgt = (i < EE) ? edge_index[EE + i] : (i - EE);
    atomicAdd(&g_deg[tgt], 1);
}

__global__ void k_scan_deg() {
    __shared__ int wsum[32];
    __shared__ int sc;
    int tid = threadIdx.x, lane = tid & 31, w = tid >> 5;
    if (tid == 0) { sc = 0; g_rowptr[0] = 0; }
    __syncthreads();
    for (int base = 0; base < NN; base += 1024) {
        int i = base + tid;
        int v = (i < NN) ? g_deg[i] : 0;
        int x = v;
#pragma unroll
        for (int o = 1; o < 32; o <<= 1) {
            int t = __shfl_up_sync(0xffffffffu, x, o);
            if (lane >= o) x += t;
        }
        if (lane == 31) wsum[w] = x;
        __syncthreads();
        if (w == 0) {
            int y = wsum[lane];
#pragma unroll
            for (int o = 1; o < 32; o <<= 1) {
                int t = __shfl_up_sync(0xffffffffu, y, o);
                if (lane >= o) y += t;
            }
            wsum[lane] = y;
        }
        __syncthreads();
        int pre = (w > 0) ? wsum[w - 1] : 0;
        int c = sc;
        if (i < NN) g_rowptr[i + 1] = c + pre + x;
        int total = wsum[31];
        __syncthreads();
        if (tid == 0) sc = c + total;
        __syncthreads();
    }
}

__global__ void k_fill_list(const int* __restrict__ edge_index) {
    int i = blockIdx.x * blockDim.x + threadIdx.x;
    if (i >= NE) return;
    int src, tgt;
    if (i < EE) { src = edge_index[i]; tgt = edge_index[EE + i]; }
    else        { src = i - EE;        tgt = i - EE; }
    int pos = atomicAdd(&g_cursor[tgt], 1);
    g_srclist[g_rowptr[tgt] + pos] = src;
}

// ---------------- weight transpose + bf16 split ----------------
__global__ void k_wsplit(const float* __restrict__ W, uint16_t* __restrict__ hi,
                         uint16_t* __restrict__ lo, int K, int Nc) {
    int i = blockIdx.x * blockDim.x + threadIdx.x;
    if (i >= K * Nc) return;
    int n = i / K, k = i - n * K;
    uint16_t h, l;
    bf16split(W[(size_t)k * Nc + n], h, l);
    hi[i] = h; lo[i] = l;
}
__global__ void k_wsplit4(const float* __restrict__ W0, const float* __restrict__ W1,
                          const float* __restrict__ W2, const float* __restrict__ W3,
                          uint16_t* __restrict__ hi, uint16_t* __restrict__ lo) {
    int i = blockIdx.x * blockDim.x + threadIdx.x;
    if (i >= 256 * H1) return;
    int np = i >> 7, k = i & 127;
    int jj = np >> 6, n = np & 63;
    const float* W = (jj == 0) ? W0 : (jj == 1) ? W1 : (jj == 2) ? W2 : W3;
    uint16_t h, l;
    bf16split(W[(size_t)k * 64 + n], h, l);
    hi[i] = h; lo[i] = l;
}
__global__ void k_pack_bias(const float* __restrict__ b0, const float* __restrict__ b1,
                            const float* __restrict__ b2, const float* __restrict__ b3) {
    int i = threadIdx.x;            // 256 threads
    int jj = i >> 6, n = i & 63;
    const float* b = (jj == 0) ? b0 : (jj == 1) ? b1 : (jj == 2) ? b2 : b3;
    g_bias23[i] = b[n];
}

// ---------------- GEMM job plumbing ----------------
struct TJob  { const uint16_t* Bh; const uint16_t* Bl; const float* bias; float* C; };
struct TJobs { TJob j[2]; };

// ---------------- gemmT: HMMA bf16 split GEMM, 128x128 tile --------------
__global__ __launch_bounds__(256)
void gemmT(const float* __restrict__ A, TJobs jobs, int M, int K, int Nc,
           const float* __restrict__ bnG, const float* __restrict__ bnB) {
    const TJob jb = jobs.j[blockIdx.z];
    __shared__ __align__(16) uint16_t Ah[128][40], Al[128][40];
    __shared__ __align__(16) uint16_t Bh[128][40], Bl[128][40];
    int tid = threadIdx.x, lane = tid & 31, warp = tid >> 5;
    int row0 = blockIdx.y * 128, col0 = blockIdx.x * 128;
    int wm = (warp & 1) * 64, wn = (warp >> 1) * 32;
    int grp = lane >> 3, rl = lane & 7;
    float c[4][4][4];
#pragma unroll
    for (int mi = 0; mi < 4; mi++)
#pragma unroll
        for (int ni = 0; ni < 4; ni++)
#pragma unroll
            for (int e = 0; e < 4; e++) c[mi][ni][e] = 0.f;

    int ar = tid >> 1, kh = (tid & 1) * 16;
    int r = row0 + ar;
    bool va = r < M;

    for (int k0 = 0; k0 < K; k0 += 32) {
        const float* pa = A + (size_t)r * K + k0 + kh;
#pragma unroll
        for (int q = 0; q < 4; q++) {
            float4 v = va ? *(const float4*)(pa + q * 4) : make_float4(0.f, 0.f, 0.f, 0.f);
            if (bnG) {
                int ch = k0 + kh + q * 4;
                float4 mm = *(const float4*)(g_mean + ch);
                float4 rs = *(const float4*)(g_rstd + ch);
                float4 gg = *(const float4*)(bnG + ch);
                float4 bb = *(const float4*)(bnB + ch);
                v.x = fmaxf((v.x - mm.x) * rs.x * gg.x + bb.x, 0.f);
                v.y = fmaxf((v.y - mm.y) * rs.y * gg.y + bb.y, 0.f);
                v.z = fmaxf((v.z - mm.z) * rs.z * gg.z + bb.z, 0.f);
                v.w = fmaxf((v.w - mm.w) * rs.w * gg.w + bb.w, 0.f);
            }
            uint16_t h0, l0, h1, l1, h2, l2, h3, l3;
            bf16split(v.x, h0, l0); bf16split(v.y, h1, l1);
            bf16split(v.z, h2, l2); bf16split(v.w, h3, l3);
            *(uint32_t*)&Ah[ar][kh + q * 4]     = (uint32_t)h0 | ((uint32_t)h1 << 16);
            *(uint32_t*)&Ah[ar][kh + q * 4 + 2] = (uint32_t)h2 | ((uint32_t)h3 << 16);
            *(uint32_t*)&Al[ar][kh + q * 4]     = (uint32_t)l0 | ((uint32_t)l1 << 16);
            *(uint32_t*)&Al[ar][kh + q * 4 + 2] = (uint32_t)l2 | ((uint32_t)l3 << 16);
        }
        {
            const uint16_t* pbh = jb.Bh + (size_t)(col0 + ar) * K + k0 + kh;
            const uint16_t* pbl = jb.Bl + (size_t)(col0 + ar) * K + k0 + kh;
            *(uint4*)&Bh[ar][kh]     = *(const uint4*)pbh;
            *(uint4*)&Bh[ar][kh + 8] = *(const uint4*)(pbh + 8);
            *(uint4*)&Bl[ar][kh]     = *(const uint4*)pbl;
            *(uint4*)&Bl[ar][kh + 8] = *(const uint4*)(pbl + 8);
        }
        __syncthreads();
#pragma unroll
        for (int pass = 0; pass < 3; pass++) {
            const uint16_t (*Aq)[40] = (pass == 2) ? Al : Ah;
            const uint16_t (*Bq)[40] = (pass == 1) ? Bl : Bh;
#pragma unroll
            for (int k1 = 0; k1 < 32; k1 += 16) {
                uint32_t af[4][4], bf[4][2];
#pragma unroll
                for (int mi = 0; mi < 4; mi++) {
                    int arow = wm + mi * 16 + (grp & 1) * 8 + rl;
                    int acol = k1 + (grp >> 1) * 8;
                    ldsm_x4(af[mi][0], af[mi][1], af[mi][2], af[mi][3],
                            smem_u32(&Aq[arow][acol]));
                }
#pragma unroll
                for (int ni = 0; ni < 4; ni++) {
                    int brow = wn + ni * 8 + rl;
                    int bcol = k1 + (grp & 1) * 8;
                    ldsm_x2(bf[ni][0], bf[ni][1], smem_u32(&Bq[brow][bcol]));
                }
#pragma unroll
                for (int mi = 0; mi < 4; mi++)
#pragma unroll
                    for (int ni = 0; ni < 4; ni++)
                        mma_bf16(c[mi][ni], af[mi][0], af[mi][1], af[mi][2], af[mi][3],
                                 bf[ni][0], bf[ni][1]);
            }
        }
        __syncthreads();
    }
    int qr = lane >> 2, qc = 2 * (lane & 3);
#pragma unroll
    for (int mi = 0; mi < 4; mi++) {
#pragma unroll
        for (int half = 0; half < 2; half++) {
            int row = wm + mi * 16 + qr + half * 8;
            int rr = row0 + row;
            if (rr < M) {
                float* Crow = jb.C + (size_t)rr * Nc;
#pragma unroll
                for (int ni = 0; ni < 4; ni++) {
                    int cc = col0 + wn + ni * 8 + qc;
                    float2 p;
                    p.x = c[mi][ni][2 * half]     + __ldg(&jb.bias[cc]);
                    p.y = c[mi][ni][2 * half + 1] + __ldg(&jb.bias[cc + 1]);
                    *(float2*)&Crow[cc] = p;
                }
            }
        }
    }
}

// ---------------- gemmT64: same, 64x128 tile (better wave balance) --------
__global__ __launch_bounds__(256)
void gemmT64(const float* __restrict__ A, TJobs jobs, int M, int K, int Nc,
             const float* __restrict__ bnG, const float* __restrict__ bnB) {
    const TJob jb = jobs.j[blockIdx.z];
    __shared__ __align__(16) uint16_t Ah[64][40], Al[64][40];
    __shared__ __align__(16) uint16_t Bh[128][40], Bl[128][40];
    int tid = threadIdx.x, lane = tid & 31, warp = tid >> 5;
    int row0 = blockIdx.y * 64, col0 = blockIdx.x * 128;
    int wm = (warp & 1) * 32, wn = (warp >> 1) * 32;
    int grp = lane >> 3, rl = lane & 7;
    float c[2][4][4];
#pragma unroll
    for (int mi = 0; mi < 2; mi++)
#pragma unroll
        for (int ni = 0; ni < 4; ni++)
#pragma unroll
            for (int e = 0; e < 4; e++) c[mi][ni][e] = 0.f;

    int ar = tid >> 2, ks = (tid & 3) * 8;     // A: 64 rows, 8 vals per thread
    int br = tid >> 1, kb = (tid & 1) * 16;    // B: 128 rows, 16 vals per thread
    int r = row0 + ar;
    bool va = r < M;

    for (int k0 = 0; k0 < K; k0 += 32) {
        const float* pa = A + (size_t)r * K + k0 + ks;
#pragma unroll
        for (int q = 0; q < 2; q++) {
            float4 v = va ? *(const float4*)(pa + q * 4) : make_float4(0.f, 0.f, 0.f, 0.f);
            if (bnG) {
                int ch = k0 + ks + q * 4;
                float4 mm = *(const float4*)(g_mean + ch);
                float4 rs = *(const float4*)(g_rstd + ch);
                float4 gg = *(const float4*)(bnG + ch);
                float4 bb = *(const float4*)(bnB + ch);
                v.x = fmaxf((v.x - mm.x) * rs.x * gg.x + bb.x, 0.f);
                v.y = fmaxf((v.y - mm.y) * rs.y * gg.y + bb.y, 0.f);
                v.z = fmaxf((v.z - mm.z) * rs.z * gg.z + bb.z, 0.f);
                v.w = fmaxf((v.w - mm.w) * rs.w * gg.w + bb.w, 0.f);
            }
            uint16_t h0, l0, h1, l1, h2, l2, h3, l3;
            bf16split(v.x, h0, l0); bf16split(v.y, h1, l1);
            bf16split(v.z, h2, l2); bf16split(v.w, h3, l3);
            *(uint32_t*)&Ah[ar][ks + q * 4]     = (uint32_t)h0 | ((uint32_t)h1 << 16);
            *(uint32_t*)&Ah[ar][ks + q * 4 + 2] = (uint32_t)h2 | ((uint32_t)h3 << 16);
            *(uint32_t*)&Al[ar][ks + q * 4]     = (uint32_t)l0 | ((uint32_t)l1 << 16);
            *(uint32_t*)&Al[ar][ks + q * 4 + 2] = (uint32_t)l2 | ((uint32_t)l3 << 16);
        }
        {
            const uint16_t* pbh = jb.Bh + (size_t)(col0 + br) * K + k0 + kb;
            const uint16_t* pbl = jb.Bl + (size_t)(col0 + br) * K + k0 + kb;
            *(uint4*)&Bh[br][kb]     = *(const uint4*)pbh;
            *(uint4*)&Bh[br][kb + 8] = *(const uint4*)(pbh + 8);
            *(uint4*)&Bl[br][kb]     = *(const uint4*)pbl;
            *(uint4*)&Bl[br][kb + 8] = *(const uint4*)(pbl + 8);
        }
        __syncthreads();
#pragma unroll
        for (int pass = 0; pass < 3; pass++) {
            const uint16_t (*Aq)[40] = (pass == 2) ? Al : Ah;
            const uint16_t (*Bq)[40] = (pass == 1) ? Bl : Bh;
#pragma unroll
            for (int k1 = 0; k1 < 32; k1 += 16) {
                uint32_t af[2][4], bf[4][2];
#pragma unroll
                for (int mi = 0; mi < 2; mi++) {
                    int arow = wm + mi * 16 + (grp & 1) * 8 + rl;
                    int acol = k1 + (grp >> 1) * 8;
                    ldsm_x4(af[mi][0], af[mi][1], af[mi][2], af[mi][3],
                            smem_u32(&Aq[arow][acol]));
                }
#pragma unroll
                for (int ni = 0; ni < 4; ni++) {
                    int brow = wn + ni * 8 + rl;
                    int bcol = k1 + (grp & 1) * 8;
                    ldsm_x2(bf[ni][0], bf[ni][1], smem_u32(&Bq[brow][bcol]));
                }
#pragma unroll
                for (int mi = 0; mi < 2; mi++)
#pragma unroll
                    for (int ni = 0; ni < 4; ni++)
                        mma_bf16(c[mi][ni], af[mi][0], af[mi][1], af[mi][2], af[mi][3],
                                 bf[ni][0], bf[ni][1]);
            }
        }
        __syncthreads();
    }
    int qr = lane >> 2, qc = 2 * (lane & 3);
#pragma unroll
    for (int mi = 0; mi < 2; mi++) {
#pragma unroll
        for (int half = 0; half < 2; half++) {
            int row = wm + mi * 16 + qr + half * 8;
            int rr = row0 + row;
            if (rr < M) {
                float* Crow = jb.C + (size_t)rr * Nc;
#pragma unroll
                for (int ni = 0; ni < 4; ni++) {
                    int cc = col0 + wn + ni * 8 + qc;
                    float2 p;
                    p.x = c[mi][ni][2 * half]     + __ldg(&jb.bias[cc]);
                    p.y = c[mi][ni][2 * half + 1] + __ldg(&jb.bias[cc + 1]);
                    *(float2*)&Crow[cc] = p;
                }
            }
        }
    }
}

// ---------------- GATv2 aggregation (one block per target node) -----------
struct AJob  { const float* xl; const float* xr; int ld; const float* att;
               const float* bias; float* out; int ldo; };
struct AJobs { AJob j[2]; };

template <int C>
__global__ void gat_agg(AJobs jobs) {
    constexpr int W  = C / 32;
    constexpr int NL = C / 4;
    const AJob jb = jobs.j[blockIdx.y];
    int t = blockIdx.x;
    int tid = threadIdx.x, lane = tid & 31, warp = tid >> 5;
    __shared__ float4 s_xr4[NL], s_att4[NL];
    __shared__ float  s_e[MAXDEG];
    __shared__ int    s_src[MAXDEG];
    __shared__ float  s_red[W];
    __shared__ float4 s_part[W][NL];
    if (tid < NL) {
        s_xr4[tid]  = *(const float4*)(jb.xr + (size_t)t * jb.ld + tid * 4);
        s_att4[tid] = *(const float4*)(jb.att + tid * 4);
    }
    int beg = g_rowptr[t];
    int deg = g_rowptr[t + 1] - beg;
    __syncthreads();

    float4 xr4 = make_float4(0.f, 0.f, 0.f, 0.f);
    float4 at4 = xr4;
    if (lane < NL) { xr4 = s_xr4[lane]; at4 = s_att4[lane]; }
    const float* xl = jb.xl;
    int ld = jb.ld;

    int j = warp;
    for (; j + W < deg; j += 2 * W) {
        int s0 = g_srclist[beg + j], s1 = g_srclist[beg + j + W];
        float p0 = 0.f, p1 = 0.f;
        if (lane < NL) {
            float4 v0 = *(const float4*)(xl + (size_t)s0 * ld + lane * 4);
            float4 v1 = *(const float4*)(xl + (size_t)s1 * ld + lane * 4);
            float a, b, cc, d;
            a = v0.x + xr4.x; a = fmaxf(a, NEG_SLOPE * a);
            b = v0.y + xr4.y; b = fmaxf(b, NEG_SLOPE * b);
            cc = v0.z + xr4.z; cc = fmaxf(cc, NEG_SLOPE * cc);
            d = v0.w + xr4.w; d = fmaxf(d, NEG_SLOPE * d);
            p0 = at4.x * a + at4.y * b + at4.z * cc + at4.w * d;
            a = v1.x + xr4.x; a = fmaxf(a, NEG_SLOPE * a);
            b = v1.y + xr4.y; b = fmaxf(b, NEG_SLOPE * b);
            cc = v1.z + xr4.z; cc = fmaxf(cc, NEG_SLOPE * cc);
            d = v1.w + xr4.w; d = fmaxf(d, NEG_SLOPE * d);
            p1 = at4.x * a + at4.y * b + at4.z * cc + at4.w * d;
        }
#pragma unroll
        for (int o = 16; o; o >>= 1) {
            p0 += __shfl_xor_sync(0xffffffffu, p0, o);
            p1 += __shfl_xor_sync(0xffffffffu, p1, o);
        }
        if (lane == 0) {
            s_e[j] = p0; s_src[j] = s0;
            s_e[j + W] = p1; s_src[j + W] = s1;
        }
    }
    if (j < deg) {
        int s0 = g_srclist[beg + j];
        float p0 = 0.f;
        if (lane < NL) {
            float4 v0 = *(const float4*)(xl + (size_t)s0 * ld + lane * 4);
            float a, b, cc, d;
            a = v0.x + xr4.x; a = fmaxf(a, NEG_SLOPE * a);
            b = v0.y + xr4.y; b = fmaxf(b, NEG_SLOPE * b);
            cc = v0.z + xr4.z; cc = fmaxf(cc, NEG_SLOPE * cc);
            d = v0.w + xr4.w; d = fmaxf(d, NEG_SLOPE * d);
            p0 = at4.x * a + at4.y * b + at4.z * cc + at4.w * d;
        }
#pragma unroll
        for (int o = 16; o; o >>= 1) p0 += __shfl_xor_sync(0xffffffffu, p0, o);
        if (lane == 0) { s_e[j] = p0; s_src[j] = s0; }
    }
    __syncthreads();

    float m = -1e30f;
    for (int q = tid; q < deg; q += C) m = fmaxf(m, s_e[q]);
#pragma unroll
    for (int o = 16; o; o >>= 1) m = fmaxf(m, __shfl_xor_sync(0xffffffffu, m, o));
    if (lane == 0) s_red[warp] = m;
    __syncthreads();
    m = s_red[0];
#pragma unroll
    for (int w = 1; w < W; w++) m = fmaxf(m, s_red[w]);
    __syncthreads();

    float ssum = 0.f;
    for (int q = tid; q < deg; q += C) {
        float wj = __expf(s_e[q] - m);
        s_e[q] = wj;
        ssum += wj;
    }
#pragma unroll
    for (int o = 16; o; o >>= 1) ssum += __shfl_xor_sync(0xffffffffu, ssum, o);
    if (lane == 0) s_red[warp] = ssum;
    __syncthreads();
    ssum = 0.f;
#pragma unroll
    for (int w = 0; w < W; w++) ssum += s_red[w];
    float inv = 1.f / ssum;

    float4 f0 = make_float4(0.f, 0.f, 0.f, 0.f);
    float4 f1 = f0;
    if (lane < NL) {
        int q = warp;
        for (; q + W < deg; q += 2 * W) {
            float w0 = s_e[q], w1 = s_e[q + W];
            float4 v0 = *(const float4*)(xl + (size_t)s_src[q] * ld + lane * 4);
            float4 v1 = *(const float4*)(xl + (size_t)s_src[q + W] * ld + lane * 4);
            f0.x += w0 * v0.x; f0.y += w0 * v0.y; f0.z += w0 * v0.z; f0.w += w0 * v0.w;
            f1.x += w1 * v1.x; f1.y += w1 * v1.y; f1.z += w1 * v1.z; f1.w += w1 * v1.w;
        }
        if (q < deg) {
            float w0 = s_e[q];
            float4 v0 = *(const float4*)(xl + (size_t)s_src[q] * ld + lane * 4);
            f0.x += w0 * v0.x; f0.y += w0 * v0.y; f0.z += w0 * v0.z; f0.w += w0 * v0.w;
        }
        f0.x += f1.x; f0.y += f1.y; f0.z += f1.z; f0.w += f1.w;
        s_part[warp][lane] = f0;
    }
    __syncthreads();
    if (warp == 0 && lane < NL) {
        float4 tt = s_part[0][lane];
#pragma unroll
        for (int w = 1; w < W; w++) {
            float4 q4 = s_part[w][lane];
            tt.x += q4.x; tt.y += q4.y; tt.z += q4.z; tt.w += q4.w;
        }
        float4 b4 = *(const float4*)(jb.bias + lane * 4);
        float4 o4;
        o4.x = tt.x * inv + b4.x;
        o4.y = tt.y * inv + b4.y;
        o4.z = tt.z * inv + b4.z;
        o4.w = tt.w * inv + b4.w;
        *(float4*)(jb.out + (size_t)t * jb.ldo + lane * 4) = o4;
    }
}

// ---------------- batch norm stats ----------------
template <int C>
__global__ void bn_stats(const float* __restrict__ h) {
    int c = blockIdx.x;
    int tid = threadIdx.x;
    float s = 0.f, s2 = 0.f;
    for (int r = tid; r < NN; r += 256) {
        float v = h[(size_t)r * C + c];
        s += v; s2 += v * v;
    }
    __shared__ float sh[8], sh2[8];
#pragma unroll
    for (int o = 16; o; o >>= 1) {
        s  += __shfl_xor_sync(0xffffffffu, s,  o);
        s2 += __shfl_xor_sync(0xffffffffu, s2, o);
    }
    if ((tid & 31) == 0) { sh[tid >> 5] = s; sh2[tid >> 5] = s2; }
    __syncthreads();
    if (tid == 0) {
        float ts = 0.f, ts2 = 0.f;
        for (int w = 0; w < 8; w++) { ts += sh[w]; ts2 += sh2[w]; }
        float mean = ts / NN;
        float var = ts2 / NN - mean * mean;
        g_mean[c] = mean;
        g_rstd[c] = rsqrtf(var + BN_EPS);
    }
}

// ---------------- reparameterize + fp16 pre-split ----------------
__global__ void k_reparam(const float* __restrict__ eps, float* __restrict__ out) {
    int i = blockIdx.x * blockDim.x + threadIdx.x;
    if (i >= NN * NHID2) return;
    float mu = out[MU_OFF + i];
    float lv = out[LV_OFF + i];
    float e = eps[i] * __expf(lv) + mu;
    out[EMB_OFF + i] = e;
    __half h = __float2half_rn(e);
    __half l = __float2half_rn(e - __half2float(h));
    g_ebh[i] = __half_as_ushort(h);
    g_ebl[i] = __half_as_ushort(l);
}

// ---------------- readj = sigmoid(emb @ emb^T), fp16 2-pass HMMA ----------
// smem: Ahi / Alo / Bhi as [128][GP] fp16; reused as 64KB fp32 staging.
#define GP 72
#define G_AHI 0
#define G_ALO (G_AHI + 128 * GP * 2)
#define G_BHI (G_ALO + 128 * GP * 2)
#define G_SMEM 65536     // stag 64KB dominates (fill arrays 55296B)

__global__ __launch_bounds__(256)
void gram_hmma(const uint16_t* __restrict__ Eh, const uint16_t* __restrict__ El,
               float* __restrict__ out) {
    int by = blockIdx.y, bx = blockIdx.x;
    if (bx < by) return;
    extern __shared__ __align__(16) char smem[];
    uint32_t sb = smem_u32(smem);
    int tid = threadIdx.x, lane = tid & 31, warp = tid >> 5;
    int row0 = by * 128, col0 = bx * 128;

    // fill: tid<128 -> A row hi+lo; tid>=128 -> B row hi
    {
        int rrow = tid & 127;
        uint4 z = make_uint4(0, 0, 0, 0);
        if (tid < 128) {
            int rA = row0 + rrow;
            bool va = rA < NN;
            const uint4* ph = (const uint4*)(Eh + (size_t)rA * 64);
            const uint4* pl = (const uint4*)(El + (size_t)rA * 64);
#pragma unroll
            for (int q = 0; q < 8; q++) {
                uint32_t off = (rrow * GP + q * 8) * 2;
                *(uint4*)(smem + G_AHI + off) = va ? ph[q] : z;
                *(uint4*)(smem + G_ALO + off) = va ? pl[q] : z;
            }
        } else {
            int rB = col0 + rrow;
            bool vb = rB < NN;
            const uint4* ph = (const uint4*)(Eh + (size_t)rB * 64);
#pragma unroll
            for (int q = 0; q < 8; q++) {
                uint32_t off = (rrow * GP + q * 8) * 2;
                *(uint4*)(smem + G_BHI + off) = vb ? ph[q] : z;
            }
        }
    }
    __syncthreads();

    int wm = (warp & 1) * 64;
    int wn = (warp >> 1) * 32;
    float c[4][4][4];
#pragma unroll
    for (int mi = 0; mi < 4; mi++)
#pragma unroll
        for (int ni = 0; ni < 4; ni++)
#pragma unroll
            for (int e = 0; e < 4; e++) c[mi][ni][e] = 0.f;

    int grp = lane >> 3, rl = lane & 7;
#pragma unroll
    for (int pass = 0; pass < 2; pass++) {
        uint32_t aBase = sb + ((pass == 1) ? G_ALO : G_AHI);
        uint32_t bBase = sb + G_BHI;
#pragma unroll
        for (int k0 = 0; k0 < 64; k0 += 16) {
            uint32_t af[4][4], bf[4][2];
#pragma unroll
            for (int mi = 0; mi < 4; mi++) {
                int arow = wm + mi * 16 + (grp & 1) * 8 + rl;
                int acol = k0 + (grp >> 1) * 8;
                ldsm_x4(af[mi][0], af[mi][1], af[mi][2], af[mi][3],
                        aBase + (arow * GP + acol) * 2);
            }
#pragma unroll
            for (int ni = 0; ni < 4; ni++) {
                int brow = wn + ni * 8 + rl;
                int bcol = k0 + (grp & 1) * 8;
                ldsm_x2(bf[ni][0], bf[ni][1], bBase + (brow * GP + bcol) * 2);
            }
#pragma unroll
            for (int mi = 0; mi < 4; mi++)
#pragma unroll
                for (int ni = 0; ni < 4; ni++)
                    mma_f16(c[mi][ni], af[mi][0], af[mi][1], af[mi][2], af[mi][3],
                            bf[ni][0], bf[ni][1]);
        }
    }
    __syncthreads();

    float* stag = (float*)smem;
    bool diag = (bx == by);
    int qr = lane >> 2, qc = 2 * (lane & 3);
#pragma unroll
    for (int mi = 0; mi < 4; mi++) {
#pragma unroll
        for (int ni = 0; ni < 4; ni++) {
#pragma unroll
            for (int half = 0; half < 2; half++) {
                int row = wm + mi * 16 + qr + half * 8;
                int col = wn + ni * 8 + qc;
                float v0 = 1.f / (1.f + __expf(-c[mi][ni][2 * half]));
                float v1 = 1.f / (1.f + __expf(-c[mi][ni][2 * half + 1]));
                int r = row0 + row, cc = col0 + col;
                if (r < NN && cc < NN)
                    *(float2*)(out + (size_t)r * NN + cc) = make_float2(v0, v1);
                if (!diag) {
                    int s = row & 31;
                    stag[row * 128 + (col ^ s)] = v0;
                    stag[row * 128 + ((col + 1) ^ s)] = v1;
                }
            }
        }
    }
    if (diag) return;
    __syncthreads();

    // mirror: warp per column, 128B coalesced stores
    for (int cc = warp; cc < 128; cc += 8) {
        int cgl = col0 + cc;
        if (cgl >= NN) continue;
        float* mrow = out + (size_t)cgl * NN + row0;
#pragma unroll
        for (int ib = 0; ib < 128; ib += 32) {
            int i = ib + lane;
            if (row0 + i < NN)
                mrow[i] = stag[i * 128 + (cc ^ (i & 31))];
        }
    }
}

// ---------------- launch ----------------
extern "C" void kernel_launch(void* const* d_in, const int* in_sizes, int n_in,
                              void* d_out, int out_size) {
    const float* x   = (const float*)d_in[0];
    const int*   ei  = (const int*)  d_in[1];
    const float* eps = (const float*)d_in[2];
    const float* w1l = (const float*)d_in[3];
    const float* b1l = (const float*)d_in[4];
    const float* w1r = (const float*)d_in[5];
    const float* b1r = (const float*)d_in[6];
    const float* a1  = (const float*)d_in[7];
    const float* bias1 = (const float*)d_in[8];
    const float* bn1_g = (const float*)d_in[9];
    const float* bn1_b = (const float*)d_in[10];
    const float* w2l = (const float*)d_in[11];
    const float* b2l = (const float*)d_in[12];
    const float* w2r = (const float*)d_in[13];
    const float* b2r = (const float*)d_in[14];
    const float* a2  = (const float*)d_in[15];
    const float* bias2 = (const float*)d_in[16];
    const float* w3l = (const float*)d_in[17];
    const float* b3l = (const float*)d_in[18];
    const float* w3r = (const float*)d_in[19];
    const float* b3r = (const float*)d_in[20];
    const float* a3  = (const float*)d_in[21];
    const float* bias3 = (const float*)d_in[22];
    const float* dw1 = (const float*)d_in[23];
    const float* db1 = (const float*)d_in[24];
    const float* dbn_g = (const float*)d_in[25];
    const float* dbn_b = (const float*)d_in[26];
    const float* dw2 = (const float*)d_in[27];
    const float* db2 = (const float*)d_in[28];
    float* out = (float*)d_out;

    float *p_xl1, *p_xr1, *p_h, *p_x23, *p_d, *p_b23;
    cudaGetSymbolAddress((void**)&p_xl1, g_xl1);
    cudaGetSymbolAddress((void**)&p_xr1, g_xr1);
    cudaGetSymbolAddress((void**)&p_h,   g_h);
    cudaGetSymbolAddress((void**)&p_x23, g_x23);
    cudaGetSymbolAddress((void**)&p_d,   g_d);
    cudaGetSymbolAddress((void**)&p_b23, g_bias23);
    uint16_t *p_w1lh, *p_w1ll, *p_w1rh, *p_w1rl, *p_w23h, *p_w23l;
    uint16_t *p_dw1h, *p_dw1l, *p_dw2h, *p_dw2l, *p_ebh, *p_ebl;
    cudaGetSymbolAddress((void**)&p_w1lh, g_w1lh);
    cudaGetSymbolAddress((void**)&p_w1ll, g_w1ll);
    cudaGetSymbolAddress((void**)&p_w1rh, g_w1rh);
    cudaGetSymbolAddress((void**)&p_w1rl, g_w1rl);
    cudaGetSymbolAddress((void**)&p_w23h, g_w23h);
    cudaGetSymbolAddress((void**)&p_w23l, g_w23l);
    cudaGetSymbolAddress((void**)&p_dw1h, g_dw1h);
    cudaGetSymbolAddress((void**)&p_dw1l, g_dw1l);
    cudaGetSymbolAddress((void**)&p_dw2h, g_dw2h);
    cudaGetSymbolAddress((void**)&p_dw2l, g_dw2l);
    cudaGetSymbolAddress((void**)&p_ebh,  g_ebh);
    cudaGetSymbolAddress((void**)&p_ebl,  g_ebl);

    cudaFuncSetAttribute(gram_hmma, cudaFuncAttributeMaxDynamicSharedMemorySize, G_SMEM);

    static cudaStream_t s_side = nullptr;
    static cudaEvent_t evA = nullptr, evB = nullptr, evC = nullptr, evD = nullptr;
    if (!s_side) {
        cudaStreamCreateWithFlags(&s_side, cudaStreamNonBlocking);
        cudaEventCreateWithFlags(&evA, cudaEventDisableTiming);
        cudaEventCreateWithFlags(&evB, cudaEventDisableTiming);
        cudaEventCreateWithFlags(&evC, cudaEventDisableTiming);
        cudaEventCreateWithFlags(&evD, cudaEventDisableTiming);
    }

    const int MT  = (NN + 127) / 128;   // 79
    const int MT64 = (NN + 63) / 64;    // 157

    // ---- fork: CSR build on side stream ----
    cudaEventRecord(evA, 0);
    cudaStreamWaitEvent(s_side, evA, 0);
    k_zero_counts<<<(NN + 255) / 256, 256, 0, s_side>>>();
    k_count_deg<<<(NE + 255) / 256, 256, 0, s_side>>>(ei);
    k_scan_deg<<<1, 1024, 0, s_side>>>();
    k_fill_list<<<(NE + 255) / 256, 256, 0, s_side>>>(ei);
    cudaEventRecord(evB, s_side);

    // ---- main: weight splits + bias pack + layer-1 HMMA GEMM ----
    k_wsplit<<<(NFEAT * H1 + 255) / 256, 256>>>(w1l, p_w1lh, p_w1ll, NFEAT, H1);
    k_wsplit<<<(NFEAT * H1 + 255) / 256, 256>>>(w1r, p_w1rh, p_w1rl, NFEAT, H1);
    k_wsplit4<<<(256 * H1 + 255) / 256, 256>>>(w2l, w2r, w3l, w3r, p_w23h, p_w23l);
    k_wsplit<<<(NHID1 * NHID2 + 255) / 256, 256>>>(dw1, p_dw1h, p_dw1l, NHID2, NHID1);
    k_wsplit<<<(NHID1 * NFEAT + 255) / 256, 256>>>(dw2, p_dw2h, p_dw2l, NHID1, NFEAT);
    k_pack_bias<<<1, 256>>>(b2l, b2r, b3l, b3r);
    {
        TJobs j1 = {{ { p_w1lh, p_w1ll, b1l, p_xl1 }, { p_w1rh, p_w1rl, b1r, p_xr1 } }};
        gemmT64<<<dim3(1, MT64, 2), 256>>>(x, j1, NN, NFEAT, H1, nullptr, nullptr);
    }
    cudaStreamWaitEvent(0, evB, 0);   // join CSR

    // ---- GAT layer 1 -> BN stats (apply fused into next GEMM) ----
    {
        AJobs aj = {{ { p_xl1, p_xr1, H1, a1, bias1, p_h, H1 }, {} }};
        gat_agg<H1><<<dim3(NN, 1), H1>>>(aj);
    }
    bn_stats<H1><<<H1, 256>>>(p_h);

    // ---- layers 2 & 3 packed GEMM (BN+ReLU fused on A) ----
    {
        TJobs j2 = {{ { p_w23h, p_w23l, p_b23, p_x23 }, {} }};
        gemmT<<<dim3(2, MT, 1), 256>>>(p_h, j2, NN, H1, 256, bn1_g, bn1_b);
    }

    // ---- GAT layers 2 (mu) and 3 (logvar) ----
    {
        AJobs aj = {{ { p_x23 + 0,   p_x23 + 64,  256, a2, bias2, out + MU_OFF, 64 },
                      { p_x23 + 128, p_x23 + 192, 256, a3, bias3, out + LV_OFF, 64 } }};
        gat_agg<NHID2><<<dim3(NN, 2), NHID2>>>(aj);
    }

    // ---- reparameterize + fp16 pre-split ----
    k_reparam<<<(NN * NHID2 + 255) / 256, 256>>>(eps, out);

    // ---- fork: decoder MLP on side stream, gram on main ----
    cudaEventRecord(evC, 0);
    cudaStreamWaitEvent(s_side, evC, 0);
    {
        TJobs jd = {{ { p_dw1h, p_dw1l, db1, p_d }, {} }};
        gemmT<<<dim3(2, MT, 1), 256, 0, s_side>>>(out + EMB_OFF, jd, NN, NHID2, NHID1,
                                                  nullptr, nullptr);
    }
    bn_stats<NHID1><<<NHID1, 256, 0, s_side>>>(p_d);
    {
        TJobs jd = {{ { p_dw2h, p_dw2l, db2, out + REX_OFF }, {} }};
        gemmT<<<dim3(4, MT, 1), 256, 0, s_side>>>(p_d, jd, NN, NHID1, NFEAT,
                                                  dbn_g, dbn_b);
    }
    cudaEventRecord(evD, s_side);

    gram_hmma<<<dim3(MT, MT), 256, G_SMEM>>>(p_ebh, p_ebl, out + READJ_OFF);

    cudaStreamWaitEvent(0, evD, 0);   // join decoder
}

// round 10
// speedup vs baseline: 1.9025x; 1.0924x over previous
#include <cuda_runtime.h>
#include <cuda_fp16.h>
#include <cstdint>
#include <math.h>

#define NN     10000
#define EE     320000
#define NE     (EE + NN)     // with self loops
#define NFEAT  512
#define NHID1  256
#define NHID2  64
#define H1     128           // 2*nhid2
#define NEG_SLOPE 0.2f
#define BN_EPS 1e-5f
#define MAXDEG 512

// output layout (flattened tuple: emb, re_x, readj, mu, logvar)
#define EMB_OFF   ((size_t)0)
#define REX_OFF   ((size_t)NN * NHID2)
#define READJ_OFF (REX_OFF + (size_t)NN * NFEAT)
#define MU_OFF    (READJ_OFF + (size_t)NN * NN)
#define LV_OFF    (MU_OFF + (size_t)NN * NHID2)

typedef unsigned long long u64;

// ---------------- warp MMA helpers (baseline PTX, works on sm_103) --------
__device__ __forceinline__ uint32_t smem_u32(const void* p) {
    uint32_t a;
    asm("{ .reg .u64 t; cvta.to.shared.u64 t, %1; cvt.u32.u64 %0, t; }" : "=r"(a) : "l"(p));
    return a;
}
__device__ __forceinline__ void ldsm_x4(uint32_t& r0, uint32_t& r1, uint32_t& r2, uint32_t& r3, uint32_t addr) {
    asm volatile("ldmatrix.sync.aligned.m8n8.x4.shared.b16 {%0,%1,%2,%3}, [%4];"
                 : "=r"(r0), "=r"(r1), "=r"(r2), "=r"(r3) : "r"(addr));
}
__device__ __forceinline__ void ldsm_x2(uint32_t& r0, uint32_t& r1, uint32_t addr) {
    asm volatile("ldmatrix.sync.aligned.m8n8.x2.shared.b16 {%0,%1}, [%2];"
                 : "=r"(r0), "=r"(r1) : "r"(addr));
}
__device__ __forceinline__ void mma_f16(float* d, uint32_t a0, uint32_t a1, uint32_t a2, uint32_t a3,
                                        uint32_t b0, uint32_t b1) {
    asm volatile("mma.sync.aligned.m16n8k16.row.col.f32.f16.f16.f32 "
                 "{%0,%1,%2,%3}, {%4,%5,%6,%7}, {%8,%9}, {%0,%1,%2,%3};"
                 : "+f"(d[0]), "+f"(d[1]), "+f"(d[2]), "+f"(d[3])
                 : "r"(a0), "r"(a1), "r"(a2), "r"(a3), "r"(b0), "r"(b1));
}
__device__ __forceinline__ void f16split(float v, uint16_t& h, uint16_t& l) {
    __half hb = __float2half_rn(v);
    __half lb = __float2half_rn(v - __half2float(hb));
    h = __half_as_ushort(hb);
    l = __half_as_ushort(lb);
}

// ---------------- scratch (device globals; no allocation allowed) ----------
__device__ float g_xl1[NN * H1];
__device__ float g_xr1[NN * H1];
__device__ float g_h  [NN * H1];
__device__ float g_x23[NN * 256];        // packed: xl2|xr2|xl3|xr3 (64 each)
__device__ float g_d  [NN * NHID1];
__device__ int   g_deg[NN];
__device__ int   g_rowptr[NN + 1];
__device__ int   g_cursor[NN];
__device__ int   g_srclist[NE];
__device__ float g_mean[NHID1];
__device__ float g_rstd[NHID1];
__device__ float g_bias23[256];
// emb fp16 hi/lo (pre-split for gram)
__device__ uint16_t g_ebh[NN * NHID2], g_ebl[NN * NHID2];
// transposed fp16 weights [Nc][K] (hi only; A-side carries the residual)
__device__ uint16_t g_w1lh[H1 * NFEAT];
__device__ uint16_t g_w1rh[H1 * NFEAT];
__device__ uint16_t g_w23h[256 * H1];
__device__ uint16_t g_dw1h[NHID1 * NHID2];
__device__ uint16_t g_dw2h[NFEAT * NHID1];

// ---------------- CSR build ----------------
__global__ void k_zero_counts() {
    int i = blockIdx.x * blockDim.x + threadIdx.x;
    if (i < NN) { g_deg[i] = 0; g_cursor[i] = 0; }
}

__global__ void k_count_deg(const int* __restrict__ edge_index) {
    int i = blockIdx.x * blockDim.x + threadIdx.x;
    if (i >= NE) return;
    int tgt = (i < EE) ? edge_index[EE + i] : (i - EE);
    atomicAdd(&g_deg[tgt], 1);
}

__global__ void k_scan_deg() {
    __shared__ int wsum[32];
    __shared__ int sc;
    int tid = threadIdx.x, lane = tid & 31, w = tid >> 5;
    if (tid == 0) { sc = 0; g_rowptr[0] = 0; }
    __syncthreads();
    for (int base = 0; base < NN; base += 1024) {
        int i = base + tid;
        int v = (i < NN) ? g_deg[i] : 0;
        int x = v;
#pragma unroll
        for (int o = 1; o < 32; o <<= 1) {
            int t = __shfl_up_sync(0xffffffffu, x, o);
            if (lane >= o) x += t;
        }
        if (lane == 31) wsum[w] = x;
        __syncthreads();
        if (w == 0) {
            int y = wsum[lane];
#pragma unroll
            for (int o = 1; o < 32; o <<= 1) {
                int t = __shfl_up_sync(0xffffffffu, y, o);
                if (lane >= o) y += t;
            }
            wsum[lane] = y;
        }
        __syncthreads();
        int pre = (w > 0) ? wsum[w - 1] : 0;
        int c = sc;
        if (i < NN) g_rowptr[i + 1] = c + pre + x;
        int total = wsum[31];
        __syncthreads();
        if (tid == 0) sc = c + total;
        __syncthreads();
    }
}

__global__ void k_fill_list(const int* __restrict__ edge_index) {
    int i = blockIdx.x * blockDim.x + threadIdx.x;
    if (i >= NE) return;
    int src, tgt;
    if (i < EE) { src = edge_index[i]; tgt = edge_index[EE + i]; }
    else        { src = i - EE;        tgt = i - EE; }
    int pos = atomicAdd(&g_cursor[tgt], 1);
    g_srclist[g_rowptr[tgt] + pos] = src;
}

// ---------------- weight transpose + fp16 convert ----------------
__global__ void k_wsplit(const float* __restrict__ W, uint16_t* __restrict__ hi,
                         int K, int Nc) {
    int i = blockIdx.x * blockDim.x + threadIdx.x;
    if (i >= K * Nc) return;
    int n = i / K, k = i - n * K;
    hi[i] = __half_as_ushort(__float2half_rn(W[(size_t)k * Nc + n]));
}
__global__ void k_wsplit4(const float* __restrict__ W0, const float* __restrict__ W1,
                          const float* __restrict__ W2, const float* __restrict__ W3,
                          uint16_t* __restrict__ hi) {
    int i = blockIdx.x * blockDim.x + threadIdx.x;
    if (i >= 256 * H1) return;
    int np = i >> 7, k = i & 127;
    int jj = np >> 6, n = np & 63;
    const float* W = (jj == 0) ? W0 : (jj == 1) ? W1 : (jj == 2) ? W2 : W3;
    hi[i] = __half_as_ushort(__float2half_rn(W[(size_t)k * 64 + n]));
}
__global__ void k_pack_bias(const float* __restrict__ b0, const float* __restrict__ b1,
                            const float* __restrict__ b2, const float* __restrict__ b3) {
    int i = threadIdx.x;            // 256 threads
    int jj = i >> 6, n = i & 63;
    const float* b = (jj == 0) ? b0 : (jj == 1) ? b1 : (jj == 2) ? b2 : b3;
    g_bias23[i] = b[n];
}

// ---------------- GEMM job plumbing ----------------
struct TJob  { const uint16_t* Bh; const float* bias; float* C; };
struct TJobs { TJob j[2]; };

// ---------------- gemmT: fp16 2-pass HMMA GEMM, 128x128 tile -------------
// A fp32 [M,K] split to fp16 hi/lo per tile (opt. fused BN+ReLU), B fp16 [Nc][K].
__global__ __launch_bounds__(256)
void gemmT(const float* __restrict__ A, TJobs jobs, int M, int K, int Nc,
           const float* __restrict__ bnG, const float* __restrict__ bnB) {
    const TJob jb = jobs.j[blockIdx.z];
    __shared__ __align__(16) uint16_t Ah[128][40], Al[128][40];
    __shared__ __align__(16) uint16_t Bh[128][40];
    int tid = threadIdx.x, lane = tid & 31, warp = tid >> 5;
    int row0 = blockIdx.y * 128, col0 = blockIdx.x * 128;
    int wm = (warp & 1) * 64, wn = (warp >> 1) * 32;
    int grp = lane >> 3, rl = lane & 7;
    float c[4][4][4];
#pragma unroll
    for (int mi = 0; mi < 4; mi++)
#pragma unroll
        for (int ni = 0; ni < 4; ni++)
#pragma unroll
            for (int e = 0; e < 4; e++) c[mi][ni][e] = 0.f;

    int ar = tid >> 1, kh = (tid & 1) * 16;
    int r = row0 + ar;
    bool va = r < M;

    for (int k0 = 0; k0 < K; k0 += 32) {
        const float* pa = A + (size_t)r * K + k0 + kh;
#pragma unroll
        for (int q = 0; q < 4; q++) {
            float4 v = va ? *(const float4*)(pa + q * 4) : make_float4(0.f, 0.f, 0.f, 0.f);
            if (bnG) {
                int ch = k0 + kh + q * 4;
                float4 mm = *(const float4*)(g_mean + ch);
                float4 rs = *(const float4*)(g_rstd + ch);
                float4 gg = *(const float4*)(bnG + ch);
                float4 bb = *(const float4*)(bnB + ch);
                v.x = fmaxf((v.x - mm.x) * rs.x * gg.x + bb.x, 0.f);
                v.y = fmaxf((v.y - mm.y) * rs.y * gg.y + bb.y, 0.f);
                v.z = fmaxf((v.z - mm.z) * rs.z * gg.z + bb.z, 0.f);
                v.w = fmaxf((v.w - mm.w) * rs.w * gg.w + bb.w, 0.f);
            }
            uint16_t h0, l0, h1, l1, h2, l2, h3, l3;
            f16split(v.x, h0, l0); f16split(v.y, h1, l1);
            f16split(v.z, h2, l2); f16split(v.w, h3, l3);
            *(uint32_t*)&Ah[ar][kh + q * 4]     = (uint32_t)h0 | ((uint32_t)h1 << 16);
            *(uint32_t*)&Ah[ar][kh + q * 4 + 2] = (uint32_t)h2 | ((uint32_t)h3 << 16);
            *(uint32_t*)&Al[ar][kh + q * 4]     = (uint32_t)l0 | ((uint32_t)l1 << 16);
            *(uint32_t*)&Al[ar][kh + q * 4 + 2] = (uint32_t)l2 | ((uint32_t)l3 << 16);
        }
        {
            const uint16_t* pbh = jb.Bh + (size_t)(col0 + ar) * K + k0 + kh;
            *(uint4*)&Bh[ar][kh]     = *(const uint4*)pbh;
            *(uint4*)&Bh[ar][kh + 8] = *(const uint4*)(pbh + 8);
        }
        __syncthreads();
#pragma unroll
        for (int pass = 0; pass < 2; pass++) {
            const uint16_t (*Aq)[40] = (pass == 1) ? Al : Ah;
#pragma unroll
            for (int k1 = 0; k1 < 32; k1 += 16) {
                uint32_t af[4][4], bf[4][2];
#pragma unroll
                for (int mi = 0; mi < 4; mi++) {
                    int arow = wm + mi * 16 + (grp & 1) * 8 + rl;
                    int acol = k1 + (grp >> 1) * 8;
                    ldsm_x4(af[mi][0], af[mi][1], af[mi][2], af[mi][3],
                            smem_u32(&Aq[arow][acol]));
                }
#pragma unroll
                for (int ni = 0; ni < 4; ni++) {
                    int brow = wn + ni * 8 + rl;
                    int bcol = k1 + (grp & 1) * 8;
                    ldsm_x2(bf[ni][0], bf[ni][1], smem_u32(&Bh[brow][bcol]));
                }
#pragma unroll
                for (int mi = 0; mi < 4; mi++)
#pragma unroll
                    for (int ni = 0; ni < 4; ni++)
                        mma_f16(c[mi][ni], af[mi][0], af[mi][1], af[mi][2], af[mi][3],
                                bf[ni][0], bf[ni][1]);
            }
        }
        __syncthreads();
    }
    int qr = lane >> 2, qc = 2 * (lane & 3);
#pragma unroll
    for (int mi = 0; mi < 4; mi++) {
#pragma unroll
        for (int half = 0; half < 2; half++) {
            int row = wm + mi * 16 + qr + half * 8;
            int rr = row0 + row;
            if (rr < M) {
                float* Crow = jb.C + (size_t)rr * Nc;
#pragma unroll
                for (int ni = 0; ni < 4; ni++) {
                    int cc = col0 + wn + ni * 8 + qc;
                    float2 p;
                    p.x = c[mi][ni][2 * half]     + __ldg(&jb.bias[cc]);
                    p.y = c[mi][ni][2 * half + 1] + __ldg(&jb.bias[cc + 1]);
                    *(float2*)&Crow[cc] = p;
                }
            }
        }
    }
}

// ---------------- gemmT64: same, 64x128 tile (better wave balance) --------
__global__ __launch_bounds__(256)
void gemmT64(const float* __restrict__ A, TJobs jobs, int M, int K, int Nc,
             const float* __restrict__ bnG, const float* __restrict__ bnB) {
    const TJob jb = jobs.j[blockIdx.z];
    __shared__ __align__(16) uint16_t Ah[64][40], Al[64][40];
    __shared__ __align__(16) uint16_t Bh[128][40];
    int tid = threadIdx.x, lane = tid & 31, warp = tid >> 5;
    int row0 = blockIdx.y * 64, col0 = blockIdx.x * 128;
    int wm = (warp & 1) * 32, wn = (warp >> 1) * 32;
    int grp = lane >> 3, rl = lane & 7;
    float c[2][4][4];
#pragma unroll
    for (int mi = 0; mi < 2; mi++)
#pragma unroll
        for (int ni = 0; ni < 4; ni++)
#pragma unroll
            for (int e = 0; e < 4; e++) c[mi][ni][e] = 0.f;

    int ar = tid >> 2, ks = (tid & 3) * 8;
    int br = tid >> 1, kb = (tid & 1) * 16;
    int r = row0 + ar;
    bool va = r < M;

    for (int k0 = 0; k0 < K; k0 += 32) {
        const float* pa = A + (size_t)r * K + k0 + ks;
#pragma unroll
        for (int q = 0; q < 2; q++) {
            float4 v = va ? *(const float4*)(pa + q * 4) : make_float4(0.f, 0.f, 0.f, 0.f);
            if (bnG) {
                int ch = k0 + ks + q * 4;
                float4 mm = *(const float4*)(g_mean + ch);
                float4 rs = *(const float4*)(g_rstd + ch);
                float4 gg = *(const float4*)(bnG + ch);
                float4 bb = *(const float4*)(bnB + ch);
                v.x = fmaxf((v.x - mm.x) * rs.x * gg.x + bb.x, 0.f);
                v.y = fmaxf((v.y - mm.y) * rs.y * gg.y + bb.y, 0.f);
                v.z = fmaxf((v.z - mm.z) * rs.z * gg.z + bb.z, 0.f);
                v.w = fmaxf((v.w - mm.w) * rs.w * gg.w + bb.w, 0.f);
            }
            uint16_t h0, l0, h1, l1, h2, l2, h3, l3;
            f16split(v.x, h0, l0); f16split(v.y, h1, l1);
            f16split(v.z, h2, l2); f16split(v.w, h3, l3);
            *(uint32_t*)&Ah[ar][ks + q * 4]     = (uint32_t)h0 | ((uint32_t)h1 << 16);
            *(uint32_t*)&Ah[ar][ks + q * 4 + 2] = (uint32_t)h2 | ((uint32_t)h3 << 16);
            *(uint32_t*)&Al[ar][ks + q * 4]     = (uint32_t)l0 | ((uint32_t)l1 << 16);
            *(uint32_t*)&Al[ar][ks + q * 4 + 2] = (uint32_t)l2 | ((uint32_t)l3 << 16);
        }
        {
            const uint16_t* pbh = jb.Bh + (size_t)(col0 + br) * K + k0 + kb;
            *(uint4*)&Bh[br][kb]     = *(const uint4*)pbh;
            *(uint4*)&Bh[br][kb + 8] = *(const uint4*)(pbh + 8);
        }
        __syncthreads();
#pragma unroll
        for (int pass = 0; pass < 2; pass++) {
            const uint16_t (*Aq)[40] = (pass == 1) ? Al : Ah;
#pragma unroll
            for (int k1 = 0; k1 < 32; k1 += 16) {
                uint32_t af[2][4], bf[4][2];
#pragma unroll
                for (int mi = 0; mi < 2; mi++) {
                    int arow = wm + mi * 16 + (grp & 1) * 8 + rl;
                    int acol = k1 + (grp >> 1) * 8;
                    ldsm_x4(af[mi][0], af[mi][1], af[mi][2], af[mi][3],
                            smem_u32(&Aq[arow][acol]));
                }
#pragma unroll
                for (int ni = 0; ni < 4; ni++) {
                    int brow = wn + ni * 8 + rl;
                    int bcol = k1 + (grp & 1) * 8;
                    ldsm_x2(bf[ni][0], bf[ni][1], smem_u32(&Bh[brow][bcol]));
                }
#pragma unroll
                for (int mi = 0; mi < 2; mi++)
#pragma unroll
                    for (int ni = 0; ni < 4; ni++)
                        mma_f16(c[mi][ni], af[mi][0], af[mi][1], af[mi][2], af[mi][3],
                                bf[ni][0], bf[ni][1]);
            }
        }
        __syncthreads();
    }
    int qr = lane >> 2, qc = 2 * (lane & 3);
#pragma unroll
    for (int mi = 0; mi < 2; mi++) {
#pragma unroll
        for (int half = 0; half < 2; half++) {
            int row = wm + mi * 16 + qr + half * 8;
            int rr = row0 + row;
            if (rr < M) {
                float* Crow = jb.C + (size_t)rr * Nc;
#pragma unroll
                for (int ni = 0; ni < 4; ni++) {
                    int cc = col0 + wn + ni * 8 + qc;
                    float2 p;
                    p.x = c[mi][ni][2 * half]     + __ldg(&jb.bias[cc]);
                    p.y = c[mi][ni][2 * half + 1] + __ldg(&jb.bias[cc + 1]);
                    *(float2*)&Crow[cc] = p;
                }
            }
        }
    }
}

// ---------------- GATv2 aggregation (one block per target node) -----------
struct AJob  { const float* xl; const float* xr; int ld; const float* att;
               const float* bias; float* out; int ldo; };
struct AJobs { AJob j[2]; };

template <int C>
__device__ __forceinline__ float gat_score(const float* xs, float4 xr4, float4 at4, int lane) {
    float p = 0.f;
    if (lane < C / 4) {
        float4 v = *(const float4*)(xs + lane * 4);
        float a = v.x + xr4.x; a = fmaxf(a, NEG_SLOPE * a);
        float b = v.y + xr4.y; b = fmaxf(b, NEG_SLOPE * b);
        float c = v.z + xr4.z; c = fmaxf(c, NEG_SLOPE * c);
        float d = v.w + xr4.w; d = fmaxf(d, NEG_SLOPE * d);
        p = at4.x * a + at4.y * b + at4.z * c + at4.w * d;
    }
    return p;
}

template <int C>
__global__ void gat_agg(AJobs jobs) {
    constexpr int W  = C / 32;
    constexpr int NL = C / 4;
    const AJob jb = jobs.j[blockIdx.y];
    int t = blockIdx.x;
    int tid = threadIdx.x, lane = tid & 31, warp = tid >> 5;
    __shared__ float4 s_xr4[NL], s_att4[NL];
    __shared__ float  s_e[MAXDEG];
    __shared__ int    s_src[MAXDEG];
    __shared__ float  s_red[W];
    __shared__ float4 s_part[W][NL];
    if (tid < NL) {
        s_xr4[tid]  = *(const float4*)(jb.xr + (size_t)t * jb.ld + tid * 4);
        s_att4[tid] = *(const float4*)(jb.att + tid * 4);
    }
    int beg = g_rowptr[t];
    int deg = g_rowptr[t + 1] - beg;
    __syncthreads();

    float4 xr4 = make_float4(0.f, 0.f, 0.f, 0.f);
    float4 at4 = xr4;
    if (lane < NL) { xr4 = s_xr4[lane]; at4 = s_att4[lane]; }
    const float* xl = jb.xl;
    int ld = jb.ld;

    // pass A: scores, 4 edges in flight per warp
    int j = warp;
    for (; j + 3 * W < deg; j += 4 * W) {
        int s0 = g_srclist[beg + j];
        int s1 = g_srclist[beg + j + W];
        int s2 = g_srclist[beg + j + 2 * W];
        int s3 = g_srclist[beg + j + 3 * W];
        float p0 = gat_score<C>(xl + (size_t)s0 * ld, xr4, at4, lane);
        float p1 = gat_score<C>(xl + (size_t)s1 * ld, xr4, at4, lane);
        float p2 = gat_score<C>(xl + (size_t)s2 * ld, xr4, at4, lane);
        float p3 = gat_score<C>(xl + (size_t)s3 * ld, xr4, at4, lane);
#pragma unroll
        for (int o = 16; o; o >>= 1) {
            p0 += __shfl_xor_sync(0xffffffffu, p0, o);
            p1 += __shfl_xor_sync(0xffffffffu, p1, o);
            p2 += __shfl_xor_sync(0xffffffffu, p2, o);
            p3 += __shfl_xor_sync(0xffffffffu, p3, o);
        }
        if (lane == 0) {
            s_e[j] = p0;         s_src[j] = s0;
            s_e[j + W] = p1;     s_src[j + W] = s1;
            s_e[j + 2 * W] = p2; s_src[j + 2 * W] = s2;
            s_e[j + 3 * W] = p3; s_src[j + 3 * W] = s3;
        }
    }
    for (; j < deg; j += W) {
        int s0 = g_srclist[beg + j];
        float p0 = gat_score<C>(xl + (size_t)s0 * ld, xr4, at4, lane);
#pragma unroll
        for (int o = 16; o; o >>= 1) p0 += __shfl_xor_sync(0xffffffffu, p0, o);
        if (lane == 0) { s_e[j] = p0; s_src[j] = s0; }
    }
    __syncthreads();

    float m = -1e30f;
    for (int q = tid; q < deg; q += C) m = fmaxf(m, s_e[q]);
#pragma unroll
    for (int o = 16; o; o >>= 1) m = fmaxf(m, __shfl_xor_sync(0xffffffffu, m, o));
    if (lane == 0) s_red[warp] = m;
    __syncthreads();
    m = s_red[0];
#pragma unroll
    for (int w = 1; w < W; w++) m = fmaxf(m, s_red[w]);
    __syncthreads();

    float ssum = 0.f;
    for (int q = tid; q < deg; q += C) {
        float wj = __expf(s_e[q] - m);
        s_e[q] = wj;
        ssum += wj;
    }
#pragma unroll
    for (int o = 16; o; o >>= 1) ssum += __shfl_xor_sync(0xffffffffu, ssum, o);
    if (lane == 0) s_red[warp] = ssum;
    __syncthreads();
    ssum = 0.f;
#pragma unroll
    for (int w = 0; w < W; w++) ssum += s_red[w];
    float inv = 1.f / ssum;

    // pass B: weighted aggregation, 4 edges in flight
    float4 f0 = make_float4(0.f, 0.f, 0.f, 0.f);
    float4 f1 = f0, f2 = f0, f3 = f0;
    if (lane < NL) {
        int q = warp;
        for (; q + 3 * W < deg; q += 4 * W) {
            float w0 = s_e[q], w1 = s_e[q + W], w2 = s_e[q + 2 * W], w3 = s_e[q + 3 * W];
            float4 v0 = *(const float4*)(xl + (size_t)s_src[q] * ld + lane * 4);
            float4 v1 = *(const float4*)(xl + (size_t)s_src[q + W] * ld + lane * 4);
            float4 v2 = *(const float4*)(xl + (size_t)s_src[q + 2 * W] * ld + lane * 4);
            float4 v3 = *(const float4*)(xl + (size_t)s_src[q + 3 * W] * ld + lane * 4);
            f0.x += w0 * v0.x; f0.y += w0 * v0.y; f0.z += w0 * v0.z; f0.w += w0 * v0.w;
            f1.x += w1 * v1.x; f1.y += w1 * v1.y; f1.z += w1 * v1.z; f1.w += w1 * v1.w;
            f2.x += w2 * v2.x; f2.y += w2 * v2.y; f2.z += w2 * v2.z; f2.w += w2 * v2.w;
            f3.x += w3 * v3.x; f3.y += w3 * v3.y; f3.z += w3 * v3.z; f3.w += w3 * v3.w;
        }
        for (; q < deg; q += W) {
            float w0 = s_e[q];
            float4 v0 = *(const float4*)(xl + (size_t)s_src[q] * ld + lane * 4);
            f0.x += w0 * v0.x; f0.y += w0 * v0.y; f0.z += w0 * v0.z; f0.w += w0 * v0.w;
        }
        f0.x += f1.x + f2.x + f3.x;
        f0.y += f1.y + f2.y + f3.y;
        f0.z += f1.z + f2.z + f3.z;
        f0.w += f1.w + f2.w + f3.w;
        s_part[warp][lane] = f0;
    }
    __syncthreads();
    if (warp == 0 && lane < NL) {
        float4 tt = s_part[0][lane];
#pragma unroll
        for (int w = 1; w < W; w++) {
            float4 q4 = s_part[w][lane];
            tt.x += q4.x; tt.y += q4.y; tt.z += q4.z; tt.w += q4.w;
        }
        float4 b4 = *(const float4*)(jb.bias + lane * 4);
        float4 o4;
        o4.x = tt.x * inv + b4.x;
        o4.y = tt.y * inv + b4.y;
        o4.z = tt.z * inv + b4.z;
        o4.w = tt.w * inv + b4.w;
        *(float4*)(jb.out + (size_t)t * jb.ldo + lane * 4) = o4;
    }
}

// ---------------- batch norm stats ----------------
template <int C>
__global__ void bn_stats(const float* __restrict__ h) {
    int c = blockIdx.x;
    int tid = threadIdx.x;
    float s = 0.f, s2 = 0.f;
    for (int r = tid; r < NN; r += 256) {
        float v = h[(size_t)r * C + c];
        s += v; s2 += v * v;
    }
    __shared__ float sh[8], sh2[8];
#pragma unroll
    for (int o = 16; o; o >>= 1) {
        s  += __shfl_xor_sync(0xffffffffu, s,  o);
        s2 += __shfl_xor_sync(0xffffffffu, s2, o);
    }
    if ((tid & 31) == 0) { sh[tid >> 5] = s; sh2[tid >> 5] = s2; }
    __syncthreads();
    if (tid == 0) {
        float ts = 0.f, ts2 = 0.f;
        for (int w = 0; w < 8; w++) { ts += sh[w]; ts2 += sh2[w]; }
        float mean = ts / NN;
        float var = ts2 / NN - mean * mean;
        g_mean[c] = mean;
        g_rstd[c] = rsqrtf(var + BN_EPS);
    }
}

// ---------------- reparameterize + fp16 pre-split ----------------
__global__ void k_reparam(const float* __restrict__ eps, float* __restrict__ out) {
    int i = blockIdx.x * blockDim.x + threadIdx.x;
    if (i >= NN * NHID2) return;
    float mu = out[MU_OFF + i];
    float lv = out[LV_OFF + i];
    float e = eps[i] * __expf(lv) + mu;
    out[EMB_OFF + i] = e;
    uint16_t h, l;
    f16split(e, h, l);
    g_ebh[i] = h;
    g_ebl[i] = l;
}

// ---------------- readj = sigmoid(emb @ emb^T), fp16 2-pass HMMA ----------
// triangular-compact grid: 3160 blocks, linear->(by,bx) upper-tri decode
#define GP 72
#define G_AHI 0
#define G_ALO (G_AHI + 128 * GP * 2)
#define G_BHI (G_ALO + 128 * GP * 2)
#define G_SMEM 65536
#define MTG 79

__global__ __launch_bounds__(256)
void gram_hmma(const uint16_t* __restrict__ Eh, const uint16_t* __restrict__ El,
               float* __restrict__ out) {
    // decode linear block id -> upper-triangular (by, bx)
    int bid = blockIdx.x;
    int by = (int)(0.5f * (2.f * MTG + 1.f) -
                   sqrtf((2.f * MTG + 1.f) * (2.f * MTG + 1.f) * 0.25f - 2.f * (float)bid));
    if (by < 0) by = 0;
    if (by > MTG - 1) by = MTG - 1;
    int start = by * MTG - (by * (by - 1)) / 2;
    while (start > bid) { by--; start = by * MTG - (by * (by - 1)) / 2; }
    while (bid >= start + (MTG - by)) { by++; start = by * MTG - (by * (by - 1)) / 2; }
    int bx = by + (bid - start);

    extern __shared__ __align__(16) char smem[];
    uint32_t sb = smem_u32(smem);
    int tid = threadIdx.x, lane = tid & 31, warp = tid >> 5;
    int row0 = by * 128, col0 = bx * 128;

    {
        int rrow = tid & 127;
        uint4 z = make_uint4(0, 0, 0, 0);
        if (tid < 128) {
            int rA = row0 + rrow;
            bool va = rA < NN;
            const uint4* ph = (const uint4*)(Eh + (size_t)rA * 64);
            const uint4* pl = (const uint4*)(El + (size_t)rA * 64);
#pragma unroll
            for (int q = 0; q < 8; q++) {
                uint32_t off = (rrow * GP + q * 8) * 2;
                *(uint4*)(smem + G_AHI + off) = va ? ph[q] : z;
                *(uint4*)(smem + G_ALO + off) = va ? pl[q] : z;
            }
        } else {
            int rB = col0 + rrow;
            bool vb = rB < NN;
            const uint4* ph = (const uint4*)(Eh + (size_t)rB * 64);
#pragma unroll
            for (int q = 0; q < 8; q++) {
                uint32_t off = (rrow * GP + q * 8) * 2;
                *(uint4*)(smem + G_BHI + off) = vb ? ph[q] : z;
            }
        }
    }
    __syncthreads();

    int wm = (warp & 1) * 64;
    int wn = (warp >> 1) * 32;
    float c[4][4][4];
#pragma unroll
    for (int mi = 0; mi < 4; mi++)
#pragma unroll
        for (int ni = 0; ni < 4; ni++)
#pragma unroll
            for (int e = 0; e < 4; e++) c[mi][ni][e] = 0.f;

    int grp = lane >> 3, rl = lane & 7;
#pragma unroll
    for (int pass = 0; pass < 2; pass++) {
        uint32_t aBase = sb + ((pass == 1) ? G_ALO : G_AHI);
        uint32_t bBase = sb + G_BHI;
#pragma unroll
        for (int k0 = 0; k0 < 64; k0 += 16) {
            uint32_t af[4][4], bf[4][2];
#pragma unroll
            for (int mi = 0; mi < 4; mi++) {
                int arow = wm + mi * 16 + (grp & 1) * 8 + rl;
                int acol = k0 + (grp >> 1) * 8;
                ldsm_x4(af[mi][0], af[mi][1], af[mi][2], af[mi][3],
                        aBase + (arow * GP + acol) * 2);
            }
#pragma unroll
            for (int ni = 0; ni < 4; ni++) {
                int brow = wn + ni * 8 + rl;
                int bcol = k0 + (grp & 1) * 8;
                ldsm_x2(bf[ni][0], bf[ni][1], bBase + (brow * GP + bcol) * 2);
            }
#pragma unroll
            for (int mi = 0; mi < 4; mi++)
#pragma unroll
                for (int ni = 0; ni < 4; ni++)
                    mma_f16(c[mi][ni], af[mi][0], af[mi][1], af[mi][2], af[mi][3],
                            bf[ni][0], bf[ni][1]);
        }
    }
    __syncthreads();

    float* stag = (float*)smem;
    bool diag = (bx == by);
    int qr = lane >> 2, qc = 2 * (lane & 3);
#pragma unroll
    for (int mi = 0; mi < 4; mi++) {
#pragma unroll
        for (int ni = 0; ni < 4; ni++) {
#pragma unroll
            for (int half = 0; half < 2; half++) {
                int row = wm + mi * 16 + qr + half * 8;
                int col = wn + ni * 8 + qc;
                float v0 = 1.f / (1.f + __expf(-c[mi][ni][2 * half]));
                float v1 = 1.f / (1.f + __expf(-c[mi][ni][2 * half + 1]));
                int r = row0 + row, cc = col0 + col;
                if (r < NN && cc < NN)
                    *(float2*)(out + (size_t)r * NN + cc) = make_float2(v0, v1);
                if (!diag) {
                    int s = row & 31;
                    stag[row * 128 + (col ^ s)] = v0;
                    stag[row * 128 + ((col + 1) ^ s)] = v1;
                }
            }
        }
    }
    if (diag) return;
    __syncthreads();

    // mirror: warp per column, 128B coalesced stores
    for (int cc = warp; cc < 128; cc += 8) {
        int cgl = col0 + cc;
        if (cgl >= NN) continue;
        float* mrow = out + (size_t)cgl * NN + row0;
#pragma unroll
        for (int ib = 0; ib < 128; ib += 32) {
            int i = ib + lane;
            if (row0 + i < NN)
                mrow[i] = stag[i * 128 + (cc ^ (i & 31))];
        }
    }
}

// ---------------- launch ----------------
extern "C" void kernel_launch(void* const* d_in, const int* in_sizes, int n_in,
                              void* d_out, int out_size) {
    const float* x   = (const float*)d_in[0];
    const int*   ei  = (const int*)  d_in[1];
    const float* eps = (const float*)d_in[2];
    const float* w1l = (const float*)d_in[3];
    const float* b1l = (const float*)d_in[4];
    const float* w1r = (const float*)d_in[5];
    const float* b1r = (const float*)d_in[6];
    const float* a1  = (const float*)d_in[7];
    const float* bias1 = (const float*)d_in[8];
    const float* bn1_g = (const float*)d_in[9];
    const float* bn1_b = (const float*)d_in[10];
    const float* w2l = (const float*)d_in[11];
    const float* b2l = (const float*)d_in[12];
    const float* w2r = (const float*)d_in[13];
    const float* b2r = (const float*)d_in[14];
    const float* a2  = (const float*)d_in[15];
    const float* bias2 = (const float*)d_in[16];
    const float* w3l = (const float*)d_in[17];
    const float* b3l = (const float*)d_in[18];
    const float* w3r = (const float*)d_in[19];
    const float* b3r = (const float*)d_in[20];
    const float* a3  = (const float*)d_in[21];
    const float* bias3 = (const float*)d_in[22];
    const float* dw1 = (const float*)d_in[23];
    const float* db1 = (const float*)d_in[24];
    const float* dbn_g = (const float*)d_in[25];
    const float* dbn_b = (const float*)d_in[26];
    const float* dw2 = (const float*)d_in[27];
    const float* db2 = (const float*)d_in[28];
    float* out = (float*)d_out;

    float *p_xl1, *p_xr1, *p_h, *p_x23, *p_d, *p_b23;
    cudaGetSymbolAddress((void**)&p_xl1, g_xl1);
    cudaGetSymbolAddress((void**)&p_xr1, g_xr1);
    cudaGetSymbolAddress((void**)&p_h,   g_h);
    cudaGetSymbolAddress((void**)&p_x23, g_x23);
    cudaGetSymbolAddress((void**)&p_d,   g_d);
    cudaGetSymbolAddress((void**)&p_b23, g_bias23);
    uint16_t *p_w1lh, *p_w1rh, *p_w23h, *p_dw1h, *p_dw2h, *p_ebh, *p_ebl;
    cudaGetSymbolAddress((void**)&p_w1lh, g_w1lh);
    cudaGetSymbolAddress((void**)&p_w1rh, g_w1rh);
    cudaGetSymbolAddress((void**)&p_w23h, g_w23h);
    cudaGetSymbolAddress((void**)&p_dw1h, g_dw1h);
    cudaGetSymbolAddress((void**)&p_dw2h, g_dw2h);
    cudaGetSymbolAddress((void**)&p_ebh,  g_ebh);
    cudaGetSymbolAddress((void**)&p_ebl,  g_ebl);

    cudaFuncSetAttribute(gram_hmma, cudaFuncAttributeMaxDynamicSharedMemorySize, G_SMEM);

    static cudaStream_t s_side = nullptr;
    static cudaEvent_t evA = nullptr, evB = nullptr, evC = nullptr, evD = nullptr;
    if (!s_side) {
        cudaStreamCreateWithFlags(&s_side, cudaStreamNonBlocking);
        cudaEventCreateWithFlags(&evA, cudaEventDisableTiming);
        cudaEventCreateWithFlags(&evB, cudaEventDisableTiming);
        cudaEventCreateWithFlags(&evC, cudaEventDisableTiming);
        cudaEventCreateWithFlags(&evD, cudaEventDisableTiming);
    }

    const int MT  = (NN + 127) / 128;   // 79
    const int MT64 = (NN + 63) / 64;    // 157

    // ---- fork: CSR build on side stream ----
    cudaEventRecord(evA, 0);
    cudaStreamWaitEvent(s_side, evA, 0);
    k_zero_counts<<<(NN + 255) / 256, 256, 0, s_side>>>();
    k_count_deg<<<(NE + 255) / 256, 256, 0, s_side>>>(ei);
    k_scan_deg<<<1, 1024, 0, s_side>>>();
    k_fill_list<<<(NE + 255) / 256, 256, 0, s_side>>>(ei);
    cudaEventRecord(evB, s_side);

    // ---- main: weight converts + bias pack + layer-1 GEMM ----
    k_wsplit<<<(NFEAT * H1 + 255) / 256, 256>>>(w1l, p_w1lh, NFEAT, H1);
    k_wsplit<<<(NFEAT * H1 + 255) / 256, 256>>>(w1r, p_w1rh, NFEAT, H1);
    k_wsplit4<<<(256 * H1 + 255) / 256, 256>>>(w2l, w2r, w3l, w3r, p_w23h);
    k_wsplit<<<(NHID1 * NHID2 + 255) / 256, 256>>>(dw1, p_dw1h, NHID2, NHID1);
    k_wsplit<<<(NHID1 * NFEAT + 255) / 256, 256>>>(dw2, p_dw2h, NHID1, NFEAT);
    k_pack_bias<<<1, 256>>>(b2l, b2r, b3l, b3r);
    {
        TJobs j1 = {{ { p_w1lh, b1l, p_xl1 }, { p_w1rh, b1r, p_xr1 } }};
        gemmT64<<<dim3(1, MT64, 2), 256>>>(x, j1, NN, NFEAT, H1, nullptr, nullptr);
    }
    cudaStreamWaitEvent(0, evB, 0);   // join CSR

    // ---- GAT layer 1 -> BN stats (apply fused into next GEMM) ----
    {
        AJobs aj = {{ { p_xl1, p_xr1, H1, a1, bias1, p_h, H1 }, {} }};
        gat_agg<H1><<<dim3(NN, 1), H1>>>(aj);
    }
    bn_stats<H1><<<H1, 256>>>(p_h);

    // ---- layers 2 & 3 packed GEMM (BN+ReLU fused on A) ----
    {
        TJobs j2 = {{ { p_w23h, p_b23, p_x23 }, {} }};
        gemmT<<<dim3(2, MT, 1), 256>>>(p_h, j2, NN, H1, 256, bn1_g, bn1_b);
    }

    // ---- GAT layers 2 (mu) and 3 (logvar) ----
    {
        AJobs aj = {{ { p_x23 + 0,   p_x23 + 64,  256, a2, bias2, out + MU_OFF, 64 },
                      { p_x23 + 128, p_x23 + 192, 256, a3, bias3, out + LV_OFF, 64 } }};
        gat_agg<NHID2><<<dim3(NN, 2), NHID2>>>(aj);
    }

    // ---- reparameterize + fp16 pre-split ----
    k_reparam<<<(NN * NHID2 + 255) / 256, 256>>>(eps, out);

    // ---- fork: decoder MLP on side stream, gram on main ----
    cudaEventRecord(evC, 0);
    cudaStreamWaitEvent(s_side, evC, 0);
    {
        TJobs jd = {{ { p_dw1h, db1, p_d }, {} }};
        gemmT<<<dim3(2, MT, 1), 256, 0, s_side>>>(out + EMB_OFF, jd, NN, NHID2, NHID1,
                                                  nullptr, nullptr);
    }
    bn_stats<NHID1><<<NHID1, 256, 0, s_side>>>(p_d);
    {
        TJobs jd = {{ { p_dw2h, db2, out + REX_OFF }, {} }};
        gemmT<<<dim3(4, MT, 1), 256, 0, s_side>>>(p_d, jd, NN, NHID1, NFEAT,
                                                  dbn_g, dbn_b);
    }
    cudaEventRecord(evD, s_side);

    gram_hmma<<<MT * (MT + 1) / 2, 256, G_SMEM>>>(p_ebh, p_ebl, out + READJ_OFF);

    cudaStreamWaitEvent(0, evD, 0);   // join decoder
}

// round 11
// speedup vs baseline: 2.0595x; 1.0825x over previous
#include <cuda_runtime.h>
#include <cuda_fp16.h>
#include <cstdint>
#include <math.h>

#define NN     10000
#define EE     320000
#define NE     (EE + NN)     // with self loops
#define NFEAT  512
#define NHID1  256
#define NHID2  64
#define H1     128           // 2*nhid2
#define NEG_SLOPE 0.2f
#define BN_EPS 1e-5f

// output layout (flattened tuple: emb, re_x, readj, mu, logvar)
#define EMB_OFF   ((size_t)0)
#define REX_OFF   ((size_t)NN * NHID2)
#define READJ_OFF (REX_OFF + (size_t)NN * NFEAT)
#define MU_OFF    (READJ_OFF + (size_t)NN * NN)
#define LV_OFF    (MU_OFF + (size_t)NN * NHID2)

typedef unsigned long long u64;

// ---------------- warp MMA helpers (baseline PTX, works on sm_103) --------
__device__ __forceinline__ uint32_t smem_u32(const void* p) {
    uint32_t a;
    asm("{ .reg .u64 t; cvta.to.shared.u64 t, %1; cvt.u32.u64 %0, t; }" : "=r"(a) : "l"(p));
    return a;
}
__device__ __forceinline__ void ldsm_x4(uint32_t& r0, uint32_t& r1, uint32_t& r2, uint32_t& r3, uint32_t addr) {
    asm volatile("ldmatrix.sync.aligned.m8n8.x4.shared.b16 {%0,%1,%2,%3}, [%4];"
                 : "=r"(r0), "=r"(r1), "=r"(r2), "=r"(r3) : "r"(addr));
}
__device__ __forceinline__ void ldsm_x2(uint32_t& r0, uint32_t& r1, uint32_t addr) {
    asm volatile("ldmatrix.sync.aligned.m8n8.x2.shared.b16 {%0,%1}, [%2];"
                 : "=r"(r0), "=r"(r1) : "r"(addr));
}
__device__ __forceinline__ void mma_f16(float* d, uint32_t a0, uint32_t a1, uint32_t a2, uint32_t a3,
                                        uint32_t b0, uint32_t b1) {
    asm volatile("mma.sync.aligned.m16n8k16.row.col.f32.f16.f16.f32 "
                 "{%0,%1,%2,%3}, {%4,%5,%6,%7}, {%8,%9}, {%0,%1,%2,%3};"
                 : "+f"(d[0]), "+f"(d[1]), "+f"(d[2]), "+f"(d[3])
                 : "r"(a0), "r"(a1), "r"(a2), "r"(a3), "r"(b0), "r"(b1));
}
__device__ __forceinline__ void f16split(float v, uint16_t& h, uint16_t& l) {
    __half hb = __float2half_rn(v);
    __half lb = __float2half_rn(v - __half2float(hb));
    h = __half_as_ushort(hb);
    l = __half_as_ushort(lb);
}

// ---------------- scratch (device globals; no allocation allowed) ----------
__device__ float g_xl1[NN * H1];
__device__ float g_xr1[NN * H1];
__device__ float g_h  [NN * H1];
__device__ float g_x23[NN * 256];        // packed: xl2|xr2|xl3|xr3 (64 each)
__device__ float g_d  [NN * NHID1];
__device__ int   g_deg[NN];
__device__ int   g_rowptr[NN + 1];
__device__ int   g_cursor[NN];
__device__ int   g_srclist[NE];
__device__ float g_mean[NHID1];
__device__ float g_rstd[NHID1];
__device__ float g_bias23[256];
// emb fp16 hi/lo (pre-split for gram)
__device__ uint16_t g_ebh[NN * NHID2], g_ebl[NN * NHID2];
// transposed fp16 weights [Nc][K] (hi only; A-side carries the residual)
__device__ uint16_t g_w1lh[H1 * NFEAT];
__device__ uint16_t g_w1rh[H1 * NFEAT];
__device__ uint16_t g_w23h[256 * H1];
__device__ uint16_t g_dw1h[NHID1 * NHID2];
__device__ uint16_t g_dw2h[NFEAT * NHID1];

// ---------------- CSR build ----------------
__global__ void k_zero_counts() {
    int i = blockIdx.x * blockDim.x + threadIdx.x;
    if (i < NN) { g_deg[i] = 0; g_cursor[i] = 0; }
}

__global__ void k_count_deg(const int* __restrict__ edge_index) {
    int i = blockIdx.x * blockDim.x + threadIdx.x;
    if (i >= NE) return;
    int tgt = (i < EE) ? edge_index[EE + i] : (i - EE);
    atomicAdd(&g_deg[tgt], 1);
}

__global__ void k_scan_deg() {
    __shared__ int wsum[32];
    __shared__ int sc;
    int tid = threadIdx.x, lane = tid & 31, w = tid >> 5;
    if (tid == 0) { sc = 0; g_rowptr[0] = 0; }
    __syncthreads();
    for (int base = 0; base < NN; base += 1024) {
        int i = base + tid;
        int v = (i < NN) ? g_deg[i] : 0;
        int x = v;
#pragma unroll
        for (int o = 1; o < 32; o <<= 1) {
            int t = __shfl_up_sync(0xffffffffu, x, o);
            if (lane >= o) x += t;
        }
        if (lane == 31) wsum[w] = x;
        __syncthreads();
        if (w == 0) {
            int y = wsum[lane];
#pragma unroll
            for (int o = 1; o < 32; o <<= 1) {
                int t = __shfl_up_sync(0xffffffffu, y, o);
                if (lane >= o) y += t;
            }
            wsum[lane] = y;
        }
        __syncthreads();
        int pre = (w > 0) ? wsum[w - 1] : 0;
        int c = sc;
        if (i < NN) g_rowptr[i + 1] = c + pre + x;
        int total = wsum[31];
        __syncthreads();
        if (tid == 0) sc = c + total;
        __syncthreads();
    }
}

__global__ void k_fill_list(const int* __restrict__ edge_index) {
    int i = blockIdx.x * blockDim.x + threadIdx.x;
    if (i >= NE) return;
    int src, tgt;
    if (i < EE) { src = edge_index[i]; tgt = edge_index[EE + i]; }
    else        { src = i - EE;        tgt = i - EE; }
    int pos = atomicAdd(&g_cursor[tgt], 1);
    g_srclist[g_rowptr[tgt] + pos] = src;
}

// ---------------- weight transpose + fp16 convert ----------------
__global__ void k_wsplit(const float* __restrict__ W, uint16_t* __restrict__ hi,
                         int K, int Nc) {
    int i = blockIdx.x * blockDim.x + threadIdx.x;
    if (i >= K * Nc) return;
    int n = i / K, k = i - n * K;
    hi[i] = __half_as_ushort(__float2half_rn(W[(size_t)k * Nc + n]));
}
__global__ void k_wsplit4(const float* __restrict__ W0, const float* __restrict__ W1,
                          const float* __restrict__ W2, const float* __restrict__ W3,
                          uint16_t* __restrict__ hi) {
    int i = blockIdx.x * blockDim.x + threadIdx.x;
    if (i >= 256 * H1) return;
    int np = i >> 7, k = i & 127;
    int jj = np >> 6, n = np & 63;
    const float* W = (jj == 0) ? W0 : (jj == 1) ? W1 : (jj == 2) ? W2 : W3;
    hi[i] = __half_as_ushort(__float2half_rn(W[(size_t)k * 64 + n]));
}
__global__ void k_pack_bias(const float* __restrict__ b0, const float* __restrict__ b1,
                            const float* __restrict__ b2, const float* __restrict__ b3) {
    int i = threadIdx.x;            // 256 threads
    int jj = i >> 6, n = i & 63;
    const float* b = (jj == 0) ? b0 : (jj == 1) ? b1 : (jj == 2) ? b2 : b3;
    g_bias23[i] = b[n];
}

// ---------------- GEMM job plumbing ----------------
struct TJob  { const uint16_t* Bh; const float* bias; float* C; };
struct TJobs { TJob j[2]; };

// ---------------- gemmT: fp16 2-pass HMMA GEMM, 128x128 tile -------------
__global__ __launch_bounds__(256)
void gemmT(const float* __restrict__ A, TJobs jobs, int M, int K, int Nc,
           const float* __restrict__ bnG, const float* __restrict__ bnB) {
    const TJob jb = jobs.j[blockIdx.z];
    __shared__ __align__(16) uint16_t Ah[128][40], Al[128][40];
    __shared__ __align__(16) uint16_t Bh[128][40];
    int tid = threadIdx.x, lane = tid & 31, warp = tid >> 5;
    int row0 = blockIdx.y * 128, col0 = blockIdx.x * 128;
    int wm = (warp & 1) * 64, wn = (warp >> 1) * 32;
    int grp = lane >> 3, rl = lane & 7;
    float c[4][4][4];
#pragma unroll
    for (int mi = 0; mi < 4; mi++)
#pragma unroll
        for (int ni = 0; ni < 4; ni++)
#pragma unroll
            for (int e = 0; e < 4; e++) c[mi][ni][e] = 0.f;

    int ar = tid >> 1, kh = (tid & 1) * 16;
    int r = row0 + ar;
    bool va = r < M;

    for (int k0 = 0; k0 < K; k0 += 32) {
        const float* pa = A + (size_t)r * K + k0 + kh;
#pragma unroll
        for (int q = 0; q < 4; q++) {
            float4 v = va ? *(const float4*)(pa + q * 4) : make_float4(0.f, 0.f, 0.f, 0.f);
            if (bnG) {
                int ch = k0 + kh + q * 4;
                float4 mm = *(const float4*)(g_mean + ch);
                float4 rs = *(const float4*)(g_rstd + ch);
                float4 gg = *(const float4*)(bnG + ch);
                float4 bb = *(const float4*)(bnB + ch);
                v.x = fmaxf((v.x - mm.x) * rs.x * gg.x + bb.x, 0.f);
                v.y = fmaxf((v.y - mm.y) * rs.y * gg.y + bb.y, 0.f);
                v.z = fmaxf((v.z - mm.z) * rs.z * gg.z + bb.z, 0.f);
                v.w = fmaxf((v.w - mm.w) * rs.w * gg.w + bb.w, 0.f);
            }
            uint16_t h0, l0, h1, l1, h2, l2, h3, l3;
            f16split(v.x, h0, l0); f16split(v.y, h1, l1);
            f16split(v.z, h2, l2); f16split(v.w, h3, l3);
            *(uint32_t*)&Ah[ar][kh + q * 4]     = (uint32_t)h0 | ((uint32_t)h1 << 16);
            *(uint32_t*)&Ah[ar][kh + q * 4 + 2] = (uint32_t)h2 | ((uint32_t)h3 << 16);
            *(uint32_t*)&Al[ar][kh + q * 4]     = (uint32_t)l0 | ((uint32_t)l1 << 16);
            *(uint32_t*)&Al[ar][kh + q * 4 + 2] = (uint32_t)l2 | ((uint32_t)l3 << 16);
        }
        {
            const uint16_t* pbh = jb.Bh + (size_t)(col0 + ar) * K + k0 + kh;
            *(uint4*)&Bh[ar][kh]     = *(const uint4*)pbh;
            *(uint4*)&Bh[ar][kh + 8] = *(const uint4*)(pbh + 8);
        }
        __syncthreads();
#pragma unroll
        for (int pass = 0; pass < 2; pass++) {
            const uint16_t (*Aq)[40] = (pass == 1) ? Al : Ah;
#pragma unroll
            for (int k1 = 0; k1 < 32; k1 += 16) {
                uint32_t af[4][4], bf[4][2];
#pragma unroll
                for (int mi = 0; mi < 4; mi++) {
                    int arow = wm + mi * 16 + (grp & 1) * 8 + rl;
                    int acol = k1 + (grp >> 1) * 8;
                    ldsm_x4(af[mi][0], af[mi][1], af[mi][2], af[mi][3],
                            smem_u32(&Aq[arow][acol]));
                }
#pragma unroll
                for (int ni = 0; ni < 4; ni++) {
                    int brow = wn + ni * 8 + rl;
                    int bcol = k1 + (grp & 1) * 8;
                    ldsm_x2(bf[ni][0], bf[ni][1], smem_u32(&Bh[brow][bcol]));
                }
#pragma unroll
                for (int mi = 0; mi < 4; mi++)
#pragma unroll
                    for (int ni = 0; ni < 4; ni++)
                        mma_f16(c[mi][ni], af[mi][0], af[mi][1], af[mi][2], af[mi][3],
                                bf[ni][0], bf[ni][1]);
            }
        }
        __syncthreads();
    }
    int qr = lane >> 2, qc = 2 * (lane & 3);
#pragma unroll
    for (int mi = 0; mi < 4; mi++) {
#pragma unroll
        for (int half = 0; half < 2; half++) {
            int row = wm + mi * 16 + qr + half * 8;
            int rr = row0 + row;
            if (rr < M) {
                float* Crow = jb.C + (size_t)rr * Nc;
#pragma unroll
                for (int ni = 0; ni < 4; ni++) {
                    int cc = col0 + wn + ni * 8 + qc;
                    float2 p;
                    p.x = c[mi][ni][2 * half]     + __ldg(&jb.bias[cc]);
                    p.y = c[mi][ni][2 * half + 1] + __ldg(&jb.bias[cc + 1]);
                    *(float2*)&Crow[cc] = p;
                }
            }
        }
    }
}

// ---------------- gemmT64: same, 64x128 tile (better wave balance) --------
__global__ __launch_bounds__(256)
void gemmT64(const float* __restrict__ A, TJobs jobs, int M, int K, int Nc,
             const float* __restrict__ bnG, const float* __restrict__ bnB) {
    const TJob jb = jobs.j[blockIdx.z];
    __shared__ __align__(16) uint16_t Ah[64][40], Al[64][40];
    __shared__ __align__(16) uint16_t Bh[128][40];
    int tid = threadIdx.x, lane = tid & 31, warp = tid >> 5;
    int row0 = blockIdx.y * 64, col0 = blockIdx.x * 128;
    int wm = (warp & 1) * 32, wn = (warp >> 1) * 32;
    int grp = lane >> 3, rl = lane & 7;
    float c[2][4][4];
#pragma unroll
    for (int mi = 0; mi < 2; mi++)
#pragma unroll
        for (int ni = 0; ni < 4; ni++)
#pragma unroll
            for (int e = 0; e < 4; e++) c[mi][ni][e] = 0.f;

    int ar = tid >> 2, ks = (tid & 3) * 8;
    int br = tid >> 1, kb = (tid & 1) * 16;
    int r = row0 + ar;
    bool va = r < M;

    for (int k0 = 0; k0 < K; k0 += 32) {
        const float* pa = A + (size_t)r * K + k0 + ks;
#pragma unroll
        for (int q = 0; q < 2; q++) {
            float4 v = va ? *(const float4*)(pa + q * 4) : make_float4(0.f, 0.f, 0.f, 0.f);
            if (bnG) {
                int ch = k0 + ks + q * 4;
                float4 mm = *(const float4*)(g_mean + ch);
                float4 rs = *(const float4*)(g_rstd + ch);
                float4 gg = *(const float4*)(bnG + ch);
                float4 bb = *(const float4*)(bnB + ch);
                v.x = fmaxf((v.x - mm.x) * rs.x * gg.x + bb.x, 0.f);
                v.y = fmaxf((v.y - mm.y) * rs.y * gg.y + bb.y, 0.f);
                v.z = fmaxf((v.z - mm.z) * rs.z * gg.z + bb.z, 0.f);
                v.w = fmaxf((v.w - mm.w) * rs.w * gg.w + bb.w, 0.f);
            }
            uint16_t h0, l0, h1, l1, h2, l2, h3, l3;
            f16split(v.x, h0, l0); f16split(v.y, h1, l1);
            f16split(v.z, h2, l2); f16split(v.w, h3, l3);
            *(uint32_t*)&Ah[ar][ks + q * 4]     = (uint32_t)h0 | ((uint32_t)h1 << 16);
            *(uint32_t*)&Ah[ar][ks + q * 4 + 2] = (uint32_t)h2 | ((uint32_t)h3 << 16);
            *(uint32_t*)&Al[ar][ks + q * 4]     = (uint32_t)l0 | ((uint32_t)l1 << 16);
            *(uint32_t*)&Al[ar][ks + q * 4 + 2] = (uint32_t)l2 | ((uint32_t)l3 << 16);
        }
        {
            const uint16_t* pbh = jb.Bh + (size_t)(col0 + br) * K + k0 + kb;
            *(uint4*)&Bh[br][kb]     = *(const uint4*)pbh;
            *(uint4*)&Bh[br][kb + 8] = *(const uint4*)(pbh + 8);
        }
        __syncthreads();
#pragma unroll
        for (int pass = 0; pass < 2; pass++) {
            const uint16_t (*Aq)[40] = (pass == 1) ? Al : Ah;
#pragma unroll
            for (int k1 = 0; k1 < 32; k1 += 16) {
                uint32_t af[2][4], bf[4][2];
#pragma unroll
                for (int mi = 0; mi < 2; mi++) {
                    int arow = wm + mi * 16 + (grp & 1) * 8 + rl;
                    int acol = k1 + (grp >> 1) * 8;
                    ldsm_x4(af[mi][0], af[mi][1], af[mi][2], af[mi][3],
                            smem_u32(&Aq[arow][acol]));
                }
#pragma unroll
                for (int ni = 0; ni < 4; ni++) {
                    int brow = wn + ni * 8 + rl;
                    int bcol = k1 + (grp & 1) * 8;
                    ldsm_x2(bf[ni][0], bf[ni][1], smem_u32(&Bh[brow][bcol]));
                }
#pragma unroll
                for (int mi = 0; mi < 2; mi++)
#pragma unroll
                    for (int ni = 0; ni < 4; ni++)
                        mma_f16(c[mi][ni], af[mi][0], af[mi][1], af[mi][2], af[mi][3],
                                bf[ni][0], bf[ni][1]);
            }
        }
        __syncthreads();
    }
    int qr = lane >> 2, qc = 2 * (lane & 3);
#pragma unroll
    for (int mi = 0; mi < 2; mi++) {
#pragma unroll
        for (int half = 0; half < 2; half++) {
            int row = wm + mi * 16 + qr + half * 8;
            int rr = row0 + row;
            if (rr < M) {
                float* Crow = jb.C + (size_t)rr * Nc;
#pragma unroll
                for (int ni = 0; ni < 4; ni++) {
                    int cc = col0 + wn + ni * 8 + qc;
                    float2 p;
                    p.x = c[mi][ni][2 * half]     + __ldg(&jb.bias[cc]);
                    p.y = c[mi][ni][2 * half + 1] + __ldg(&jb.bias[cc + 1]);
                    *(float2*)&Crow[cc] = p;
                }
            }
        }
    }
}

// ---------------- GATv2 aggregation: fused online-softmax single pass -----
// One block per (node, job). Edges partitioned over groups of NL=C/4 lanes;
// each group keeps a running (max, sum, weighted-accum) and each edge row is
// read exactly ONCE. 2-edge ILP via two independent softmax states.
struct AJob  { const float* xl; const float* xr; int ld; const float* att;
               const float* bias; float* out; int ldo; };
struct AJobs { AJob j[2]; };

template <int C>
__global__ void gat_fused(AJobs jobs) {
    constexpr int W   = C / 32;                      // warps per block
    constexpr int NL  = (C / 4 < 32) ? C / 4 : 32;   // lanes per group
    constexpr int GPW = 32 / NL;                     // groups per warp
    constexpr int NG  = W * GPW;                     // total groups
    const AJob jb = jobs.j[blockIdx.y];
    int t = blockIdx.x;
    int tid = threadIdx.x, lane = tid & 31, warp = tid >> 5;
    int sub = lane / NL, lg = lane & (NL - 1);
    int gid = warp * GPW + sub;
    uint32_t gmask = ((NL < 32) ? ((1u << NL) - 1u) << (sub * NL) : 0xffffffffu);

    __shared__ float4 s_xr4[C / 4], s_att4[C / 4];
    __shared__ float  s_m[NG], s_s[NG];
    __shared__ float4 s_acc[NG][NL];
    if (tid < C / 4) {
        s_xr4[tid]  = *(const float4*)(jb.xr + (size_t)t * jb.ld + tid * 4);
        s_att4[tid] = *(const float4*)(jb.att + tid * 4);
    }
    int beg = g_rowptr[t];
    int deg = g_rowptr[t + 1] - beg;
    __syncthreads();

    float4 xr4 = s_xr4[lg];
    float4 at4 = s_att4[lg];
    const float* xl = jb.xl;
    int ld = jb.ld;

    float m0 = -1e30f, z0 = 0.f;
    float m1 = -1e30f, z1 = 0.f;
    float4 a0 = make_float4(0.f, 0.f, 0.f, 0.f), a1 = a0;

    int j = gid;
    for (; j + NG < deg; j += 2 * NG) {
        int sA = g_srclist[beg + j];
        int sB = g_srclist[beg + j + NG];
        float4 vA = *(const float4*)(xl + (size_t)sA * ld + lg * 4);
        float4 vB = *(const float4*)(xl + (size_t)sB * ld + lg * 4);
        float pA, pB;
        {
            float a = vA.x + xr4.x; a = fmaxf(a, NEG_SLOPE * a);
            float b = vA.y + xr4.y; b = fmaxf(b, NEG_SLOPE * b);
            float c = vA.z + xr4.z; c = fmaxf(c, NEG_SLOPE * c);
            float d = vA.w + xr4.w; d = fmaxf(d, NEG_SLOPE * d);
            pA = at4.x * a + at4.y * b + at4.z * c + at4.w * d;
            a = vB.x + xr4.x; a = fmaxf(a, NEG_SLOPE * a);
            b = vB.y + xr4.y; b = fmaxf(b, NEG_SLOPE * b);
            c = vB.z + xr4.z; c = fmaxf(c, NEG_SLOPE * c);
            d = vB.w + xr4.w; d = fmaxf(d, NEG_SLOPE * d);
            pB = at4.x * a + at4.y * b + at4.z * c + at4.w * d;
        }
#pragma unroll
        for (int o = NL / 2; o; o >>= 1) {
            pA += __shfl_xor_sync(gmask, pA, o);
            pB += __shfl_xor_sync(gmask, pB, o);
        }
        // online softmax update (state 0 with edge A)
        float mn0 = fmaxf(m0, pA);
        float sc0 = __expf(m0 - mn0);
        float w0  = __expf(pA - mn0);
        z0 = z0 * sc0 + w0;
        a0.x = a0.x * sc0 + w0 * vA.x;
        a0.y = a0.y * sc0 + w0 * vA.y;
        a0.z = a0.z * sc0 + w0 * vA.z;
        a0.w = a0.w * sc0 + w0 * vA.w;
        m0 = mn0;
        // state 1 with edge B
        float mn1 = fmaxf(m1, pB);
        float sc1 = __expf(m1 - mn1);
        float w1  = __expf(pB - mn1);
        z1 = z1 * sc1 + w1;
        a1.x = a1.x * sc1 + w1 * vB.x;
        a1.y = a1.y * sc1 + w1 * vB.y;
        a1.z = a1.z * sc1 + w1 * vB.z;
        a1.w = a1.w * sc1 + w1 * vB.w;
        m1 = mn1;
    }
    if (j < deg) {
        int sA = g_srclist[beg + j];
        float4 vA = *(const float4*)(xl + (size_t)sA * ld + lg * 4);
        float a = vA.x + xr4.x; a = fmaxf(a, NEG_SLOPE * a);
        float b = vA.y + xr4.y; b = fmaxf(b, NEG_SLOPE * b);
        float c = vA.z + xr4.z; c = fmaxf(c, NEG_SLOPE * c);
        float d = vA.w + xr4.w; d = fmaxf(d, NEG_SLOPE * d);
        float pA = at4.x * a + at4.y * b + at4.z * c + at4.w * d;
#pragma unroll
        for (int o = NL / 2; o; o >>= 1) pA += __shfl_xor_sync(gmask, pA, o);
        float mn0 = fmaxf(m0, pA);
        float sc0 = __expf(m0 - mn0);
        float w0  = __expf(pA - mn0);
        z0 = z0 * sc0 + w0;
        a0.x = a0.x * sc0 + w0 * vA.x;
        a0.y = a0.y * sc0 + w0 * vA.y;
        a0.z = a0.z * sc0 + w0 * vA.z;
        a0.w = a0.w * sc0 + w0 * vA.w;
        m0 = mn0;
    }
    // merge the two ILP states
    {
        float M = fmaxf(m0, m1);
        float e0 = __expf(m0 - M), e1 = __expf(m1 - M);
        z0 = z0 * e0 + z1 * e1;
        a0.x = a0.x * e0 + a1.x * e1;
        a0.y = a0.y * e0 + a1.y * e1;
        a0.z = a0.z * e0 + a1.z * e1;
        a0.w = a0.w * e0 + a1.w * e1;
        m0 = M;
    }
    if (lg == 0) { s_m[gid] = m0; s_s[gid] = z0; }
    s_acc[gid][lg] = a0;
    __syncthreads();

    // block merge across groups: first NL threads (tid < NL)
    if (tid < NL) {
        float M = s_m[0];
#pragma unroll
        for (int g = 1; g < NG; g++) M = fmaxf(M, s_m[g]);
        float zt = 0.f;
        float4 at = make_float4(0.f, 0.f, 0.f, 0.f);
#pragma unroll
        for (int g = 0; g < NG; g++) {
            float f = __expf(s_m[g] - M);
            zt += s_s[g] * f;
            float4 q = s_acc[g][tid];
            at.x += q.x * f; at.y += q.y * f; at.z += q.z * f; at.w += q.w * f;
        }
        float inv = 1.f / zt;
        float4 b4 = *(const float4*)(jb.bias + tid * 4);
        float4 o4;
        o4.x = at.x * inv + b4.x;
        o4.y = at.y * inv + b4.y;
        o4.z = at.z * inv + b4.z;
        o4.w = at.w * inv + b4.w;
        *(float4*)(jb.out + (size_t)t * jb.ldo + tid * 4) = o4;
    }
}

// ---------------- batch norm stats ----------------
template <int C>
__global__ void bn_stats(const float* __restrict__ h) {
    int c = blockIdx.x;
    int tid = threadIdx.x;
    float s = 0.f, s2 = 0.f;
    for (int r = tid; r < NN; r += 256) {
        float v = h[(size_t)r * C + c];
        s += v; s2 += v * v;
    }
    __shared__ float sh[8], sh2[8];
#pragma unroll
    for (int o = 16; o; o >>= 1) {
        s  += __shfl_xor_sync(0xffffffffu, s,  o);
        s2 += __shfl_xor_sync(0xffffffffu, s2, o);
    }
    if ((tid & 31) == 0) { sh[tid >> 5] = s; sh2[tid >> 5] = s2; }
    __syncthreads();
    if (tid == 0) {
        float ts = 0.f, ts2 = 0.f;
        for (int w = 0; w < 8; w++) { ts += sh[w]; ts2 += sh2[w]; }
        float mean = ts / NN;
        float var = ts2 / NN - mean * mean;
        g_mean[c] = mean;
        g_rstd[c] = rsqrtf(var + BN_EPS);
    }
}

// ---------------- reparameterize + fp16 pre-split ----------------
__global__ void k_reparam(const float* __restrict__ eps, float* __restrict__ out) {
    int i = blockIdx.x * blockDim.x + threadIdx.x;
    if (i >= NN * NHID2) return;
    float mu = out[MU_OFF + i];
    float lv = out[LV_OFF + i];
    float e = eps[i] * __expf(lv) + mu;
    out[EMB_OFF + i] = e;
    uint16_t h, l;
    f16split(e, h, l);
    g_ebh[i] = h;
    g_ebl[i] = l;
}

// ---------------- readj = sigmoid(emb @ emb^T), fp16 2-pass HMMA ----------
#define GP 72
#define G_AHI 0
#define G_ALO (G_AHI + 128 * GP * 2)
#define G_BHI (G_ALO + 128 * GP * 2)
#define G_SMEM 65536
#define MTG 79

__global__ __launch_bounds__(256)
void gram_hmma(const uint16_t* __restrict__ Eh, const uint16_t* __restrict__ El,
               float* __restrict__ out) {
    // decode linear block id -> upper-triangular (by, bx)
    int bid = blockIdx.x;
    int by = (int)(0.5f * (2.f * MTG + 1.f) -
                   sqrtf((2.f * MTG + 1.f) * (2.f * MTG + 1.f) * 0.25f - 2.f * (float)bid));
    if (by < 0) by = 0;
    if (by > MTG - 1) by = MTG - 1;
    int start = by * MTG - (by * (by - 1)) / 2;
    while (start > bid) { by--; start = by * MTG - (by * (by - 1)) / 2; }
    while (bid >= start + (MTG - by)) { by++; start = by * MTG - (by * (by - 1)) / 2; }
    int bx = by + (bid - start);

    extern __shared__ __align__(16) char smem[];
    uint32_t sb = smem_u32(smem);
    int tid = threadIdx.x, lane = tid & 31, warp = tid >> 5;
    int row0 = by * 128, col0 = bx * 128;

    {
        int rrow = tid & 127;
        uint4 z = make_uint4(0, 0, 0, 0);
        if (tid < 128) {
            int rA = row0 + rrow;
            bool va = rA < NN;
            const uint4* ph = (const uint4*)(Eh + (size_t)rA * 64);
            const uint4* pl = (const uint4*)(El + (size_t)rA * 64);
#pragma unroll
            for (int q = 0; q < 8; q++) {
                uint32_t off = (rrow * GP + q * 8) * 2;
                *(uint4*)(smem + G_AHI + off) = va ? ph[q] : z;
                *(uint4*)(smem + G_ALO + off) = va ? pl[q] : z;
            }
        } else {
            int rB = col0 + rrow;
            bool vb = rB < NN;
            const uint4* ph = (const uint4*)(Eh + (size_t)rB * 64);
#pragma unroll
            for (int q = 0; q < 8; q++) {
                uint32_t off = (rrow * GP + q * 8) * 2;
                *(uint4*)(smem + G_BHI + off) = vb ? ph[q] : z;
            }
        }
    }
    __syncthreads();

    int wm = (warp & 1) * 64;
    int wn = (warp >> 1) * 32;
    float c[4][4][4];
#pragma unroll
    for (int mi = 0; mi < 4; mi++)
#pragma unroll
        for (int ni = 0; ni < 4; ni++)
#pragma unroll
            for (int e = 0; e < 4; e++) c[mi][ni][e] = 0.f;

    int grp = lane >> 3, rl = lane & 7;
#pragma unroll
    for (int pass = 0; pass < 2; pass++) {
        uint32_t aBase = sb + ((pass == 1) ? G_ALO : G_AHI);
        uint32_t bBase = sb + G_BHI;
#pragma unroll
        for (int k0 = 0; k0 < 64; k0 += 16) {
            uint32_t af[4][4], bf[4][2];
#pragma unroll
            for (int mi = 0; mi < 4; mi++) {
                int arow = wm + mi * 16 + (grp & 1) * 8 + rl;
                int acol = k0 + (grp >> 1) * 8;
                ldsm_x4(af[mi][0], af[mi][1], af[mi][2], af[mi][3],
                        aBase + (arow * GP + acol) * 2);
            }
#pragma unroll
            for (int ni = 0; ni < 4; ni++) {
                int brow = wn + ni * 8 + rl;
                int bcol = k0 + (grp & 1) * 8;
                ldsm_x2(bf[ni][0], bf[ni][1], bBase + (brow * GP + bcol) * 2);
            }
#pragma unroll
            for (int mi = 0; mi < 4; mi++)
#pragma unroll
                for (int ni = 0; ni < 4; ni++)
                    mma_f16(c[mi][ni], af[mi][0], af[mi][1], af[mi][2], af[mi][3],
                            bf[ni][0], bf[ni][1]);
        }
    }
    __syncthreads();

    float* stag = (float*)smem;
    bool diag = (bx == by);
    int qr = lane >> 2, qc = 2 * (lane & 3);
#pragma unroll
    for (int mi = 0; mi < 4; mi++) {
#pragma unroll
        for (int ni = 0; ni < 4; ni++) {
#pragma unroll
            for (int half = 0; half < 2; half++) {
                int row = wm + mi * 16 + qr + half * 8;
                int col = wn + ni * 8 + qc;
                float v0 = 1.f / (1.f + __expf(-c[mi][ni][2 * half]));
                float v1 = 1.f / (1.f + __expf(-c[mi][ni][2 * half + 1]));
                int r = row0 + row, cc = col0 + col;
                if (r < NN && cc < NN)
                    *(float2*)(out + (size_t)r * NN + cc) = make_float2(v0, v1);
                if (!diag) {
                    int s = row & 31;
                    stag[row * 128 + (col ^ s)] = v0;
                    stag[row * 128 + ((col + 1) ^ s)] = v1;
                }
            }
        }
    }
    if (diag) return;
    __syncthreads();

    // mirror: warp per column, 128B coalesced stores
    for (int cc = warp; cc < 128; cc += 8) {
        int cgl = col0 + cc;
        if (cgl >= NN) continue;
        float* mrow = out + (size_t)cgl * NN + row0;
#pragma unroll
        for (int ib = 0; ib < 128; ib += 32) {
            int i = ib + lane;
            if (row0 + i < NN)
                mrow[i] = stag[i * 128 + (cc ^ (i & 31))];
        }
    }
}

// ---------------- launch ----------------
extern "C" void kernel_launch(void* const* d_in, const int* in_sizes, int n_in,
                              void* d_out, int out_size) {
    const float* x   = (const float*)d_in[0];
    const int*   ei  = (const int*)  d_in[1];
    const float* eps = (const float*)d_in[2];
    const float* w1l = (const float*)d_in[3];
    const float* b1l = (const float*)d_in[4];
    const float* w1r = (const float*)d_in[5];
    const float* b1r = (const float*)d_in[6];
    const float* a1  = (const float*)d_in[7];
    const float* bias1 = (const float*)d_in[8];
    const float* bn1_g = (const float*)d_in[9];
    const float* bn1_b = (const float*)d_in[10];
    const float* w2l = (const float*)d_in[11];
    const float* b2l = (const float*)d_in[12];
    const float* w2r = (const float*)d_in[13];
    const float* b2r = (const float*)d_in[14];
    const float* a2  = (const float*)d_in[15];
    const float* bias2 = (const float*)d_in[16];
    const float* w3l = (const float*)d_in[17];
    const float* b3l = (const float*)d_in[18];
    const float* w3r = (const float*)d_in[19];
    const float* b3r = (const float*)d_in[20];
    const float* a3  = (const float*)d_in[21];
    const float* bias3 = (const float*)d_in[22];
    const float* dw1 = (const float*)d_in[23];
    const float* db1 = (const float*)d_in[24];
    const float* dbn_g = (const float*)d_in[25];
    const float* dbn_b = (const float*)d_in[26];
    const float* dw2 = (const float*)d_in[27];
    const float* db2 = (const float*)d_in[28];
    float* out = (float*)d_out;

    float *p_xl1, *p_xr1, *p_h, *p_x23, *p_d, *p_b23;
    cudaGetSymbolAddress((void**)&p_xl1, g_xl1);
    cudaGetSymbolAddress((void**)&p_xr1, g_xr1);
    cudaGetSymbolAddress((void**)&p_h,   g_h);
    cudaGetSymbolAddress((void**)&p_x23, g_x23);
    cudaGetSymbolAddress((void**)&p_d,   g_d);
    cudaGetSymbolAddress((void**)&p_b23, g_bias23);
    uint16_t *p_w1lh, *p_w1rh, *p_w23h, *p_dw1h, *p_dw2h, *p_ebh, *p_ebl;
    cudaGetSymbolAddress((void**)&p_w1lh, g_w1lh);
    cudaGetSymbolAddress((void**)&p_w1rh, g_w1rh);
    cudaGetSymbolAddress((void**)&p_w23h, g_w23h);
    cudaGetSymbolAddress((void**)&p_dw1h, g_dw1h);
    cudaGetSymbolAddress((void**)&p_dw2h, g_dw2h);
    cudaGetSymbolAddress((void**)&p_ebh,  g_ebh);
    cudaGetSymbolAddress((void**)&p_ebl,  g_ebl);

    cudaFuncSetAttribute(gram_hmma, cudaFuncAttributeMaxDynamicSharedMemorySize, G_SMEM);

    static cudaStream_t s_side = nullptr;
    static cudaEvent_t evA = nullptr, evB = nullptr, evC = nullptr, evD = nullptr;
    if (!s_side) {
        cudaStreamCreateWithFlags(&s_side, cudaStreamNonBlocking);
        cudaEventCreateWithFlags(&evA, cudaEventDisableTiming);
        cudaEventCreateWithFlags(&evB, cudaEventDisableTiming);
        cudaEventCreateWithFlags(&evC, cudaEventDisableTiming);
        cudaEventCreateWithFlags(&evD, cudaEventDisableTiming);
    }

    const int MT  = (NN + 127) / 128;   // 79
    const int MT64 = (NN + 63) / 64;    // 157

    // ---- fork: CSR build on side stream ----
    cudaEventRecord(evA, 0);
    cudaStreamWaitEvent(s_side, evA, 0);
    k_zero_counts<<<(NN + 255) / 256, 256, 0, s_side>>>();
    k_count_deg<<<(NE + 255) / 256, 256, 0, s_side>>>(ei);
    k_scan_deg<<<1, 1024, 0, s_side>>>();
    k_fill_list<<<(NE + 255) / 256, 256, 0, s_side>>>(ei);
    cudaEventRecord(evB, s_side);

    // ---- main: weight converts + bias pack + layer-1 GEMM ----
    k_wsplit<<<(NFEAT * H1 + 255) / 256, 256>>>(w1l, p_w1lh, NFEAT, H1);
    k_wsplit<<<(NFEAT * H1 + 255) / 256, 256>>>(w1r, p_w1rh, NFEAT, H1);
    k_wsplit4<<<(256 * H1 + 255) / 256, 256>>>(w2l, w2r, w3l, w3r, p_w23h);
    k_wsplit<<<(NHID1 * NHID2 + 255) / 256, 256>>>(dw1, p_dw1h, NHID2, NHID1);
    k_wsplit<<<(NHID1 * NFEAT + 255) / 256, 256>>>(dw2, p_dw2h, NHID1, NFEAT);
    k_pack_bias<<<1, 256>>>(b2l, b2r, b3l, b3r);
    {
        TJobs j1 = {{ { p_w1lh, b1l, p_xl1 }, { p_w1rh, b1r, p_xr1 } }};
        gemmT64<<<dim3(1, MT64, 2), 256>>>(x, j1, NN, NFEAT, H1, nullptr, nullptr);
    }
    cudaStreamWaitEvent(0, evB, 0);   // join CSR

    // ---- GAT layer 1 (fused online softmax) -> BN stats ----
    {
        AJobs aj = {{ { p_xl1, p_xr1, H1, a1, bias1, p_h, H1 }, {} }};
        gat_fused<H1><<<dim3(NN, 1), H1>>>(aj);
    }
    bn_stats<H1><<<H1, 256>>>(p_h);

    // ---- layers 2 & 3 packed GEMM (BN+ReLU fused on A) ----
    {
        TJobs j2 = {{ { p_w23h, p_b23, p_x23 }, {} }};
        gemmT<<<dim3(2, MT, 1), 256>>>(p_h, j2, NN, H1, 256, bn1_g, bn1_b);
    }

    // ---- GAT layers 2 (mu) and 3 (logvar), fused ----
    {
        AJobs aj = {{ { p_x23 + 0,   p_x23 + 64,  256, a2, bias2, out + MU_OFF, 64 },
                      { p_x23 + 128, p_x23 + 192, 256, a3, bias3, out + LV_OFF, 64 } }};
        gat_fused<NHID2><<<dim3(NN, 2), NHID2>>>(aj);
    }

    // ---- reparameterize + fp16 pre-split ----
    k_reparam<<<(NN * NHID2 + 255) / 256, 256>>>(eps, out);

    // ---- fork: decoder MLP on side stream, gram on main ----
    cudaEventRecord(evC, 0);
    cudaStreamWaitEvent(s_side, evC, 0);
    {
        TJobs jd = {{ { p_dw1h, db1, p_d }, {} }};
        gemmT<<<dim3(2, MT, 1), 256, 0, s_side>>>(out + EMB_OFF, jd, NN, NHID2, NHID1,
                                                  nullptr, nullptr);
    }
    bn_stats<NHID1><<<NHID1, 256, 0, s_side>>>(p_d);
    {
        TJobs jd = {{ { p_dw2h, db2, out + REX_OFF }, {} }};
        gemmT<<<dim3(4, MT, 1), 256, 0, s_side>>>(p_d, jd, NN, NHID1, NFEAT,
                                                  dbn_g, dbn_b);
    }
    cudaEventRecord(evD, s_side);

    gram_hmma<<<MT * (MT + 1) / 2, 256, G_SMEM>>>(p_ebh, p_ebl, out + READJ_OFF);

    cudaStreamWaitEvent(0, evD, 0);   // join decoder
}

// round 12
// speedup vs baseline: 2.1147x; 1.0268x over previous
#include <cuda_runtime.h>
#include <cuda_fp16.h>
#include <cstdint>
#include <math.h>

#define NN     10000
#define EE     320000
#define NE     (EE + NN)     // with self loops
#define NFEAT  512
#define NHID1  256
#define NHID2  64
#define H1     128           // 2*nhid2
#define NEG_SLOPE 0.2f
#define BN_EPS 1e-5f

// output layout (flattened tuple: emb, re_x, readj, mu, logvar)
#define EMB_OFF   ((size_t)0)
#define REX_OFF   ((size_t)NN * NHID2)
#define READJ_OFF (REX_OFF + (size_t)NN * NFEAT)
#define MU_OFF    (READJ_OFF + (size_t)NN * NN)
#define LV_OFF    (MU_OFF + (size_t)NN * NHID2)

typedef unsigned long long u64;

// ---------------- warp MMA helpers (baseline PTX, works on sm_103) --------
__device__ __forceinline__ uint32_t smem_u32(const void* p) {
    uint32_t a;
    asm("{ .reg .u64 t; cvta.to.shared.u64 t, %1; cvt.u32.u64 %0, t; }" : "=r"(a) : "l"(p));
    return a;
}
__device__ __forceinline__ void ldsm_x4(uint32_t& r0, uint32_t& r1, uint32_t& r2, uint32_t& r3, uint32_t addr) {
    asm volatile("ldmatrix.sync.aligned.m8n8.x4.shared.b16 {%0,%1,%2,%3}, [%4];"
                 : "=r"(r0), "=r"(r1), "=r"(r2), "=r"(r3) : "r"(addr));
}
__device__ __forceinline__ void ldsm_x2(uint32_t& r0, uint32_t& r1, uint32_t addr) {
    asm volatile("ldmatrix.sync.aligned.m8n8.x2.shared.b16 {%0,%1}, [%2];"
                 : "=r"(r0), "=r"(r1) : "r"(addr));
}
__device__ __forceinline__ void mma_f16(float* d, uint32_t a0, uint32_t a1, uint32_t a2, uint32_t a3,
                                        uint32_t b0, uint32_t b1) {
    asm volatile("mma.sync.aligned.m16n8k16.row.col.f32.f16.f16.f32 "
                 "{%0,%1,%2,%3}, {%4,%5,%6,%7}, {%8,%9}, {%0,%1,%2,%3};"
                 : "+f"(d[0]), "+f"(d[1]), "+f"(d[2]), "+f"(d[3])
                 : "r"(a0), "r"(a1), "r"(a2), "r"(a3), "r"(b0), "r"(b1));
}
__device__ __forceinline__ void f16split(float v, uint16_t& h, uint16_t& l) {
    __half hb = __float2half_rn(v);
    __half lb = __float2half_rn(v - __half2float(hb));
    h = __half_as_ushort(hb);
    l = __half_as_ushort(lb);
}
__device__ __forceinline__ uint16_t f16h(float v) {
    return __half_as_ushort(__float2half_rn(v));
}

// ---------------- scratch (device globals; no allocation allowed) ----------
__device__ float g_xl1[NN * H1];
__device__ float g_xr1[NN * H1];
__device__ float g_h  [NN * H1];
__device__ float g_x23[NN * 256];        // packed: xl2|xr2|xl3|xr3 (64 each)
__device__ float g_d  [NN * NHID1];
__device__ int   g_deg[NN];
__device__ int   g_rowptr[NN + 1];
__device__ int   g_cursor[NN];
__device__ int   g_srclist[NE];
__device__ float g_mean[NHID1];
__device__ float g_rstd[NHID1];
__device__ float g_bias23[256];
// emb fp16 hi/lo (pre-split for gram + decoder GEMM)
__device__ uint16_t g_ebh[NN * NHID2], g_ebl[NN * NHID2];
// transposed fp16 weights [Nc][K]
__device__ uint16_t g_w1lh[H1 * NFEAT];
__device__ uint16_t g_w1rh[H1 * NFEAT];
__device__ uint16_t g_w23h[256 * H1];
__device__ uint16_t g_dw1h[NHID1 * NHID2];
__device__ uint16_t g_dw2h[NFEAT * NHID1];

// ---------------- CSR build ----------------
__global__ void k_zero_counts() {
    int i = blockIdx.x * blockDim.x + threadIdx.x;
    if (i < NN) { g_deg[i] = 0; g_cursor[i] = 0; }
}

__global__ void k_count_deg(const int* __restrict__ edge_index) {
    int i = blockIdx.x * blockDim.x + threadIdx.x;
    if (i >= NE) return;
    int tgt = (i < EE) ? edge_index[EE + i] : (i - EE);
    atomicAdd(&g_deg[tgt], 1);
}

__global__ void k_scan_deg() {
    __shared__ int wsum[32];
    __shared__ int sc;
    int tid = threadIdx.x, lane = tid & 31, w = tid >> 5;
    if (tid == 0) { sc = 0; g_rowptr[0] = 0; }
    __syncthreads();
    for (int base = 0; base < NN; base += 1024) {
        int i = base + tid;
        int v = (i < NN) ? g_deg[i] : 0;
        int x = v;
#pragma unroll
        for (int o = 1; o < 32; o <<= 1) {
            int t = __shfl_up_sync(0xffffffffu, x, o);
            if (lane >= o) x += t;
        }
        if (lane == 31) wsum[w] = x;
        __syncthreads();
        if (w == 0) {
            int y = wsum[lane];
#pragma unroll
            for (int o = 1; o < 32; o <<= 1) {
                int t = __shfl_up_sync(0xffffffffu, y, o);
                if (lane >= o) y += t;
            }
            wsum[lane] = y;
        }
        __syncthreads();
        int pre = (w > 0) ? wsum[w - 1] : 0;
        int c = sc;
        if (i < NN) g_rowptr[i + 1] = c + pre + x;
        int total = wsum[31];
        __syncthreads();
        if (tid == 0) sc = c + total;
        __syncthreads();
    }
}

__global__ void k_fill_list(const int* __restrict__ edge_index) {
    int i = blockIdx.x * blockDim.x + threadIdx.x;
    if (i >= NE) return;
    int src, tgt;
    if (i < EE) { src = edge_index[i]; tgt = edge_index[EE + i]; }
    else        { src = i - EE;        tgt = i - EE; }
    int pos = atomicAdd(&g_cursor[tgt], 1);
    g_srclist[g_rowptr[tgt] + pos] = src;
}

// ---------------- fused prep: all weight transposes + bias pack -----------
#define P_S01 (H1 * NFEAT)          // w1l & w1r together
#define P_S2  (256 * H1)
#define P_S3  (NHID1 * NHID2)
#define P_S4  (NFEAT * NHID1)
#define P_TOT (P_S01 + P_S2 + P_S3 + P_S4 + 256)

__global__ void k_prep(const float* __restrict__ w1l, const float* __restrict__ w1r,
                       const float* __restrict__ w2l, const float* __restrict__ w2r,
                       const float* __restrict__ w3l, const float* __restrict__ w3r,
                       const float* __restrict__ dw1, const float* __restrict__ dw2,
                       const float* __restrict__ b2l, const float* __restrict__ b2r,
                       const float* __restrict__ b3l, const float* __restrict__ b3r) {
    int i = blockIdx.x * blockDim.x + threadIdx.x;
    if (i < P_S01) {                       // w1{l,r}: [K=NFEAT][H1] -> [H1][NFEAT]
        int n = i / NFEAT, k = i - n * NFEAT;
        g_w1lh[i] = f16h(w1l[(size_t)k * H1 + n]);
        g_w1rh[i] = f16h(w1r[(size_t)k * H1 + n]);
        return;
    }
    i -= P_S01;
    if (i < P_S2) {                        // w23 packed: 4x [H1][64] -> [256][H1]
        int np = i >> 7, k = i & 127;
        int jj = np >> 6, n = np & 63;
        const float* W = (jj == 0) ? w2l : (jj == 1) ? w2r : (jj == 2) ? w3l : w3r;
        g_w23h[i] = f16h(W[(size_t)k * 64 + n]);
        return;
    }
    i -= P_S2;
    if (i < P_S3) {                        // dw1: [K=64][256] -> [256][64]
        int n = i / NHID2, k = i - n * NHID2;
        g_dw1h[i] = f16h(dw1[(size_t)k * NHID1 + n]);
        return;
    }
    i -= P_S3;
    if (i < P_S4) {                        // dw2: [K=256][512] -> [512][256]
        int n = i / NHID1, k = i - n * NHID1;
        g_dw2h[i] = f16h(dw2[(size_t)k * NFEAT + n]);
        return;
    }
    i -= P_S4;
    if (i < 256) {
        int jj = i >> 6, n = i & 63;
        const float* b = (jj == 0) ? b2l : (jj == 1) ? b2r : (jj == 2) ? b3l : b3r;
        g_bias23[i] = b[n];
    }
}

// ---------------- GEMM job plumbing ----------------
struct TJob  { const uint16_t* Bh; const float* bias; float* C; };
struct TJobs { TJob j[2]; };

// ---------------- gemmT: fp16 2-pass HMMA GEMM, 128x128 tile -------------
__global__ __launch_bounds__(256)
void gemmT(const float* __restrict__ A, TJobs jobs, int M, int K, int Nc,
           const float* __restrict__ bnG, const float* __restrict__ bnB) {
    const TJob jb = jobs.j[blockIdx.z];
    __shared__ __align__(16) uint16_t Ah[128][40], Al[128][40];
    __shared__ __align__(16) uint16_t Bh[128][40];
    int tid = threadIdx.x, lane = tid & 31, warp = tid >> 5;
    int row0 = blockIdx.y * 128, col0 = blockIdx.x * 128;
    int wm = (warp & 1) * 64, wn = (warp >> 1) * 32;
    int grp = lane >> 3, rl = lane & 7;
    float c[4][4][4];
#pragma unroll
    for (int mi = 0; mi < 4; mi++)
#pragma unroll
        for (int ni = 0; ni < 4; ni++)
#pragma unroll
            for (int e = 0; e < 4; e++) c[mi][ni][e] = 0.f;

    int ar = tid >> 1, kh = (tid & 1) * 16;
    int r = row0 + ar;
    bool va = r < M;

    for (int k0 = 0; k0 < K; k0 += 32) {
        const float* pa = A + (size_t)r * K + k0 + kh;
#pragma unroll
        for (int q = 0; q < 4; q++) {
            float4 v = va ? *(const float4*)(pa + q * 4) : make_float4(0.f, 0.f, 0.f, 0.f);
            if (bnG) {
                int ch = k0 + kh + q * 4;
                float4 mm = *(const float4*)(g_mean + ch);
                float4 rs = *(const float4*)(g_rstd + ch);
                float4 gg = *(const float4*)(bnG + ch);
                float4 bb = *(const float4*)(bnB + ch);
                v.x = fmaxf((v.x - mm.x) * rs.x * gg.x + bb.x, 0.f);
                v.y = fmaxf((v.y - mm.y) * rs.y * gg.y + bb.y, 0.f);
                v.z = fmaxf((v.z - mm.z) * rs.z * gg.z + bb.z, 0.f);
                v.w = fmaxf((v.w - mm.w) * rs.w * gg.w + bb.w, 0.f);
            }
            uint16_t h0, l0, h1, l1, h2, l2, h3, l3;
            f16split(v.x, h0, l0); f16split(v.y, h1, l1);
            f16split(v.z, h2, l2); f16split(v.w, h3, l3);
            *(uint32_t*)&Ah[ar][kh + q * 4]     = (uint32_t)h0 | ((uint32_t)h1 << 16);
            *(uint32_t*)&Ah[ar][kh + q * 4 + 2] = (uint32_t)h2 | ((uint32_t)h3 << 16);
            *(uint32_t*)&Al[ar][kh + q * 4]     = (uint32_t)l0 | ((uint32_t)l1 << 16);
            *(uint32_t*)&Al[ar][kh + q * 4 + 2] = (uint32_t)l2 | ((uint32_t)l3 << 16);
        }
        {
            const uint16_t* pbh = jb.Bh + (size_t)(col0 + ar) * K + k0 + kh;
            *(uint4*)&Bh[ar][kh]     = *(const uint4*)pbh;
            *(uint4*)&Bh[ar][kh + 8] = *(const uint4*)(pbh + 8);
        }
        __syncthreads();
#pragma unroll
        for (int pass = 0; pass < 2; pass++) {
            const uint16_t (*Aq)[40] = (pass == 1) ? Al : Ah;
#pragma unroll
            for (int k1 = 0; k1 < 32; k1 += 16) {
                uint32_t af[4][4], bf[4][2];
#pragma unroll
                for (int mi = 0; mi < 4; mi++) {
                    int arow = wm + mi * 16 + (grp & 1) * 8 + rl;
                    int acol = k1 + (grp >> 1) * 8;
                    ldsm_x4(af[mi][0], af[mi][1], af[mi][2], af[mi][3],
                            smem_u32(&Aq[arow][acol]));
                }
#pragma unroll
                for (int ni = 0; ni < 4; ni++) {
                    int brow = wn + ni * 8 + rl;
                    int bcol = k1 + (grp & 1) * 8;
                    ldsm_x2(bf[ni][0], bf[ni][1], smem_u32(&Bh[brow][bcol]));
                }
#pragma unroll
                for (int mi = 0; mi < 4; mi++)
#pragma unroll
                    for (int ni = 0; ni < 4; ni++)
                        mma_f16(c[mi][ni], af[mi][0], af[mi][1], af[mi][2], af[mi][3],
                                bf[ni][0], bf[ni][1]);
            }
        }
        __syncthreads();
    }
    int qr = lane >> 2, qc = 2 * (lane & 3);
#pragma unroll
    for (int mi = 0; mi < 4; mi++) {
#pragma unroll
        for (int half = 0; half < 2; half++) {
            int row = wm + mi * 16 + qr + half * 8;
            int rr = row0 + row;
            if (rr < M) {
                float* Crow = jb.C + (size_t)rr * Nc;
#pragma unroll
                for (int ni = 0; ni < 4; ni++) {
                    int cc = col0 + wn + ni * 8 + qc;
                    float2 p;
                    p.x = c[mi][ni][2 * half]     + __ldg(&jb.bias[cc]);
                    p.y = c[mi][ni][2 * half + 1] + __ldg(&jb.bias[cc + 1]);
                    *(float2*)&Crow[cc] = p;
                }
            }
        }
    }
}

// ---------------- gemmT64: same, 64x128 tile (better wave balance) --------
__global__ __launch_bounds__(256)
void gemmT64(const float* __restrict__ A, TJobs jobs, int M, int K, int Nc,
             const float* __restrict__ bnG, const float* __restrict__ bnB) {
    const TJob jb = jobs.j[blockIdx.z];
    __shared__ __align__(16) uint16_t Ah[64][40], Al[64][40];
    __shared__ __align__(16) uint16_t Bh[128][40];
    int tid = threadIdx.x, lane = tid & 31, warp = tid >> 5;
    int row0 = blockIdx.y * 64, col0 = blockIdx.x * 128;
    int wm = (warp & 1) * 32, wn = (warp >> 1) * 32;
    int grp = lane >> 3, rl = lane & 7;
    float c[2][4][4];
#pragma unroll
    for (int mi = 0; mi < 2; mi++)
#pragma unroll
        for (int ni = 0; ni < 4; ni++)
#pragma unroll
            for (int e = 0; e < 4; e++) c[mi][ni][e] = 0.f;

    int ar = tid >> 2, ks = (tid & 3) * 8;
    int br = tid >> 1, kb = (tid & 1) * 16;
    int r = row0 + ar;
    bool va = r < M;

    for (int k0 = 0; k0 < K; k0 += 32) {
        const float* pa = A + (size_t)r * K + k0 + ks;
#pragma unroll
        for (int q = 0; q < 2; q++) {
            float4 v = va ? *(const float4*)(pa + q * 4) : make_float4(0.f, 0.f, 0.f, 0.f);
            if (bnG) {
                int ch = k0 + ks + q * 4;
                float4 mm = *(const float4*)(g_mean + ch);
                float4 rs = *(const float4*)(g_rstd + ch);
                float4 gg = *(const float4*)(bnG + ch);
                float4 bb = *(const float4*)(bnB + ch);
                v.x = fmaxf((v.x - mm.x) * rs.x * gg.x + bb.x, 0.f);
                v.y = fmaxf((v.y - mm.y) * rs.y * gg.y + bb.y, 0.f);
                v.z = fmaxf((v.z - mm.z) * rs.z * gg.z + bb.z, 0.f);
                v.w = fmaxf((v.w - mm.w) * rs.w * gg.w + bb.w, 0.f);
            }
            uint16_t h0, l0, h1, l1, h2, l2, h3, l3;
            f16split(v.x, h0, l0); f16split(v.y, h1, l1);
            f16split(v.z, h2, l2); f16split(v.w, h3, l3);
            *(uint32_t*)&Ah[ar][ks + q * 4]     = (uint32_t)h0 | ((uint32_t)h1 << 16);
            *(uint32_t*)&Ah[ar][ks + q * 4 + 2] = (uint32_t)h2 | ((uint32_t)h3 << 16);
            *(uint32_t*)&Al[ar][ks + q * 4]     = (uint32_t)l0 | ((uint32_t)l1 << 16);
            *(uint32_t*)&Al[ar][ks + q * 4 + 2] = (uint32_t)l2 | ((uint32_t)l3 << 16);
        }
        {
            const uint16_t* pbh = jb.Bh + (size_t)(col0 + br) * K + k0 + kb;
            *(uint4*)&Bh[br][kb]     = *(const uint4*)pbh;
            *(uint4*)&Bh[br][kb + 8] = *(const uint4*)(pbh + 8);
        }
        __syncthreads();
#pragma unroll
        for (int pass = 0; pass < 2; pass++) {
            const uint16_t (*Aq)[40] = (pass == 1) ? Al : Ah;
#pragma unroll
            for (int k1 = 0; k1 < 32; k1 += 16) {
                uint32_t af[2][4], bf[4][2];
#pragma unroll
                for (int mi = 0; mi < 2; mi++) {
                    int arow = wm + mi * 16 + (grp & 1) * 8 + rl;
                    int acol = k1 + (grp >> 1) * 8;
                    ldsm_x4(af[mi][0], af[mi][1], af[mi][2], af[mi][3],
                            smem_u32(&Aq[arow][acol]));
                }
#pragma unroll
                for (int ni = 0; ni < 4; ni++) {
                    int brow = wn + ni * 8 + rl;
                    int bcol = k1 + (grp & 1) * 8;
                    ldsm_x2(bf[ni][0], bf[ni][1], smem_u32(&Bh[brow][bcol]));
                }
#pragma unroll
                for (int mi = 0; mi < 2; mi++)
#pragma unroll
                    for (int ni = 0; ni < 4; ni++)
                        mma_f16(c[mi][ni], af[mi][0], af[mi][1], af[mi][2], af[mi][3],
                                bf[ni][0], bf[ni][1]);
            }
        }
        __syncthreads();
    }
    int qr = lane >> 2, qc = 2 * (lane & 3);
#pragma unroll
    for (int mi = 0; mi < 2; mi++) {
#pragma unroll
        for (int half = 0; half < 2; half++) {
            int row = wm + mi * 16 + qr + half * 8;
            int rr = row0 + row;
            if (rr < M) {
                float* Crow = jb.C + (size_t)rr * Nc;
#pragma unroll
                for (int ni = 0; ni < 4; ni++) {
                    int cc = col0 + wn + ni * 8 + qc;
                    float2 p;
                    p.x = c[mi][ni][2 * half]     + __ldg(&jb.bias[cc]);
                    p.y = c[mi][ni][2 * half + 1] + __ldg(&jb.bias[cc + 1]);
                    *(float2*)&Crow[cc] = p;
                }
            }
        }
    }
}

// ---------------- gemmP: pre-split fp16 A (hi/lo), 128x128 tile ----------
__global__ __launch_bounds__(256)
void gemmP(const uint16_t* __restrict__ Ahg, const uint16_t* __restrict__ Alg,
           const uint16_t* __restrict__ Bhg, const float* __restrict__ bias,
           float* __restrict__ C, int M, int K, int Nc) {
    __shared__ __align__(16) uint16_t Ah[128][40], Al[128][40];
    __shared__ __align__(16) uint16_t Bh[128][40];
    int tid = threadIdx.x, lane = tid & 31, warp = tid >> 5;
    int row0 = blockIdx.y * 128, col0 = blockIdx.x * 128;
    int wm = (warp & 1) * 64, wn = (warp >> 1) * 32;
    int grp = lane >> 3, rl = lane & 7;
    float c[4][4][4];
#pragma unroll
    for (int mi = 0; mi < 4; mi++)
#pragma unroll
        for (int ni = 0; ni < 4; ni++)
#pragma unroll
            for (int e = 0; e < 4; e++) c[mi][ni][e] = 0.f;

    int ar = tid >> 1, kh = (tid & 1) * 16;
    int r = row0 + ar;
    bool va = r < M;
    uint4 z4 = make_uint4(0, 0, 0, 0);

    for (int k0 = 0; k0 < K; k0 += 32) {
        {
            const uint16_t* ph = Ahg + (size_t)r * K + k0 + kh;
            const uint16_t* pl = Alg + (size_t)r * K + k0 + kh;
            *(uint4*)&Ah[ar][kh]     = va ? *(const uint4*)ph : z4;
            *(uint4*)&Ah[ar][kh + 8] = va ? *(const uint4*)(ph + 8) : z4;
            *(uint4*)&Al[ar][kh]     = va ? *(const uint4*)pl : z4;
            *(uint4*)&Al[ar][kh + 8] = va ? *(const uint4*)(pl + 8) : z4;
        }
        {
            const uint16_t* pbh = Bhg + (size_t)(col0 + ar) * K + k0 + kh;
            *(uint4*)&Bh[ar][kh]     = *(const uint4*)pbh;
            *(uint4*)&Bh[ar][kh + 8] = *(const uint4*)(pbh + 8);
        }
        __syncthreads();
#pragma unroll
        for (int pass = 0; pass < 2; pass++) {
            const uint16_t (*Aq)[40] = (pass == 1) ? Al : Ah;
#pragma unroll
            for (int k1 = 0; k1 < 32; k1 += 16) {
                uint32_t af[4][4], bf[4][2];
#pragma unroll
                for (int mi = 0; mi < 4; mi++) {
                    int arow = wm + mi * 16 + (grp & 1) * 8 + rl;
                    int acol = k1 + (grp >> 1) * 8;
                    ldsm_x4(af[mi][0], af[mi][1], af[mi][2], af[mi][3],
                            smem_u32(&Aq[arow][acol]));
                }
#pragma unroll
                for (int ni = 0; ni < 4; ni++) {
                    int brow = wn + ni * 8 + rl;
                    int bcol = k1 + (grp & 1) * 8;
                    ldsm_x2(bf[ni][0], bf[ni][1], smem_u32(&Bh[brow][bcol]));
                }
#pragma unroll
                for (int mi = 0; mi < 4; mi++)
#pragma unroll
                    for (int ni = 0; ni < 4; ni++)
                        mma_f16(c[mi][ni], af[mi][0], af[mi][1], af[mi][2], af[mi][3],
                                bf[ni][0], bf[ni][1]);
            }
        }
        __syncthreads();
    }
    int qr = lane >> 2, qc = 2 * (lane & 3);
#pragma unroll
    for (int mi = 0; mi < 4; mi++) {
#pragma unroll
        for (int half = 0; half < 2; half++) {
            int row = wm + mi * 16 + qr + half * 8;
            int rr = row0 + row;
            if (rr < M) {
                float* Crow = C + (size_t)rr * Nc;
#pragma unroll
                for (int ni = 0; ni < 4; ni++) {
                    int cc = col0 + wn + ni * 8 + qc;
                    float2 p;
                    p.x = c[mi][ni][2 * half]     + __ldg(&bias[cc]);
                    p.y = c[mi][ni][2 * half + 1] + __ldg(&bias[cc + 1]);
                    *(float2*)&Crow[cc] = p;
                }
            }
        }
    }
}

// ---------------- GAT layer 1: fused online-softmax (C=128) ---------------
struct AJob  { const float* xl; const float* xr; int ld; const float* att;
               const float* bias; float* out; int ldo; };
struct AJobs { AJob j[2]; };

template <int C>
__global__ void gat_fused(AJobs jobs) {
    constexpr int W   = C / 32;
    constexpr int NL  = (C / 4 < 32) ? C / 4 : 32;
    constexpr int GPW = 32 / NL;
    constexpr int NG  = W * GPW;
    const AJob jb = jobs.j[blockIdx.y];
    int t = blockIdx.x;
    int tid = threadIdx.x, lane = tid & 31, warp = tid >> 5;
    int sub = lane / NL, lg = lane & (NL - 1);
    int gid = warp * GPW + sub;
    uint32_t gmask = ((NL < 32) ? ((1u << NL) - 1u) << (sub * NL) : 0xffffffffu);

    __shared__ float4 s_xr4[C / 4], s_att4[C / 4];
    __shared__ float  s_m[NG], s_s[NG];
    __shared__ float4 s_acc[NG][NL];
    if (tid < C / 4) {
        s_xr4[tid]  = *(const float4*)(jb.xr + (size_t)t * jb.ld + tid * 4);
        s_att4[tid] = *(const float4*)(jb.att + tid * 4);
    }
    int beg = g_rowptr[t];
    int deg = g_rowptr[t + 1] - beg;
    __syncthreads();

    float4 xr4 = s_xr4[lg];
    float4 at4 = s_att4[lg];
    const float* xl = jb.xl;
    int ld = jb.ld;

    float m0 = -1e30f, z0 = 0.f;
    float m1 = -1e30f, z1 = 0.f;
    float4 a0 = make_float4(0.f, 0.f, 0.f, 0.f), a1 = a0;

    int j = gid;
    for (; j + NG < deg; j += 2 * NG) {
        int sA = g_srclist[beg + j];
        int sB = g_srclist[beg + j + NG];
        float4 vA = *(const float4*)(xl + (size_t)sA * ld + lg * 4);
        float4 vB = *(const float4*)(xl + (size_t)sB * ld + lg * 4);
        float pA, pB;
        {
            float a = vA.x + xr4.x; a = fmaxf(a, NEG_SLOPE * a);
            float b = vA.y + xr4.y; b = fmaxf(b, NEG_SLOPE * b);
            float c = vA.z + xr4.z; c = fmaxf(c, NEG_SLOPE * c);
            float d = vA.w + xr4.w; d = fmaxf(d, NEG_SLOPE * d);
            pA = at4.x * a + at4.y * b + at4.z * c + at4.w * d;
            a = vB.x + xr4.x; a = fmaxf(a, NEG_SLOPE * a);
            b = vB.y + xr4.y; b = fmaxf(b, NEG_SLOPE * b);
            c = vB.z + xr4.z; c = fmaxf(c, NEG_SLOPE * c);
            d = vB.w + xr4.w; d = fmaxf(d, NEG_SLOPE * d);
            pB = at4.x * a + at4.y * b + at4.z * c + at4.w * d;
        }
#pragma unroll
        for (int o = NL / 2; o; o >>= 1) {
            pA += __shfl_xor_sync(gmask, pA, o);
            pB += __shfl_xor_sync(gmask, pB, o);
        }
        float mn0 = fmaxf(m0, pA);
        float sc0 = __expf(m0 - mn0);
        float w0  = __expf(pA - mn0);
        z0 = z0 * sc0 + w0;
        a0.x = a0.x * sc0 + w0 * vA.x;
        a0.y = a0.y * sc0 + w0 * vA.y;
        a0.z = a0.z * sc0 + w0 * vA.z;
        a0.w = a0.w * sc0 + w0 * vA.w;
        m0 = mn0;
        float mn1 = fmaxf(m1, pB);
        float sc1 = __expf(m1 - mn1);
        float w1  = __expf(pB - mn1);
        z1 = z1 * sc1 + w1;
        a1.x = a1.x * sc1 + w1 * vB.x;
        a1.y = a1.y * sc1 + w1 * vB.y;
        a1.z = a1.z * sc1 + w1 * vB.z;
        a1.w = a1.w * sc1 + w1 * vB.w;
        m1 = mn1;
    }
    if (j < deg) {
        int sA = g_srclist[beg + j];
        float4 vA = *(const float4*)(xl + (size_t)sA * ld + lg * 4);
        float a = vA.x + xr4.x; a = fmaxf(a, NEG_SLOPE * a);
        float b = vA.y + xr4.y; b = fmaxf(b, NEG_SLOPE * b);
        float c = vA.z + xr4.z; c = fmaxf(c, NEG_SLOPE * c);
        float d = vA.w + xr4.w; d = fmaxf(d, NEG_SLOPE * d);
        float pA = at4.x * a + at4.y * b + at4.z * c + at4.w * d;
#pragma unroll
        for (int o = NL / 2; o; o >>= 1) pA += __shfl_xor_sync(gmask, pA, o);
        float mn0 = fmaxf(m0, pA);
        float sc0 = __expf(m0 - mn0);
        float w0  = __expf(pA - mn0);
        z0 = z0 * sc0 + w0;
        a0.x = a0.x * sc0 + w0 * vA.x;
        a0.y = a0.y * sc0 + w0 * vA.y;
        a0.z = a0.z * sc0 + w0 * vA.z;
        a0.w = a0.w * sc0 + w0 * vA.w;
        m0 = mn0;
    }
    {
        float M = fmaxf(m0, m1);
        float e0 = __expf(m0 - M), e1 = __expf(m1 - M);
        z0 = z0 * e0 + z1 * e1;
        a0.x = a0.x * e0 + a1.x * e1;
        a0.y = a0.y * e0 + a1.y * e1;
        a0.z = a0.z * e0 + a1.z * e1;
        a0.w = a0.w * e0 + a1.w * e1;
        m0 = M;
    }
    if (lg == 0) { s_m[gid] = m0; s_s[gid] = z0; }
    s_acc[gid][lg] = a0;
    __syncthreads();

    if (tid < NL) {
        float M = s_m[0];
#pragma unroll
        for (int g = 1; g < NG; g++) M = fmaxf(M, s_m[g]);
        float zt = 0.f;
        float4 at = make_float4(0.f, 0.f, 0.f, 0.f);
#pragma unroll
        for (int g = 0; g < NG; g++) {
            float f = __expf(s_m[g] - M);
            zt += s_s[g] * f;
            float4 q = s_acc[g][tid];
            at.x += q.x * f; at.y += q.y * f; at.z += q.z * f; at.w += q.w * f;
        }
        float inv = 1.f / zt;
        float4 b4 = *(const float4*)(jb.bias + tid * 4);
        float4 o4;
        o4.x = at.x * inv + b4.x;
        o4.y = at.y * inv + b4.y;
        o4.z = at.z * inv + b4.z;
        o4.w = at.w * inv + b4.w;
        *(float4*)(jb.out + (size_t)t * jb.ldo + tid * 4) = o4;
    }
}

// ---------------- GAT layers 2+3 merged: one block per node ---------------
// block = 128 threads, 4 warps. Lane halves: lanes 0-15 -> mu (job 0, cols
// 0-63 xl / 64-127 xr), lanes 16-31 -> logvar (job 1, cols 128-191 / 192-255).
// One warp-wide load per edge covers both jobs' gathers; srclist read once.
__global__ void gat23_fused(const float* __restrict__ x23,
                            const float* __restrict__ a2, const float* __restrict__ bias2,
                            const float* __restrict__ a3, const float* __restrict__ bias3,
                            float* __restrict__ mu, float* __restrict__ lv) {
    int t = blockIdx.x;
    int tid = threadIdx.x, lane = tid & 31, warp = tid >> 5;
    int half = lane >> 4, lg = lane & 15;

    __shared__ float4 s_xr4[2][16], s_att4[2][16];
    __shared__ float  s_m[2][4], s_s[2][4];
    __shared__ float4 s_acc[2][4][16];
    if (tid < 32) {
        int h = tid >> 4, q = tid & 15;
        s_xr4[h][q]  = *(const float4*)(x23 + (size_t)t * 256 + h * 128 + 64 + q * 4);
        s_att4[h][q] = *(const float4*)((h ? a3 : a2) + q * 4);
    }
    int beg = g_rowptr[t];
    int deg = g_rowptr[t + 1] - beg;
    __syncthreads();

    float4 xr4 = s_xr4[half][lg];
    float4 at4 = s_att4[half][lg];
    int coff = half * 128 + lg * 4;      // xl column offset for this lane

    float m0 = -1e30f, z0 = 0.f;
    float m1 = -1e30f, z1 = 0.f;
    float4 a0 = make_float4(0.f, 0.f, 0.f, 0.f), a1 = a0;

    int j = warp;
    for (; j + 4 < deg; j += 8) {
        int sA = g_srclist[beg + j];
        int sB = g_srclist[beg + j + 4];
        float4 vA = *(const float4*)(x23 + (size_t)sA * 256 + coff);
        float4 vB = *(const float4*)(x23 + (size_t)sB * 256 + coff);
        float pA, pB;
        {
            float a = vA.x + xr4.x; a = fmaxf(a, NEG_SLOPE * a);
            float b = vA.y + xr4.y; b = fmaxf(b, NEG_SLOPE * b);
            float c = vA.z + xr4.z; c = fmaxf(c, NEG_SLOPE * c);
            float d = vA.w + xr4.w; d = fmaxf(d, NEG_SLOPE * d);
            pA = at4.x * a + at4.y * b + at4.z * c + at4.w * d;
            a = vB.x + xr4.x; a = fmaxf(a, NEG_SLOPE * a);
            b = vB.y + xr4.y; b = fmaxf(b, NEG_SLOPE * b);
            c = vB.z + xr4.z; c = fmaxf(c, NEG_SLOPE * c);
            d = vB.w + xr4.w; d = fmaxf(d, NEG_SLOPE * d);
            pB = at4.x * a + at4.y * b + at4.z * c + at4.w * d;
        }
#pragma unroll
        for (int o = 8; o; o >>= 1) {
            pA += __shfl_xor_sync(0xffffffffu, pA, o);
            pB += __shfl_xor_sync(0xffffffffu, pB, o);
        }
        float mn0 = fmaxf(m0, pA);
        float sc0 = __expf(m0 - mn0);
        float w0  = __expf(pA - mn0);
        z0 = z0 * sc0 + w0;
        a0.x = a0.x * sc0 + w0 * vA.x;
        a0.y = a0.y * sc0 + w0 * vA.y;
        a0.z = a0.z * sc0 + w0 * vA.z;
        a0.w = a0.w * sc0 + w0 * vA.w;
        m0 = mn0;
        float mn1 = fmaxf(m1, pB);
        float sc1 = __expf(m1 - mn1);
        float w1  = __expf(pB - mn1);
        z1 = z1 * sc1 + w1;
        a1.x = a1.x * sc1 + w1 * vB.x;
        a1.y = a1.y * sc1 + w1 * vB.y;
        a1.z = a1.z * sc1 + w1 * vB.z;
        a1.w = a1.w * sc1 + w1 * vB.w;
        m1 = mn1;
    }
    if (j < deg) {
        int sA = g_srclist[beg + j];
        float4 vA = *(const float4*)(x23 + (size_t)sA * 256 + coff);
        float a = vA.x + xr4.x; a = fmaxf(a, NEG_SLOPE * a);
        float b = vA.y + xr4.y; b = fmaxf(b, NEG_SLOPE * b);
        float c = vA.z + xr4.z; c = fmaxf(c, NEG_SLOPE * c);
        float d = vA.w + xr4.w; d = fmaxf(d, NEG_SLOPE * d);
        float pA = at4.x * a + at4.y * b + at4.z * c + at4.w * d;
#pragma unroll
        for (int o = 8; o; o >>= 1) pA += __shfl_xor_sync(0xffffffffu, pA, o);
        float mn0 = fmaxf(m0, pA);
        float sc0 = __expf(m0 - mn0);
        float w0  = __expf(pA - mn0);
        z0 = z0 * sc0 + w0;
        a0.x = a0.x * sc0 + w0 * vA.x;
        a0.y = a0.y * sc0 + w0 * vA.y;
        a0.z = a0.z * sc0 + w0 * vA.z;
        a0.w = a0.w * sc0 + w0 * vA.w;
        m0 = mn0;
    }
    {
        float M = fmaxf(m0, m1);
        float e0 = __expf(m0 - M), e1 = __expf(m1 - M);
        z0 = z0 * e0 + z1 * e1;
        a0.x = a0.x * e0 + a1.x * e1;
        a0.y = a0.y * e0 + a1.y * e1;
        a0.z = a0.z * e0 + a1.z * e1;
        a0.w = a0.w * e0 + a1.w * e1;
        m0 = M;
    }
    if (lg == 0) { s_m[half][warp] = m0; s_s[half][warp] = z0; }
    s_acc[half][warp][lg] = a0;
    __syncthreads();

    if (tid < 32) {
        int h = tid >> 4, q = tid & 15;
        float M = s_m[h][0];
#pragma unroll
        for (int g = 1; g < 4; g++) M = fmaxf(M, s_m[h][g]);
        float zt = 0.f;
        float4 at = make_float4(0.f, 0.f, 0.f, 0.f);
#pragma unroll
        for (int g = 0; g < 4; g++) {
            float f = __expf(s_m[h][g] - M);
            zt += s_s[h][g] * f;
            float4 qq = s_acc[h][g][q];
            at.x += qq.x * f; at.y += qq.y * f; at.z += qq.z * f; at.w += qq.w * f;
        }
        float inv = 1.f / zt;
        float4 b4 = *(const float4*)((h ? bias3 : bias2) + q * 4);
        float4 o4;
        o4.x = at.x * inv + b4.x;
        o4.y = at.y * inv + b4.y;
        o4.z = at.z * inv + b4.z;
        o4.w = at.w * inv + b4.w;
        float* op = h ? lv : mu;
        *(float4*)(op + (size_t)t * 64 + q * 4) = o4;
    }
}

// ---------------- batch norm stats ----------------
template <int C>
__global__ void bn_stats(const float* __restrict__ h) {
    int c = blockIdx.x;
    int tid = threadIdx.x;
    float s = 0.f, s2 = 0.f;
    for (int r = tid; r < NN; r += 256) {
        float v = h[(size_t)r * C + c];
        s += v; s2 += v * v;
    }
    __shared__ float sh[8], sh2[8];
#pragma unroll
    for (int o = 16; o; o >>= 1) {
        s  += __shfl_xor_sync(0xffffffffu, s,  o);
        s2 += __shfl_xor_sync(0xffffffffu, s2, o);
    }
    if ((tid & 31) == 0) { sh[tid >> 5] = s; sh2[tid >> 5] = s2; }
    __syncthreads();
    if (tid == 0) {
        float ts = 0.f, ts2 = 0.f;
        for (int w = 0; w < 8; w++) { ts += sh[w]; ts2 += sh2[w]; }
        float mean = ts / NN;
        float var = ts2 / NN - mean * mean;
        g_mean[c] = mean;
        g_rstd[c] = rsqrtf(var + BN_EPS);
    }
}

// ---------------- reparameterize + fp16 pre-split ----------------
__global__ void k_reparam(const float* __restrict__ eps, float* __restrict__ out) {
    int i = blockIdx.x * blockDim.x + threadIdx.x;
    if (i >= NN * NHID2) return;
    float mu = out[MU_OFF + i];
    float lv = out[LV_OFF + i];
    float e = eps[i] * __expf(lv) + mu;
    out[EMB_OFF + i] = e;
    uint16_t h, l;
    f16split(e, h, l);
    g_ebh[i] = h;
    g_ebl[i] = l;
}

// ---------------- readj = sigmoid(emb @ emb^T), fp16 2-pass HMMA ----------
#define GP 72
#define G_AHI 0
#define G_ALO (G_AHI + 128 * GP * 2)
#define G_BHI (G_ALO + 128 * GP * 2)
#define G_SMEM 65536
#define MTG 79

__global__ __launch_bounds__(256)
void gram_hmma(const uint16_t* __restrict__ Eh, const uint16_t* __restrict__ El,
               float* __restrict__ out) {
    int bid = blockIdx.x;
    int by = (int)(0.5f * (2.f * MTG + 1.f) -
                   sqrtf((2.f * MTG + 1.f) * (2.f * MTG + 1.f) * 0.25f - 2.f * (float)bid));
    if (by < 0) by = 0;
    if (by > MTG - 1) by = MTG - 1;
    int start = by * MTG - (by * (by - 1)) / 2;
    while (start > bid) { by--; start = by * MTG - (by * (by - 1)) / 2; }
    while (bid >= start + (MTG - by)) { by++; start = by * MTG - (by * (by - 1)) / 2; }
    int bx = by + (bid - start);

    extern __shared__ __align__(16) char smem[];
    uint32_t sb = smem_u32(smem);
    int tid = threadIdx.x, lane = tid & 31, warp = tid >> 5;
    int row0 = by * 128, col0 = bx * 128;

    {
        int rrow = tid & 127;
        uint4 z = make_uint4(0, 0, 0, 0);
        if (tid < 128) {
            int rA = row0 + rrow;
            bool va = rA < NN;
            const uint4* ph = (const uint4*)(Eh + (size_t)rA * 64);
            const uint4* pl = (const uint4*)(El + (size_t)rA * 64);
#pragma unroll
            for (int q = 0; q < 8; q++) {
                uint32_t off = (rrow * GP + q * 8) * 2;
                *(uint4*)(smem + G_AHI + off) = va ? ph[q] : z;
                *(uint4*)(smem + G_ALO + off) = va ? pl[q] : z;
            }
        } else {
            int rB = col0 + rrow;
            bool vb = rB < NN;
            const uint4* ph = (const uint4*)(Eh + (size_t)rB * 64);
#pragma unroll
            for (int q = 0; q < 8; q++) {
                uint32_t off = (rrow * GP + q * 8) * 2;
                *(uint4*)(smem + G_BHI + off) = vb ? ph[q] : z;
            }
        }
    }
    __syncthreads();

    int wm = (warp & 1) * 64;
    int wn = (warp >> 1) * 32;
    float c[4][4][4];
#pragma unroll
    for (int mi = 0; mi < 4; mi++)
#pragma unroll
        for (int ni = 0; ni < 4; ni++)
#pragma unroll
            for (int e = 0; e < 4; e++) c[mi][ni][e] = 0.f;

    int grp = lane >> 3, rl = lane & 7;
#pragma unroll
    for (int pass = 0; pass < 2; pass++) {
        uint32_t aBase = sb + ((pass == 1) ? G_ALO : G_AHI);
        uint32_t bBase = sb + G_BHI;
#pragma unroll
        for (int k0 = 0; k0 < 64; k0 += 16) {
            uint32_t af[4][4], bf[4][2];
#pragma unroll
            for (int mi = 0; mi < 4; mi++) {
                int arow = wm + mi * 16 + (grp & 1) * 8 + rl;
                int acol = k0 + (grp >> 1) * 8;
                ldsm_x4(af[mi][0], af[mi][1], af[mi][2], af[mi][3],
                        aBase + (arow * GP + acol) * 2);
            }
#pragma unroll
            for (int ni = 0; ni < 4; ni++) {
                int brow = wn + ni * 8 + rl;
                int bcol = k0 + (grp & 1) * 8;
                ldsm_x2(bf[ni][0], bf[ni][1], bBase + (brow * GP + bcol) * 2);
            }
#pragma unroll
            for (int mi = 0; mi < 4; mi++)
#pragma unroll
                for (int ni = 0; ni < 4; ni++)
                    mma_f16(c[mi][ni], af[mi][0], af[mi][1], af[mi][2], af[mi][3],
                            bf[ni][0], bf[ni][1]);
        }
    }
    __syncthreads();

    float* stag = (float*)smem;
    bool diag = (bx == by);
    int qr = lane >> 2, qc = 2 * (lane & 3);
#pragma unroll
    for (int mi = 0; mi < 4; mi++) {
#pragma unroll
        for (int ni = 0; ni < 4; ni++) {
#pragma unroll
            for (int half = 0; half < 2; half++) {
                int row = wm + mi * 16 + qr + half * 8;
                int col = wn + ni * 8 + qc;
                float v0 = 1.f / (1.f + __expf(-c[mi][ni][2 * half]));
                float v1 = 1.f / (1.f + __expf(-c[mi][ni][2 * half + 1]));
                int r = row0 + row, cc = col0 + col;
                if (r < NN && cc < NN)
                    *(float2*)(out + (size_t)r * NN + cc) = make_float2(v0, v1);
                if (!diag) {
                    int s = row & 31;
                    stag[row * 128 + (col ^ s)] = v0;
                    stag[row * 128 + ((col + 1) ^ s)] = v1;
                }
            }
        }
    }
    if (diag) return;
    __syncthreads();

    for (int cc = warp; cc < 128; cc += 8) {
        int cgl = col0 + cc;
        if (cgl >= NN) continue;
        float* mrow = out + (size_t)cgl * NN + row0;
#pragma unroll
        for (int ib = 0; ib < 128; ib += 32) {
            int i = ib + lane;
            if (row0 + i < NN)
                mrow[i] = stag[i * 128 + (cc ^ (i & 31))];
        }
    }
}

// ---------------- launch ----------------
extern "C" void kernel_launch(void* const* d_in, const int* in_sizes, int n_in,
                              void* d_out, int out_size) {
    const float* x   = (const float*)d_in[0];
    const int*   ei  = (const int*)  d_in[1];
    const float* eps = (const float*)d_in[2];
    const float* w1l = (const float*)d_in[3];
    const float* b1l = (const float*)d_in[4];
    const float* w1r = (const float*)d_in[5];
    const float* b1r = (const float*)d_in[6];
    const float* a1  = (const float*)d_in[7];
    const float* bias1 = (const float*)d_in[8];
    const float* bn1_g = (const float*)d_in[9];
    const float* bn1_b = (const float*)d_in[10];
    const float* w2l = (const float*)d_in[11];
    const float* b2l = (const float*)d_in[12];
    const float* w2r = (const float*)d_in[13];
    const float* b2r = (const float*)d_in[14];
    const float* a2  = (const float*)d_in[15];
    const float* bias2 = (const float*)d_in[16];
    const float* w3l = (const float*)d_in[17];
    const float* b3l = (const float*)d_in[18];
    const float* w3r = (const float*)d_in[19];
    const float* b3r = (const float*)d_in[20];
    const float* a3  = (const float*)d_in[21];
    const float* bias3 = (const float*)d_in[22];
    const float* dw1 = (const float*)d_in[23];
    const float* db1 = (const float*)d_in[24];
    const float* dbn_g = (const float*)d_in[25];
    const float* dbn_b = (const float*)d_in[26];
    const float* dw2 = (const float*)d_in[27];
    const float* db2 = (const float*)d_in[28];
    float* out = (float*)d_out;

    float *p_xl1, *p_xr1, *p_h, *p_x23, *p_d, *p_b23;
    cudaGetSymbolAddress((void**)&p_xl1, g_xl1);
    cudaGetSymbolAddress((void**)&p_xr1, g_xr1);
    cudaGetSymbolAddress((void**)&p_h,   g_h);
    cudaGetSymbolAddress((void**)&p_x23, g_x23);
    cudaGetSymbolAddress((void**)&p_d,   g_d);
    cudaGetSymbolAddress((void**)&p_b23, g_bias23);
    uint16_t *p_w1lh, *p_w1rh, *p_w23h, *p_dw1h, *p_dw2h, *p_ebh, *p_ebl;
    cudaGetSymbolAddress((void**)&p_w1lh, g_w1lh);
    cudaGetSymbolAddress((void**)&p_w1rh, g_w1rh);
    cudaGetSymbolAddress((void**)&p_w23h, g_w23h);
    cudaGetSymbolAddress((void**)&p_dw1h, g_dw1h);
    cudaGetSymbolAddress((void**)&p_dw2h, g_dw2h);
    cudaGetSymbolAddress((void**)&p_ebh,  g_ebh);
    cudaGetSymbolAddress((void**)&p_ebl,  g_ebl);

    cudaFuncSetAttribute(gram_hmma, cudaFuncAttributeMaxDynamicSharedMemorySize, G_SMEM);

    static cudaStream_t s_side = nullptr;
    static cudaEvent_t evA = nullptr, evB = nullptr, evC = nullptr, evD = nullptr;
    if (!s_side) {
        cudaStreamCreateWithFlags(&s_side, cudaStreamNonBlocking);
        cudaEventCreateWithFlags(&evA, cudaEventDisableTiming);
        cudaEventCreateWithFlags(&evB, cudaEventDisableTiming);
        cudaEventCreateWithFlags(&evC, cudaEventDisableTiming);
        cudaEventCreateWithFlags(&evD, cudaEventDisableTiming);
    }

    const int MT  = (NN + 127) / 128;   // 79
    const int MT64 = (NN + 63) / 64;    // 157

    // ---- fork: CSR build on side stream ----
    cudaEventRecord(evA, 0);
    cudaStreamWaitEvent(s_side, evA, 0);
    k_zero_counts<<<(NN + 255) / 256, 256, 0, s_side>>>();
    k_count_deg<<<(NE + 255) / 256, 256, 0, s_side>>>(ei);
    k_scan_deg<<<1, 1024, 0, s_side>>>();
    k_fill_list<<<(NE + 255) / 256, 256, 0, s_side>>>(ei);
    cudaEventRecord(evB, s_side);

    // ---- main: fused prep + layer-1 GEMM ----
    k_prep<<<(P_TOT + 255) / 256, 256>>>(w1l, w1r, w2l, w2r, w3l, w3r, dw1, dw2,
                                         b2l, b2r, b3l, b3r);
    {
        TJobs j1 = {{ { p_w1lh, b1l, p_xl1 }, { p_w1rh, b1r, p_xr1 } }};
        gemmT64<<<dim3(1, MT64, 2), 256>>>(x, j1, NN, NFEAT, H1, nullptr, nullptr);
    }
    cudaStreamWaitEvent(0, evB, 0);   // join CSR

    // ---- GAT layer 1 (fused online softmax) -> BN stats ----
    {
        AJobs aj = {{ { p_xl1, p_xr1, H1, a1, bias1, p_h, H1 }, {} }};
        gat_fused<H1><<<dim3(NN, 1), H1>>>(aj);
    }
    bn_stats<H1><<<H1, 256>>>(p_h);

    // ---- layers 2 & 3 packed GEMM (BN+ReLU fused on A) ----
    {
        TJobs j2 = {{ { p_w23h, p_b23, p_x23 }, {} }};
        gemmT<<<dim3(2, MT, 1), 256>>>(p_h, j2, NN, H1, 256, bn1_g, bn1_b);
    }

    // ---- GAT layers 2+3 merged (one block per node) ----
    gat23_fused<<<NN, 128>>>(p_x23, a2, bias2, a3, bias3, out + MU_OFF, out + LV_OFF);

    // ---- reparameterize + fp16 pre-split ----
    k_reparam<<<(NN * NHID2 + 255) / 256, 256>>>(eps, out);

    // ---- fork: decoder MLP on side stream, gram on main ----
    cudaEventRecord(evC, 0);
    cudaStreamWaitEvent(s_side, evC, 0);
    gemmP<<<dim3(2, MT, 1), 256, 0, s_side>>>(p_ebh, p_ebl, p_dw1h, db1, p_d,
                                              NN, NHID2, NHID1);
    bn_stats<NHID1><<<NHID1, 256, 0, s_side>>>(p_d);
    {
        TJobs jd = {{ { p_dw2h, db2, out + REX_OFF }, {} }};
        gemmT<<<dim3(4, MT, 1), 256, 0, s_side>>>(p_d, jd, NN, NHID1, NFEAT,
                                                  dbn_g, dbn_b);
    }
    cudaEventRecord(evD, s_side);

    gram_hmma<<<MT * (MT + 1) / 2, 256, G_SMEM>>>(p_ebh, p_ebl, out + READJ_OFF);

    cudaStreamWaitEvent(0, evD, 0);   // join decoder
}

// round 13
// speedup vs baseline: 2.2769x; 1.0767x over previous
#include <cuda_runtime.h>
#include <cuda_fp16.h>
#include <cstdint>
#include <math.h>

#define NN     10000
#define EE     320000
#define NE     (EE + NN)     // with self loops
#define NFEAT  512
#define NHID1  256
#define NHID2  64
#define H1     128           // 2*nhid2
#define NEG_SLOPE 0.2f
#define BN_EPS 1e-5f

// output layout (flattened tuple: emb, re_x, readj, mu, logvar)
#define EMB_OFF   ((size_t)0)
#define REX_OFF   ((size_t)NN * NHID2)
#define READJ_OFF (REX_OFF + (size_t)NN * NFEAT)
#define MU_OFF    (READJ_OFF + (size_t)NN * NN)
#define LV_OFF    (MU_OFF + (size_t)NN * NHID2)

typedef unsigned long long u64;

// ---------------- warp MMA helpers (baseline PTX, works on sm_103) --------
__device__ __forceinline__ uint32_t smem_u32(const void* p) {
    uint32_t a;
    asm("{ .reg .u64 t; cvta.to.shared.u64 t, %1; cvt.u32.u64 %0, t; }" : "=r"(a) : "l"(p));
    return a;
}
__device__ __forceinline__ void ldsm_x4(uint32_t& r0, uint32_t& r1, uint32_t& r2, uint32_t& r3, uint32_t addr) {
    asm volatile("ldmatrix.sync.aligned.m8n8.x4.shared.b16 {%0,%1,%2,%3}, [%4];"
                 : "=r"(r0), "=r"(r1), "=r"(r2), "=r"(r3) : "r"(addr));
}
__device__ __forceinline__ void ldsm_x2(uint32_t& r0, uint32_t& r1, uint32_t addr) {
    asm volatile("ldmatrix.sync.aligned.m8n8.x2.shared.b16 {%0,%1}, [%2];"
                 : "=r"(r0), "=r"(r1) : "r"(addr));
}
__device__ __forceinline__ void mma_f16(float* d, uint32_t a0, uint32_t a1, uint32_t a2, uint32_t a3,
                                        uint32_t b0, uint32_t b1) {
    asm volatile("mma.sync.aligned.m16n8k16.row.col.f32.f16.f16.f32 "
                 "{%0,%1,%2,%3}, {%4,%5,%6,%7}, {%8,%9}, {%0,%1,%2,%3};"
                 : "+f"(d[0]), "+f"(d[1]), "+f"(d[2]), "+f"(d[3])
                 : "r"(a0), "r"(a1), "r"(a2), "r"(a3), "r"(b0), "r"(b1));
}
__device__ __forceinline__ void f16split(float v, uint16_t& h, uint16_t& l) {
    __half hb = __float2half_rn(v);
    __half lb = __float2half_rn(v - __half2float(hb));
    h = __half_as_ushort(hb);
    l = __half_as_ushort(lb);
}
__device__ __forceinline__ uint16_t f16h(float v) {
    return __half_as_ushort(__float2half_rn(v));
}
__device__ __forceinline__ float4 h4_to_f4(uint2 u) {
    __half2 a = *(__half2*)&u.x;
    __half2 b = *(__half2*)&u.y;
    float2 fa = __half22float2(a);
    float2 fb = __half22float2(b);
    return make_float4(fa.x, fa.y, fb.x, fb.y);
}

// ---------------- scratch (device globals; no allocation allowed) ----------
__device__ uint16_t g_xl1h[NN * H1];    // fp16 layer-1 outputs (GAT1 only)
__device__ uint16_t g_xr1h[NN * H1];
__device__ float g_h  [NN * H1];
__device__ float g_x23[NN * 256];        // packed: xl2|xr2|xl3|xr3 (64 each)
__device__ float g_d  [NN * NHID1];
__device__ int   g_deg[NN];
__device__ int   g_rowptr[NN + 1];
__device__ int   g_cursor[NN];
__device__ int   g_srclist[NE];
__device__ float g_mean[NHID1];
__device__ float g_rstd[NHID1];
__device__ float g_bias23[256];
// emb fp16 hi/lo (pre-split for gram + decoder GEMM)
__device__ uint16_t g_ebh[NN * NHID2], g_ebl[NN * NHID2];
// transposed fp16 weights [Nc][K]
__device__ uint16_t g_w1lh[H1 * NFEAT];
__device__ uint16_t g_w1rh[H1 * NFEAT];
__device__ uint16_t g_w23h[256 * H1];
__device__ uint16_t g_dw1h[NHID1 * NHID2];
__device__ uint16_t g_dw2h[NFEAT * NHID1];

// ---------------- CSR build ----------------
__global__ void k_zero_counts() {
    int i = blockIdx.x * blockDim.x + threadIdx.x;
    if (i < NN) { g_deg[i] = 0; g_cursor[i] = 0; }
}

__global__ void k_count_deg(const int* __restrict__ edge_index) {
    int i = blockIdx.x * blockDim.x + threadIdx.x;
    if (i >= NE) return;
    int tgt = (i < EE) ? edge_index[EE + i] : (i - EE);
    atomicAdd(&g_deg[tgt], 1);
}

__global__ void k_scan_deg() {
    __shared__ int wsum[32];
    __shared__ int sc;
    int tid = threadIdx.x, lane = tid & 31, w = tid >> 5;
    if (tid == 0) { sc = 0; g_rowptr[0] = 0; }
    __syncthreads();
    for (int base = 0; base < NN; base += 1024) {
        int i = base + tid;
        int v = (i < NN) ? g_deg[i] : 0;
        int x = v;
#pragma unroll
        for (int o = 1; o < 32; o <<= 1) {
            int t = __shfl_up_sync(0xffffffffu, x, o);
            if (lane >= o) x += t;
        }
        if (lane == 31) wsum[w] = x;
        __syncthreads();
        if (w == 0) {
            int y = wsum[lane];
#pragma unroll
            for (int o = 1; o < 32; o <<= 1) {
                int t = __shfl_up_sync(0xffffffffu, y, o);
                if (lane >= o) y += t;
            }
            wsum[lane] = y;
        }
        __syncthreads();
        int pre = (w > 0) ? wsum[w - 1] : 0;
        int c = sc;
        if (i < NN) g_rowptr[i + 1] = c + pre + x;
        int total = wsum[31];
        __syncthreads();
        if (tid == 0) sc = c + total;
        __syncthreads();
    }
}

__global__ void k_fill_list(const int* __restrict__ edge_index) {
    int i = blockIdx.x * blockDim.x + threadIdx.x;
    if (i >= NE) return;
    int src, tgt;
    if (i < EE) { src = edge_index[i]; tgt = edge_index[EE + i]; }
    else        { src = i - EE;        tgt = i - EE; }
    int pos = atomicAdd(&g_cursor[tgt], 1);
    g_srclist[g_rowptr[tgt] + pos] = src;
}

// ---------------- fused prep: all weight transposes + bias pack -----------
#define P_S01 (H1 * NFEAT)
#define P_S2  (256 * H1)
#define P_S3  (NHID1 * NHID2)
#define P_S4  (NFEAT * NHID1)
#define P_TOT (P_S01 + P_S2 + P_S3 + P_S4 + 256)

__global__ void k_prep(const float* __restrict__ w1l, const float* __restrict__ w1r,
                       const float* __restrict__ w2l, const float* __restrict__ w2r,
                       const float* __restrict__ w3l, const float* __restrict__ w3r,
                       const float* __restrict__ dw1, const float* __restrict__ dw2,
                       const float* __restrict__ b2l, const float* __restrict__ b2r,
                       const float* __restrict__ b3l, const float* __restrict__ b3r) {
    int i = blockIdx.x * blockDim.x + threadIdx.x;
    if (i < P_S01) {
        int n = i / NFEAT, k = i - n * NFEAT;
        g_w1lh[i] = f16h(w1l[(size_t)k * H1 + n]);
        g_w1rh[i] = f16h(w1r[(size_t)k * H1 + n]);
        return;
    }
    i -= P_S01;
    if (i < P_S2) {
        int np = i >> 7, k = i & 127;
        int jj = np >> 6, n = np & 63;
        const float* W = (jj == 0) ? w2l : (jj == 1) ? w2r : (jj == 2) ? w3l : w3r;
        g_w23h[i] = f16h(W[(size_t)k * 64 + n]);
        return;
    }
    i -= P_S2;
    if (i < P_S3) {
        int n = i / NHID2, k = i - n * NHID2;
        g_dw1h[i] = f16h(dw1[(size_t)k * NHID1 + n]);
        return;
    }
    i -= P_S3;
    if (i < P_S4) {
        int n = i / NHID1, k = i - n * NHID1;
        g_dw2h[i] = f16h(dw2[(size_t)k * NFEAT + n]);
        return;
    }
    i -= P_S4;
    if (i < 256) {
        int jj = i >> 6, n = i & 63;
        const float* b = (jj == 0) ? b2l : (jj == 1) ? b2r : (jj == 2) ? b3l : b3r;
        g_bias23[i] = b[n];
    }
}

// ---------------- GEMM job plumbing ----------------
struct TJob  { const uint16_t* Bh; const float* bias; float* C; };
struct TJobs { TJob j[2]; };

// ---------------- gemmT: fp16 2-pass HMMA GEMM, 128x128 tile -------------
__global__ __launch_bounds__(256)
void gemmT(const float* __restrict__ A, TJobs jobs, int M, int K, int Nc,
           const float* __restrict__ bnG, const float* __restrict__ bnB) {
    const TJob jb = jobs.j[blockIdx.z];
    __shared__ __align__(16) uint16_t Ah[128][40], Al[128][40];
    __shared__ __align__(16) uint16_t Bh[128][40];
    int tid = threadIdx.x, lane = tid & 31, warp = tid >> 5;
    int row0 = blockIdx.y * 128, col0 = blockIdx.x * 128;
    int wm = (warp & 1) * 64, wn = (warp >> 1) * 32;
    int grp = lane >> 3, rl = lane & 7;
    float c[4][4][4];
#pragma unroll
    for (int mi = 0; mi < 4; mi++)
#pragma unroll
        for (int ni = 0; ni < 4; ni++)
#pragma unroll
            for (int e = 0; e < 4; e++) c[mi][ni][e] = 0.f;

    int ar = tid >> 1, kh = (tid & 1) * 16;
    int r = row0 + ar;
    bool va = r < M;

    for (int k0 = 0; k0 < K; k0 += 32) {
        const float* pa = A + (size_t)r * K + k0 + kh;
#pragma unroll
        for (int q = 0; q < 4; q++) {
            float4 v = va ? *(const float4*)(pa + q * 4) : make_float4(0.f, 0.f, 0.f, 0.f);
            if (bnG) {
                int ch = k0 + kh + q * 4;
                float4 mm = *(const float4*)(g_mean + ch);
                float4 rs = *(const float4*)(g_rstd + ch);
                float4 gg = *(const float4*)(bnG + ch);
                float4 bb = *(const float4*)(bnB + ch);
                v.x = fmaxf((v.x - mm.x) * rs.x * gg.x + bb.x, 0.f);
                v.y = fmaxf((v.y - mm.y) * rs.y * gg.y + bb.y, 0.f);
                v.z = fmaxf((v.z - mm.z) * rs.z * gg.z + bb.z, 0.f);
                v.w = fmaxf((v.w - mm.w) * rs.w * gg.w + bb.w, 0.f);
            }
            uint16_t h0, l0, h1, l1, h2, l2, h3, l3;
            f16split(v.x, h0, l0); f16split(v.y, h1, l1);
            f16split(v.z, h2, l2); f16split(v.w, h3, l3);
            *(uint32_t*)&Ah[ar][kh + q * 4]     = (uint32_t)h0 | ((uint32_t)h1 << 16);
            *(uint32_t*)&Ah[ar][kh + q * 4 + 2] = (uint32_t)h2 | ((uint32_t)h3 << 16);
            *(uint32_t*)&Al[ar][kh + q * 4]     = (uint32_t)l0 | ((uint32_t)l1 << 16);
            *(uint32_t*)&Al[ar][kh + q * 4 + 2] = (uint32_t)l2 | ((uint32_t)l3 << 16);
        }
        {
            const uint16_t* pbh = jb.Bh + (size_t)(col0 + ar) * K + k0 + kh;
            *(uint4*)&Bh[ar][kh]     = *(const uint4*)pbh;
            *(uint4*)&Bh[ar][kh + 8] = *(const uint4*)(pbh + 8);
        }
        __syncthreads();
#pragma unroll
        for (int pass = 0; pass < 2; pass++) {
            const uint16_t (*Aq)[40] = (pass == 1) ? Al : Ah;
#pragma unroll
            for (int k1 = 0; k1 < 32; k1 += 16) {
                uint32_t af[4][4], bf[4][2];
#pragma unroll
                for (int mi = 0; mi < 4; mi++) {
                    int arow = wm + mi * 16 + (grp & 1) * 8 + rl;
                    int acol = k1 + (grp >> 1) * 8;
                    ldsm_x4(af[mi][0], af[mi][1], af[mi][2], af[mi][3],
                            smem_u32(&Aq[arow][acol]));
                }
#pragma unroll
                for (int ni = 0; ni < 4; ni++) {
                    int brow = wn + ni * 8 + rl;
                    int bcol = k1 + (grp & 1) * 8;
                    ldsm_x2(bf[ni][0], bf[ni][1], smem_u32(&Bh[brow][bcol]));
                }
#pragma unroll
                for (int mi = 0; mi < 4; mi++)
#pragma unroll
                    for (int ni = 0; ni < 4; ni++)
                        mma_f16(c[mi][ni], af[mi][0], af[mi][1], af[mi][2], af[mi][3],
                                bf[ni][0], bf[ni][1]);
            }
        }
        __syncthreads();
    }
    int qr = lane >> 2, qc = 2 * (lane & 3);
#pragma unroll
    for (int mi = 0; mi < 4; mi++) {
#pragma unroll
        for (int half = 0; half < 2; half++) {
            int row = wm + mi * 16 + qr + half * 8;
            int rr = row0 + row;
            if (rr < M) {
                float* Crow = jb.C + (size_t)rr * Nc;
#pragma unroll
                for (int ni = 0; ni < 4; ni++) {
                    int cc = col0 + wn + ni * 8 + qc;
                    float2 p;
                    p.x = c[mi][ni][2 * half]     + __ldg(&jb.bias[cc]);
                    p.y = c[mi][ni][2 * half + 1] + __ldg(&jb.bias[cc + 1]);
                    *(float2*)&Crow[cc] = p;
                }
            }
        }
    }
}

// ---------------- gemmT64: 64x128 tile, fp16 OUTPUT (for GAT1 operands) ---
__global__ __launch_bounds__(256)
void gemmT64h(const float* __restrict__ A, TJobs jobs, int M, int K, int Nc) {
    const TJob jb = jobs.j[blockIdx.z];
    __shared__ __align__(16) uint16_t Ah[64][40], Al[64][40];
    __shared__ __align__(16) uint16_t Bh[128][40];
    int tid = threadIdx.x, lane = tid & 31, warp = tid >> 5;
    int row0 = blockIdx.y * 64, col0 = blockIdx.x * 128;
    int wm = (warp & 1) * 32, wn = (warp >> 1) * 32;
    int grp = lane >> 3, rl = lane & 7;
    float c[2][4][4];
#pragma unroll
    for (int mi = 0; mi < 2; mi++)
#pragma unroll
        for (int ni = 0; ni < 4; ni++)
#pragma unroll
            for (int e = 0; e < 4; e++) c[mi][ni][e] = 0.f;

    int ar = tid >> 2, ks = (tid & 3) * 8;
    int br = tid >> 1, kb = (tid & 1) * 16;
    int r = row0 + ar;
    bool va = r < M;

    for (int k0 = 0; k0 < K; k0 += 32) {
        const float* pa = A + (size_t)r * K + k0 + ks;
#pragma unroll
        for (int q = 0; q < 2; q++) {
            float4 v = va ? *(const float4*)(pa + q * 4) : make_float4(0.f, 0.f, 0.f, 0.f);
            uint16_t h0, l0, h1, l1, h2, l2, h3, l3;
            f16split(v.x, h0, l0); f16split(v.y, h1, l1);
            f16split(v.z, h2, l2); f16split(v.w, h3, l3);
            *(uint32_t*)&Ah[ar][ks + q * 4]     = (uint32_t)h0 | ((uint32_t)h1 << 16);
            *(uint32_t*)&Ah[ar][ks + q * 4 + 2] = (uint32_t)h2 | ((uint32_t)h3 << 16);
            *(uint32_t*)&Al[ar][ks + q * 4]     = (uint32_t)l0 | ((uint32_t)l1 << 16);
            *(uint32_t*)&Al[ar][ks + q * 4 + 2] = (uint32_t)l2 | ((uint32_t)l3 << 16);
        }
        {
            const uint16_t* pbh = jb.Bh + (size_t)(col0 + br) * K + k0 + kb;
            *(uint4*)&Bh[br][kb]     = *(const uint4*)pbh;
            *(uint4*)&Bh[br][kb + 8] = *(const uint4*)(pbh + 8);
        }
        __syncthreads();
#pragma unroll
        for (int pass = 0; pass < 2; pass++) {
            const uint16_t (*Aq)[40] = (pass == 1) ? Al : Ah;
#pragma unroll
            for (int k1 = 0; k1 < 32; k1 += 16) {
                uint32_t af[2][4], bf[4][2];
#pragma unroll
                for (int mi = 0; mi < 2; mi++) {
                    int arow = wm + mi * 16 + (grp & 1) * 8 + rl;
                    int acol = k1 + (grp >> 1) * 8;
                    ldsm_x4(af[mi][0], af[mi][1], af[mi][2], af[mi][3],
                            smem_u32(&Aq[arow][acol]));
                }
#pragma unroll
                for (int ni = 0; ni < 4; ni++) {
                    int brow = wn + ni * 8 + rl;
                    int bcol = k1 + (grp & 1) * 8;
                    ldsm_x2(bf[ni][0], bf[ni][1], smem_u32(&Bh[brow][bcol]));
                }
#pragma unroll
                for (int mi = 0; mi < 2; mi++)
#pragma unroll
                    for (int ni = 0; ni < 4; ni++)
                        mma_f16(c[mi][ni], af[mi][0], af[mi][1], af[mi][2], af[mi][3],
                                bf[ni][0], bf[ni][1]);
            }
        }
        __syncthreads();
    }
    int qr = lane >> 2, qc = 2 * (lane & 3);
#pragma unroll
    for (int mi = 0; mi < 2; mi++) {
#pragma unroll
        for (int half = 0; half < 2; half++) {
            int row = wm + mi * 16 + qr + half * 8;
            int rr = row0 + row;
            if (rr < M) {
                uint16_t* Crow = (uint16_t*)jb.C + (size_t)rr * Nc;
#pragma unroll
                for (int ni = 0; ni < 4; ni++) {
                    int cc = col0 + wn + ni * 8 + qc;
                    uint16_t p0 = f16h(c[mi][ni][2 * half]     + __ldg(&jb.bias[cc]));
                    uint16_t p1 = f16h(c[mi][ni][2 * half + 1] + __ldg(&jb.bias[cc + 1]));
                    *(uint32_t*)&Crow[cc] = (uint32_t)p0 | ((uint32_t)p1 << 16);
                }
            }
        }
    }
}

// ---------------- gemmP: pre-split fp16 A (hi/lo), 128x128 tile ----------
__global__ __launch_bounds__(256)
void gemmP(const uint16_t* __restrict__ Ahg, const uint16_t* __restrict__ Alg,
           const uint16_t* __restrict__ Bhg, const float* __restrict__ bias,
           float* __restrict__ C, int M, int K, int Nc) {
    __shared__ __align__(16) uint16_t Ah[128][40], Al[128][40];
    __shared__ __align__(16) uint16_t Bh[128][40];
    int tid = threadIdx.x, lane = tid & 31, warp = tid >> 5;
    int row0 = blockIdx.y * 128, col0 = blockIdx.x * 128;
    int wm = (warp & 1) * 64, wn = (warp >> 1) * 32;
    int grp = lane >> 3, rl = lane & 7;
    float c[4][4][4];
#pragma unroll
    for (int mi = 0; mi < 4; mi++)
#pragma unroll
        for (int ni = 0; ni < 4; ni++)
#pragma unroll
            for (int e = 0; e < 4; e++) c[mi][ni][e] = 0.f;

    int ar = tid >> 1, kh = (tid & 1) * 16;
    int r = row0 + ar;
    bool va = r < M;
    uint4 z4 = make_uint4(0, 0, 0, 0);

    for (int k0 = 0; k0 < K; k0 += 32) {
        {
            const uint16_t* ph = Ahg + (size_t)r * K + k0 + kh;
            const uint16_t* pl = Alg + (size_t)r * K + k0 + kh;
            *(uint4*)&Ah[ar][kh]     = va ? *(const uint4*)ph : z4;
            *(uint4*)&Ah[ar][kh + 8] = va ? *(const uint4*)(ph + 8) : z4;
            *(uint4*)&Al[ar][kh]     = va ? *(const uint4*)pl : z4;
            *(uint4*)&Al[ar][kh + 8] = va ? *(const uint4*)(pl + 8) : z4;
        }
        {
            const uint16_t* pbh = Bhg + (size_t)(col0 + ar) * K + k0 + kh;
            *(uint4*)&Bh[ar][kh]     = *(const uint4*)pbh;
            *(uint4*)&Bh[ar][kh + 8] = *(const uint4*)(pbh + 8);
        }
        __syncthreads();
#pragma unroll
        for (int pass = 0; pass < 2; pass++) {
            const uint16_t (*Aq)[40] = (pass == 1) ? Al : Ah;
#pragma unroll
            for (int k1 = 0; k1 < 32; k1 += 16) {
                uint32_t af[4][4], bf[4][2];
#pragma unroll
                for (int mi = 0; mi < 4; mi++) {
                    int arow = wm + mi * 16 + (grp & 1) * 8 + rl;
                    int acol = k1 + (grp >> 1) * 8;
                    ldsm_x4(af[mi][0], af[mi][1], af[mi][2], af[mi][3],
                            smem_u32(&Aq[arow][acol]));
                }
#pragma unroll
                for (int ni = 0; ni < 4; ni++) {
                    int brow = wn + ni * 8 + rl;
                    int bcol = k1 + (grp & 1) * 8;
                    ldsm_x2(bf[ni][0], bf[ni][1], smem_u32(&Bh[brow][bcol]));
                }
#pragma unroll
                for (int mi = 0; mi < 4; mi++)
#pragma unroll
                    for (int ni = 0; ni < 4; ni++)
                        mma_f16(c[mi][ni], af[mi][0], af[mi][1], af[mi][2], af[mi][3],
                                bf[ni][0], bf[ni][1]);
            }
        }
        __syncthreads();
    }
    int qr = lane >> 2, qc = 2 * (lane & 3);
#pragma unroll
    for (int mi = 0; mi < 4; mi++) {
#pragma unroll
        for (int half = 0; half < 2; half++) {
            int row = wm + mi * 16 + qr + half * 8;
            int rr = row0 + row;
            if (rr < M) {
                float* Crow = C + (size_t)rr * Nc;
#pragma unroll
                for (int ni = 0; ni < 4; ni++) {
                    int cc = col0 + wn + ni * 8 + qc;
                    float2 p;
                    p.x = c[mi][ni][2 * half]     + __ldg(&bias[cc]);
                    p.y = c[mi][ni][2 * half + 1] + __ldg(&bias[cc + 1]);
                    *(float2*)&Crow[cc] = p;
                }
            }
        }
    }
}

// ---------------- GAT layer 1: fused online-softmax, fp16 operands --------
// block = 128 thr (4 warps = 4 groups of 32 lanes); each lane = 4 channels.
__global__ void gat1_fused(const uint16_t* __restrict__ xlh,
                           const uint16_t* __restrict__ xrh,
                           const float* __restrict__ att, const float* __restrict__ bias,
                           float* __restrict__ out) {
    int t = blockIdx.x;
    int tid = threadIdx.x, lane = tid & 31, warp = tid >> 5;

    __shared__ float4 s_xr4[32], s_att4[32];
    __shared__ float  s_m[4], s_s[4];
    __shared__ float4 s_acc[4][32];
    if (tid < 32) {
        uint2 u = *(const uint2*)(xrh + (size_t)t * H1 + tid * 4);
        s_xr4[tid]  = h4_to_f4(u);
        s_att4[tid] = *(const float4*)(att + tid * 4);
    }
    int beg = g_rowptr[t];
    int deg = g_rowptr[t + 1] - beg;
    __syncthreads();

    float4 xr4 = s_xr4[lane];
    float4 at4 = s_att4[lane];

    float m0 = -1e30f, z0 = 0.f;
    float m1 = -1e30f, z1 = 0.f;
    float4 a0 = make_float4(0.f, 0.f, 0.f, 0.f), a1 = a0;

    int j = warp;
    for (; j + 4 < deg; j += 8) {
        int sA = g_srclist[beg + j];
        int sB = g_srclist[beg + j + 4];
        float4 vA = h4_to_f4(*(const uint2*)(xlh + (size_t)sA * H1 + lane * 4));
        float4 vB = h4_to_f4(*(const uint2*)(xlh + (size_t)sB * H1 + lane * 4));
        float pA, pB;
        {
            float a = vA.x + xr4.x; a = fmaxf(a, NEG_SLOPE * a);
            float b = vA.y + xr4.y; b = fmaxf(b, NEG_SLOPE * b);
            float c = vA.z + xr4.z; c = fmaxf(c, NEG_SLOPE * c);
            float d = vA.w + xr4.w; d = fmaxf(d, NEG_SLOPE * d);
            pA = at4.x * a + at4.y * b + at4.z * c + at4.w * d;
            a = vB.x + xr4.x; a = fmaxf(a, NEG_SLOPE * a);
            b = vB.y + xr4.y; b = fmaxf(b, NEG_SLOPE * b);
            c = vB.z + xr4.z; c = fmaxf(c, NEG_SLOPE * c);
            d = vB.w + xr4.w; d = fmaxf(d, NEG_SLOPE * d);
            pB = at4.x * a + at4.y * b + at4.z * c + at4.w * d;
        }
#pragma unroll
        for (int o = 16; o; o >>= 1) {
            pA += __shfl_xor_sync(0xffffffffu, pA, o);
            pB += __shfl_xor_sync(0xffffffffu, pB, o);
        }
        float mn0 = fmaxf(m0, pA);
        float sc0 = __expf(m0 - mn0);
        float w0  = __expf(pA - mn0);
        z0 = z0 * sc0 + w0;
        a0.x = a0.x * sc0 + w0 * vA.x;
        a0.y = a0.y * sc0 + w0 * vA.y;
        a0.z = a0.z * sc0 + w0 * vA.z;
        a0.w = a0.w * sc0 + w0 * vA.w;
        m0 = mn0;
        float mn1 = fmaxf(m1, pB);
        float sc1 = __expf(m1 - mn1);
        float w1  = __expf(pB - mn1);
        z1 = z1 * sc1 + w1;
        a1.x = a1.x * sc1 + w1 * vB.x;
        a1.y = a1.y * sc1 + w1 * vB.y;
        a1.z = a1.z * sc1 + w1 * vB.z;
        a1.w = a1.w * sc1 + w1 * vB.w;
        m1 = mn1;
    }
    if (j < deg) {
        int sA = g_srclist[beg + j];
        float4 vA = h4_to_f4(*(const uint2*)(xlh + (size_t)sA * H1 + lane * 4));
        float a = vA.x + xr4.x; a = fmaxf(a, NEG_SLOPE * a);
        float b = vA.y + xr4.y; b = fmaxf(b, NEG_SLOPE * b);
        float c = vA.z + xr4.z; c = fmaxf(c, NEG_SLOPE * c);
        float d = vA.w + xr4.w; d = fmaxf(d, NEG_SLOPE * d);
        float pA = at4.x * a + at4.y * b + at4.z * c + at4.w * d;
#pragma unroll
        for (int o = 16; o; o >>= 1) pA += __shfl_xor_sync(0xffffffffu, pA, o);
        float mn0 = fmaxf(m0, pA);
        float sc0 = __expf(m0 - mn0);
        float w0  = __expf(pA - mn0);
        z0 = z0 * sc0 + w0;
        a0.x = a0.x * sc0 + w0 * vA.x;
        a0.y = a0.y * sc0 + w0 * vA.y;
        a0.z = a0.z * sc0 + w0 * vA.z;
        a0.w = a0.w * sc0 + w0 * vA.w;
        m0 = mn0;
    }
    {
        float M = fmaxf(m0, m1);
        float e0 = __expf(m0 - M), e1 = __expf(m1 - M);
        z0 = z0 * e0 + z1 * e1;
        a0.x = a0.x * e0 + a1.x * e1;
        a0.y = a0.y * e0 + a1.y * e1;
        a0.z = a0.z * e0 + a1.z * e1;
        a0.w = a0.w * e0 + a1.w * e1;
        m0 = M;
    }
    if (lane == 0) { s_m[warp] = m0; s_s[warp] = z0; }
    s_acc[warp][lane] = a0;
    __syncthreads();

    if (tid < 32) {
        float M = s_m[0];
#pragma unroll
        for (int g = 1; g < 4; g++) M = fmaxf(M, s_m[g]);
        float zt = 0.f;
        float4 at = make_float4(0.f, 0.f, 0.f, 0.f);
#pragma unroll
        for (int g = 0; g < 4; g++) {
            float f = __expf(s_m[g] - M);
            zt += s_s[g] * f;
            float4 q = s_acc[g][tid];
            at.x += q.x * f; at.y += q.y * f; at.z += q.z * f; at.w += q.w * f;
        }
        float inv = 1.f / zt;
        float4 b4 = *(const float4*)(bias + tid * 4);
        float4 o4;
        o4.x = at.x * inv + b4.x;
        o4.y = at.y * inv + b4.y;
        o4.z = at.z * inv + b4.z;
        o4.w = at.w * inv + b4.w;
        *(float4*)(out + (size_t)t * H1 + tid * 4) = o4;
    }
}

// ---------------- GAT layers 2+3 merged + reparameterize fused ------------
__global__ void gat23_fused(const float* __restrict__ x23,
                            const float* __restrict__ a2, const float* __restrict__ bias2,
                            const float* __restrict__ a3, const float* __restrict__ bias3,
                            const float* __restrict__ eps,
                            float* __restrict__ mu, float* __restrict__ lv,
                            float* __restrict__ emb) {
    int t = blockIdx.x;
    int tid = threadIdx.x, lane = tid & 31, warp = tid >> 5;
    int half = lane >> 4, lg = lane & 15;

    __shared__ float4 s_xr4[2][16], s_att4[2][16];
    __shared__ float  s_m[2][4], s_s[2][4];
    __shared__ float4 s_acc[2][4][16];
    if (tid < 32) {
        int h = tid >> 4, q = tid & 15;
        s_xr4[h][q]  = *(const float4*)(x23 + (size_t)t * 256 + h * 128 + 64 + q * 4);
        s_att4[h][q] = *(const float4*)((h ? a3 : a2) + q * 4);
    }
    int beg = g_rowptr[t];
    int deg = g_rowptr[t + 1] - beg;
    __syncthreads();

    float4 xr4 = s_xr4[half][lg];
    float4 at4 = s_att4[half][lg];
    int coff = half * 128 + lg * 4;

    float m0 = -1e30f, z0 = 0.f;
    float m1 = -1e30f, z1 = 0.f;
    float4 a0 = make_float4(0.f, 0.f, 0.f, 0.f), a1 = a0;

    int j = warp;
    for (; j + 4 < deg; j += 8) {
        int sA = g_srclist[beg + j];
        int sB = g_srclist[beg + j + 4];
        float4 vA = *(const float4*)(x23 + (size_t)sA * 256 + coff);
        float4 vB = *(const float4*)(x23 + (size_t)sB * 256 + coff);
        float pA, pB;
        {
            float a = vA.x + xr4.x; a = fmaxf(a, NEG_SLOPE * a);
            float b = vA.y + xr4.y; b = fmaxf(b, NEG_SLOPE * b);
            float c = vA.z + xr4.z; c = fmaxf(c, NEG_SLOPE * c);
            float d = vA.w + xr4.w; d = fmaxf(d, NEG_SLOPE * d);
            pA = at4.x * a + at4.y * b + at4.z * c + at4.w * d;
            a = vB.x + xr4.x; a = fmaxf(a, NEG_SLOPE * a);
            b = vB.y + xr4.y; b = fmaxf(b, NEG_SLOPE * b);
            c = vB.z + xr4.z; c = fmaxf(c, NEG_SLOPE * c);
            d = vB.w + xr4.w; d = fmaxf(d, NEG_SLOPE * d);
            pB = at4.x * a + at4.y * b + at4.z * c + at4.w * d;
        }
#pragma unroll
        for (int o = 8; o; o >>= 1) {
            pA += __shfl_xor_sync(0xffffffffu, pA, o);
            pB += __shfl_xor_sync(0xffffffffu, pB, o);
        }
        float mn0 = fmaxf(m0, pA);
        float sc0 = __expf(m0 - mn0);
        float w0  = __expf(pA - mn0);
        z0 = z0 * sc0 + w0;
        a0.x = a0.x * sc0 + w0 * vA.x;
        a0.y = a0.y * sc0 + w0 * vA.y;
        a0.z = a0.z * sc0 + w0 * vA.z;
        a0.w = a0.w * sc0 + w0 * vA.w;
        m0 = mn0;
        float mn1 = fmaxf(m1, pB);
        float sc1 = __expf(m1 - mn1);
        float w1  = __expf(pB - mn1);
        z1 = z1 * sc1 + w1;
        a1.x = a1.x * sc1 + w1 * vB.x;
        a1.y = a1.y * sc1 + w1 * vB.y;
        a1.z = a1.z * sc1 + w1 * vB.z;
        a1.w = a1.w * sc1 + w1 * vB.w;
        m1 = mn1;
    }
    if (j < deg) {
        int sA = g_srclist[beg + j];
        float4 vA = *(const float4*)(x23 + (size_t)sA * 256 + coff);
        float a = vA.x + xr4.x; a = fmaxf(a, NEG_SLOPE * a);
        float b = vA.y + xr4.y; b = fmaxf(b, NEG_SLOPE * b);
        float c = vA.z + xr4.z; c = fmaxf(c, NEG_SLOPE * c);
        float d = vA.w + xr4.w; d = fmaxf(d, NEG_SLOPE * d);
        float pA = at4.x * a + at4.y * b + at4.z * c + at4.w * d;
#pragma unroll
        for (int o = 8; o; o >>= 1) pA += __shfl_xor_sync(0xffffffffu, pA, o);
        float mn0 = fmaxf(m0, pA);
        float sc0 = __expf(m0 - mn0);
        float w0  = __expf(pA - mn0);
        z0 = z0 * sc0 + w0;
        a0.x = a0.x * sc0 + w0 * vA.x;
        a0.y = a0.y * sc0 + w0 * vA.y;
        a0.z = a0.z * sc0 + w0 * vA.z;
        a0.w = a0.w * sc0 + w0 * vA.w;
        m0 = mn0;
    }
    {
        float M = fmaxf(m0, m1);
        float e0 = __expf(m0 - M), e1 = __expf(m1 - M);
        z0 = z0 * e0 + z1 * e1;
        a0.x = a0.x * e0 + a1.x * e1;
        a0.y = a0.y * e0 + a1.y * e1;
        a0.z = a0.z * e0 + a1.z * e1;
        a0.w = a0.w * e0 + a1.w * e1;
        m0 = M;
    }
    if (lg == 0) { s_m[half][warp] = m0; s_s[half][warp] = z0; }
    s_acc[half][warp][lg] = a0;
    __syncthreads();

    if (tid < 32) {
        int h = tid >> 4, q = tid & 15;
        float M = s_m[h][0];
#pragma unroll
        for (int g = 1; g < 4; g++) M = fmaxf(M, s_m[h][g]);
        float zt = 0.f;
        float4 at = make_float4(0.f, 0.f, 0.f, 0.f);
#pragma unroll
        for (int g = 0; g < 4; g++) {
            float f = __expf(s_m[h][g] - M);
            zt += s_s[h][g] * f;
            float4 qq = s_acc[h][g][q];
            at.x += qq.x * f; at.y += qq.y * f; at.z += qq.z * f; at.w += qq.w * f;
        }
        float inv = 1.f / zt;
        float4 b4 = *(const float4*)((h ? bias3 : bias2) + q * 4);
        float4 o4;
        o4.x = at.x * inv + b4.x;
        o4.y = at.y * inv + b4.y;
        o4.z = at.z * inv + b4.z;
        o4.w = at.w * inv + b4.w;
        float* op = h ? lv : mu;
        *(float4*)(op + (size_t)t * 64 + q * 4) = o4;
        s_att4[h][q] = o4;                          // reuse for reparam exchange
        __syncwarp();
        if (h == 0) {                               // fused reparameterize
            float4 mu4 = s_att4[0][q];
            float4 lv4 = s_att4[1][q];
            float4 e4 = *(const float4*)(eps + (size_t)t * 64 + q * 4);
            float4 em;
            em.x = e4.x * __expf(lv4.x) + mu4.x;
            em.y = e4.y * __expf(lv4.y) + mu4.y;
            em.z = e4.z * __expf(lv4.z) + mu4.z;
            em.w = e4.w * __expf(lv4.w) + mu4.w;
            *(float4*)(emb + (size_t)t * 64 + q * 4) = em;
            uint16_t hh, ll;
            ushort4 vh, vl;
            f16split(em.x, hh, ll); vh.x = hh; vl.x = ll;
            f16split(em.y, hh, ll); vh.y = hh; vl.y = ll;
            f16split(em.z, hh, ll); vh.z = hh; vl.z = ll;
            f16split(em.w, hh, ll); vh.w = hh; vl.w = ll;
            *(ushort4*)(g_ebh + (size_t)t * 64 + q * 4) = vh;
            *(ushort4*)(g_ebl + (size_t)t * 64 + q * 4) = vl;
        }
    }
}

// ---------------- batch norm stats ----------------
template <int C>
__global__ void bn_stats(const float* __restrict__ h) {
    int c = blockIdx.x;
    int tid = threadIdx.x;
    float s = 0.f, s2 = 0.f;
    for (int r = tid; r < NN; r += 256) {
        float v = h[(size_t)r * C + c];
        s += v; s2 += v * v;
    }
    __shared__ float sh[8], sh2[8];
#pragma unroll
    for (int o = 16; o; o >>= 1) {
        s  += __shfl_xor_sync(0xffffffffu, s,  o);
        s2 += __shfl_xor_sync(0xffffffffu, s2, o);
    }
    if ((tid & 31) == 0) { sh[tid >> 5] = s; sh2[tid >> 5] = s2; }
    __syncthreads();
    if (tid == 0) {
        float ts = 0.f, ts2 = 0.f;
        for (int w = 0; w < 8; w++) { ts += sh[w]; ts2 += sh2[w]; }
        float mean = ts / NN;
        float var = ts2 / NN - mean * mean;
        g_mean[c] = mean;
        g_rstd[c] = rsqrtf(var + BN_EPS);
    }
}

// ---------------- readj = sigmoid(emb @ emb^T), fp16 2-pass HMMA ----------
#define GP 72
#define G_AHI 0
#define G_ALO (G_AHI + 128 * GP * 2)
#define G_BHI (G_ALO + 128 * GP * 2)
#define G_SMEM 65536
#define MTG 79

__global__ __launch_bounds__(256)
void gram_hmma(const uint16_t* __restrict__ Eh, const uint16_t* __restrict__ El,
               float* __restrict__ out) {
    int bid = blockIdx.x;
    int by = (int)(0.5f * (2.f * MTG + 1.f) -
                   sqrtf((2.f * MTG + 1.f) * (2.f * MTG + 1.f) * 0.25f - 2.f * (float)bid));
    if (by < 0) by = 0;
    if (by > MTG - 1) by = MTG - 1;
    int start = by * MTG - (by * (by - 1)) / 2;
    while (start > bid) { by--; start = by * MTG - (by * (by - 1)) / 2; }
    while (bid >= start + (MTG - by)) { by++; start = by * MTG - (by * (by - 1)) / 2; }
    int bx = by + (bid - start);

    extern __shared__ __align__(16) char smem[];
    uint32_t sb = smem_u32(smem);
    int tid = threadIdx.x, lane = tid & 31, warp = tid >> 5;
    int row0 = by * 128, col0 = bx * 128;

    {
        int rrow = tid & 127;
        uint4 z = make_uint4(0, 0, 0, 0);
        if (tid < 128) {
            int rA = row0 + rrow;
            bool va = rA < NN;
            const uint4* ph = (const uint4*)(Eh + (size_t)rA * 64);
            const uint4* pl = (const uint4*)(El + (size_t)rA * 64);
#pragma unroll
            for (int q = 0; q < 8; q++) {
                uint32_t off = (rrow * GP + q * 8) * 2;
                *(uint4*)(smem + G_AHI + off) = va ? ph[q] : z;
                *(uint4*)(smem + G_ALO + off) = va ? pl[q] : z;
            }
        } else {
            int rB = col0 + rrow;
            bool vb = rB < NN;
            const uint4* ph = (const uint4*)(Eh + (size_t)rB * 64);
#pragma unroll
            for (int q = 0; q < 8; q++) {
                uint32_t off = (rrow * GP + q * 8) * 2;
                *(uint4*)(smem + G_BHI + off) = vb ? ph[q] : z;
            }
        }
    }
    __syncthreads();

    int wm = (warp & 1) * 64;
    int wn = (warp >> 1) * 32;
    float c[4][4][4];
#pragma unroll
    for (int mi = 0; mi < 4; mi++)
#pragma unroll
        for (int ni = 0; ni < 4; ni++)
#pragma unroll
            for (int e = 0; e < 4; e++) c[mi][ni][e] = 0.f;

    int grp = lane >> 3, rl = lane & 7;
#pragma unroll
    for (int pass = 0; pass < 2; pass++) {
        uint32_t aBase = sb + ((pass == 1) ? G_ALO : G_AHI);
        uint32_t bBase = sb + G_BHI;
#pragma unroll
        for (int k0 = 0; k0 < 64; k0 += 16) {
            uint32_t af[4][4], bf[4][2];
#pragma unroll
            for (int mi = 0; mi < 4; mi++) {
                int arow = wm + mi * 16 + (grp & 1) * 8 + rl;
                int acol = k0 + (grp >> 1) * 8;
                ldsm_x4(af[mi][0], af[mi][1], af[mi][2], af[mi][3],
                        aBase + (arow * GP + acol) * 2);
            }
#pragma unroll
            for (int ni = 0; ni < 4; ni++) {
                int brow = wn + ni * 8 + rl;
                int bcol = k0 + (grp & 1) * 8;
                ldsm_x2(bf[ni][0], bf[ni][1], bBase + (brow * GP + bcol) * 2);
            }
#pragma unroll
            for (int mi = 0; mi < 4; mi++)
#pragma unroll
                for (int ni = 0; ni < 4; ni++)
                    mma_f16(c[mi][ni], af[mi][0], af[mi][1], af[mi][2], af[mi][3],
                            bf[ni][0], bf[ni][1]);
        }
    }
    __syncthreads();

    float* stag = (float*)smem;
    bool diag = (bx == by);
    int qr = lane >> 2, qc = 2 * (lane & 3);
#pragma unroll
    for (int mi = 0; mi < 4; mi++) {
#pragma unroll
        for (int ni = 0; ni < 4; ni++) {
#pragma unroll
            for (int half = 0; half < 2; half++) {
                int row = wm + mi * 16 + qr + half * 8;
                int col = wn + ni * 8 + qc;
                float v0 = 1.f / (1.f + __expf(-c[mi][ni][2 * half]));
                float v1 = 1.f / (1.f + __expf(-c[mi][ni][2 * half + 1]));
                int r = row0 + row, cc = col0 + col;
                if (r < NN && cc < NN)
                    *(float2*)(out + (size_t)r * NN + cc) = make_float2(v0, v1);
                if (!diag) {
                    int s = row & 31;
                    stag[row * 128 + (col ^ s)] = v0;
                    stag[row * 128 + ((col + 1) ^ s)] = v1;
                }
            }
        }
    }
    if (diag) return;
    __syncthreads();

    for (int cc = warp; cc < 128; cc += 8) {
        int cgl = col0 + cc;
        if (cgl >= NN) continue;
        float* mrow = out + (size_t)cgl * NN + row0;
#pragma unroll
        for (int ib = 0; ib < 128; ib += 32) {
            int i = ib + lane;
            if (row0 + i < NN)
                mrow[i] = stag[i * 128 + (cc ^ (i & 31))];
        }
    }
}

// ---------------- launch ----------------
extern "C" void kernel_launch(void* const* d_in, const int* in_sizes, int n_in,
                              void* d_out, int out_size) {
    const float* x   = (const float*)d_in[0];
    const int*   ei  = (const int*)  d_in[1];
    const float* eps = (const float*)d_in[2];
    const float* w1l = (const float*)d_in[3];
    const float* b1l = (const float*)d_in[4];
    const float* w1r = (const float*)d_in[5];
    const float* b1r = (const float*)d_in[6];
    const float* a1  = (const float*)d_in[7];
    const float* bias1 = (const float*)d_in[8];
    const float* bn1_g = (const float*)d_in[9];
    const float* bn1_b = (const float*)d_in[10];
    const float* w2l = (const float*)d_in[11];
    const float* b2l = (const float*)d_in[12];
    const float* w2r = (const float*)d_in[13];
    const float* b2r = (const float*)d_in[14];
    const float* a2  = (const float*)d_in[15];
    const float* bias2 = (const float*)d_in[16];
    const float* w3l = (const float*)d_in[17];
    const float* b3l = (const float*)d_in[18];
    const float* w3r = (const float*)d_in[19];
    const float* b3r = (const float*)d_in[20];
    const float* a3  = (const float*)d_in[21];
    const float* bias3 = (const float*)d_in[22];
    const float* dw1 = (const float*)d_in[23];
    const float* db1 = (const float*)d_in[24];
    const float* dbn_g = (const float*)d_in[25];
    const float* dbn_b = (const float*)d_in[26];
    const float* dw2 = (const float*)d_in[27];
    const float* db2 = (const float*)d_in[28];
    float* out = (float*)d_out;

    float *p_h, *p_x23, *p_d, *p_b23;
    cudaGetSymbolAddress((void**)&p_h,   g_h);
    cudaGetSymbolAddress((void**)&p_x23, g_x23);
    cudaGetSymbolAddress((void**)&p_d,   g_d);
    cudaGetSymbolAddress((void**)&p_b23, g_bias23);
    uint16_t *p_xl1h, *p_xr1h, *p_w1lh, *p_w1rh, *p_w23h, *p_dw1h, *p_dw2h, *p_ebh, *p_ebl;
    cudaGetSymbolAddress((void**)&p_xl1h, g_xl1h);
    cudaGetSymbolAddress((void**)&p_xr1h, g_xr1h);
    cudaGetSymbolAddress((void**)&p_w1lh, g_w1lh);
    cudaGetSymbolAddress((void**)&p_w1rh, g_w1rh);
    cudaGetSymbolAddress((void**)&p_w23h, g_w23h);
    cudaGetSymbolAddress((void**)&p_dw1h, g_dw1h);
    cudaGetSymbolAddress((void**)&p_dw2h, g_dw2h);
    cudaGetSymbolAddress((void**)&p_ebh,  g_ebh);
    cudaGetSymbolAddress((void**)&p_ebl,  g_ebl);

    cudaFuncSetAttribute(gram_hmma, cudaFuncAttributeMaxDynamicSharedMemorySize, G_SMEM);

    static cudaStream_t s_side = nullptr;
    static cudaEvent_t evA = nullptr, evB = nullptr, evC = nullptr, evD = nullptr;
    if (!s_side) {
        cudaStreamCreateWithFlags(&s_side, cudaStreamNonBlocking);
        cudaEventCreateWithFlags(&evA, cudaEventDisableTiming);
        cudaEventCreateWithFlags(&evB, cudaEventDisableTiming);
        cudaEventCreateWithFlags(&evC, cudaEventDisableTiming);
        cudaEventCreateWithFlags(&evD, cudaEventDisableTiming);
    }

    const int MT  = (NN + 127) / 128;   // 79
    const int MT64 = (NN + 63) / 64;    // 157

    // ---- fork: CSR build on side stream ----
    cudaEventRecord(evA, 0);
    cudaStreamWaitEvent(s_side, evA, 0);
    k_zero_counts<<<(NN + 255) / 256, 256, 0, s_side>>>();
    k_count_deg<<<(NE + 255) / 256, 256, 0, s_side>>>(ei);
    k_scan_deg<<<1, 1024, 0, s_side>>>();
    k_fill_list<<<(NE + 255) / 256, 256, 0, s_side>>>(ei);
    cudaEventRecord(evB, s_side);

    // ---- main: fused prep + layer-1 GEMM (fp16 output) ----
    k_prep<<<(P_TOT + 255) / 256, 256>>>(w1l, w1r, w2l, w2r, w3l, w3r, dw1, dw2,
                                         b2l, b2r, b3l, b3r);
    {
        TJobs j1 = {{ { p_w1lh, b1l, (float*)p_xl1h }, { p_w1rh, b1r, (float*)p_xr1h } }};
        gemmT64h<<<dim3(1, MT64, 2), 256>>>(x, j1, NN, NFEAT, H1);
    }
    cudaStreamWaitEvent(0, evB, 0);   // join CSR

    // ---- GAT layer 1 (fp16 gather, fused online softmax) -> BN stats ----
    gat1_fused<<<NN, 128>>>(p_xl1h, p_xr1h, a1, bias1, p_h);
    bn_stats<H1><<<H1, 256>>>(p_h);

    // ---- layers 2 & 3 packed GEMM (BN+ReLU fused on A) ----
    {
        TJobs j2 = {{ { p_w23h, p_b23, p_x23 }, {} }};
        gemmT<<<dim3(2, MT, 1), 256>>>(p_h, j2, NN, H1, 256, bn1_g, bn1_b);
    }

    // ---- GAT layers 2+3 merged + fused reparameterize ----
    gat23_fused<<<NN, 128>>>(p_x23, a2, bias2, a3, bias3, eps,
                             out + MU_OFF, out + LV_OFF, out + EMB_OFF);

    // ---- fork: decoder MLP on side stream, gram on main ----
    cudaEventRecord(evC, 0);
    cudaStreamWaitEvent(s_side, evC, 0);
    gemmP<<<dim3(2, MT, 1), 256, 0, s_side>>>(p_ebh, p_ebl, p_dw1h, db1, p_d,
                                              NN, NHID2, NHID1);
    bn_stats<NHID1><<<NHID1, 256, 0, s_side>>>(p_d);
    {
        TJobs jd = {{ { p_dw2h, db2, out + REX_OFF }, {} }};
        gemmT<<<dim3(4, MT, 1), 256, 0, s_side>>>(p_d, jd, NN, NHID1, NFEAT,
                                                  dbn_g, dbn_b);
    }
    cudaEventRecord(evD, s_side);

    gram_hmma<<<MT * (MT + 1) / 2, 256, G_SMEM>>>(p_ebh, p_ebl, out + READJ_OFF);

    cudaStreamWaitEvent(0, evD, 0);   // join decoder
}